// round 1
// baseline (speedup 1.0000x reference)
#include <cuda_runtime.h>
#include <math.h>

#define B_   4
#define T_   2048
#define D_   512
#define H_   8
#define KVH_ 2
#define HD_  64
#define DN_  32
#define DR_  32
#define BT_  (B_ * T_)   // 8192
#define GQA_ (H_ / KVH_) // 4

// ---------------- scratch (device globals; no allocation allowed) ----------------
__device__ float g_cq   [BT_ * 256];
__device__ float g_ckv  [BT_ * 128];
__device__ float g_qnope[BT_ * 256];
__device__ float g_qrope[BT_ * 256];
__device__ float g_knope[BT_ * 64];
__device__ float g_krope[BT_ * 64];
__device__ float g_vproj[BT_ * 128];          // [tok, kvh*64+d]
__device__ float g_vres [BT_ * 512];          // [tok, h*64+d]
__device__ float g_q    [B_ * H_   * T_ * 64];  // [B,H,T,64]
__device__ float g_k    [B_ * KVH_ * T_ * 64];  // [B,KVH,T,64]
__device__ float g_ao   [BT_ * 512];          // attention out + v_res, [tok, h*64+d]
__device__ float g_cos  [T_ * 16];
__device__ float g_sin  [T_ * 16];

// ---------------- RoPE tables (double precision host-side math on device) --------
__global__ void rope_tables_kernel() {
    int idx = blockIdx.x * blockDim.x + threadIdx.x;
    if (idx >= T_ * 16) return;
    int t = idx >> 4, i = idx & 15;
    double invf = pow(500000.0, -((double)(2 * i)) / 32.0);
    double ang  = (double)t * invf;
    g_cos[idx] = (float)cos(ang);
    g_sin[idx] = (float)sin(ang);
}

// ---------------- generic SGEMM: C[M,N] = A[M,K] @ B[K,N] ------------------------
// Requires M%64==0, N%64==0, K%16==0. 64x64 tile, 256 threads, 4x4 microtile.
__global__ void sgemm64_kernel(const float* __restrict__ A,
                               const float* __restrict__ Bm,
                               float* __restrict__ C,
                               int M, int N, int K) {
    __shared__ float As[16][64];   // As[k][m]
    __shared__ float Bs[16][64];   // Bs[k][n]
    const int tx = threadIdx.x, ty = threadIdx.y;
    const int tid = ty * 16 + tx;
    const int m0 = blockIdx.y * 64, n0 = blockIdx.x * 64;

    const int arow = tid >> 2, akq = tid & 3;     // A: 64 rows x 4 float4
    const int brow = tid >> 4, bnq = tid & 15;    // B: 16 rows x 16 float4

    float acc[4][4] = {};

    for (int k0 = 0; k0 < K; k0 += 16) {
        float4 av = *(const float4*)(A + (size_t)(m0 + arow) * K + k0 + akq * 4);
        As[akq * 4 + 0][arow] = av.x;
        As[akq * 4 + 1][arow] = av.y;
        As[akq * 4 + 2][arow] = av.z;
        As[akq * 4 + 3][arow] = av.w;
        float4 bv = *(const float4*)(Bm + (size_t)(k0 + brow) * N + n0 + bnq * 4);
        *(float4*)&Bs[brow][bnq * 4] = bv;
        __syncthreads();
        #pragma unroll
        for (int k = 0; k < 16; k++) {
            float a[4], b[4];
            #pragma unroll
            for (int i = 0; i < 4; i++) a[i] = As[k][ty * 4 + i];
            #pragma unroll
            for (int j = 0; j < 4; j++) b[j] = Bs[k][tx * 4 + j];
            #pragma unroll
            for (int i = 0; i < 4; i++)
                #pragma unroll
                for (int j = 0; j < 4; j++)
                    acc[i][j] += a[i] * b[j];
        }
        __syncthreads();
    }
    #pragma unroll
    for (int i = 0; i < 4; i++)
        #pragma unroll
        for (int j = 0; j < 4; j++)
            C[(size_t)(m0 + ty * 4 + i) * N + n0 + tx * 4 + j] = acc[i][j];
}

// ---------------- in-place row RMSNorm -------------------------------------------
__global__ void rmsnorm_kernel(float* __restrict__ X, const float* __restrict__ w,
                               int N, int rows) {
    int warp = (blockIdx.x * blockDim.x + threadIdx.x) >> 5;
    int lane = threadIdx.x & 31;
    if (warp >= rows) return;
    float* row = X + (size_t)warp * N;
    float ss = 0.f;
    for (int c = lane; c < N; c += 32) { float v = row[c]; ss += v * v; }
    #pragma unroll
    for (int o = 16; o; o >>= 1) ss += __shfl_xor_sync(0xffffffffu, ss, o);
    float inv = rsqrtf(ss / (float)N + 1e-6f);
    for (int c = lane; c < N; c += 32) row[c] = row[c] * inv * w[c];
}

// ---------------- assemble q/k: RoPE + concat + per-head RMSNorm ------------------
// nope/rope: [tok, NH*32]; out: [B, NH, T, 64]. One warp per (b,h,t).
__global__ void assemble_qk_kernel(const float* __restrict__ nope,
                                   const float* __restrict__ rope,
                                   const float* __restrict__ w,
                                   float* __restrict__ out, int NH) {
    int gw   = (blockIdx.x * blockDim.x + threadIdx.x) >> 5;
    int lane = threadIdx.x & 31;
    if (gw >= B_ * NH * T_) return;
    int t  = gw % T_;
    int bh = gw / T_;
    int h  = bh % NH;
    int b  = bh / NH;
    int tok = b * T_ + t;
    const float* np = nope + (size_t)tok * NH * 32 + h * 32;
    const float* rp = rope + (size_t)tok * NH * 32 + h * 32;

    float v0 = np[lane];

    int j = lane;
    float cs = g_cos[t * 16 + (j & 15)];
    float sn = g_sin[t * 16 + (j & 15)];
    float xj = rp[j];
    float xp = (j < 16) ? -rp[j + 16] : rp[j - 16];
    float v1 = xj * cs + xp * sn;

    float ss = v0 * v0 + v1 * v1;
    #pragma unroll
    for (int o = 16; o; o >>= 1) ss += __shfl_xor_sync(0xffffffffu, ss, o);
    float inv = rsqrtf(ss / 64.f + 1e-6f);

    float* op = out + (size_t)gw * 64;
    op[lane]      = v0 * inv * w[lane];
    op[lane + 32] = v1 * inv * w[lane + 32];
}

// ---------------- flash attention, causal, fp32, online softmax -------------------
// grid: (T/64, B*H). block: (16,16). 64x64 tiles; smem = exactly 48KB.
__global__ void flash_kernel(const float* __restrict__ q,
                             const float* __restrict__ k,
                             const float* __restrict__ vproj,
                             const float* __restrict__ vres,
                             float* __restrict__ ao) {
    __shared__ float QsT[64 * 64];   // QsT[d][r]
    __shared__ float KsT[64 * 64];   // KsT[d][c]; reused as PsT[c][r]
    __shared__ float Vs [64 * 64];   // Vs[c][d]

    const int tx = threadIdx.x, ty = threadIdx.y;
    const int tid = ty * 16 + tx;
    const int qt = blockIdx.x;
    const int bh = blockIdx.y;
    const int b = bh / H_, h = bh % H_;
    const int kvh = h / GQA_;

    const float* qbase = q + (((size_t)(b * H_ + h)) * T_ + qt * 64) * 64;
    // load Q tile transposed
    for (int e = tid; e < 1024; e += 256) {
        int r = e >> 4, dq = e & 15;
        float4 v = *(const float4*)(qbase + r * 64 + dq * 4);
        QsT[(dq * 4 + 0) * 64 + r] = v.x;
        QsT[(dq * 4 + 1) * 64 + r] = v.y;
        QsT[(dq * 4 + 2) * 64 + r] = v.z;
        QsT[(dq * 4 + 3) * 64 + r] = v.w;
    }

    float m[4], l[4], o[4][4];
    #pragma unroll
    for (int i = 0; i < 4; i++) {
        m[i] = -1e30f; l[i] = 0.f;
        #pragma unroll
        for (int jj = 0; jj < 4; jj++) o[i][jj] = 0.f;
    }

    const float* kbase = k + ((size_t)(b * KVH_ + kvh)) * T_ * 64;
    const float* vbase = vproj + (size_t)b * T_ * 128 + kvh * 64;

    for (int kt = 0; kt <= qt; kt++) {
        __syncthreads();   // protect KsT/Vs from previous iter readers
        for (int e = tid; e < 1024; e += 256) {
            int c = e >> 4, dq = e & 15;
            float4 kv = *(const float4*)(kbase + (size_t)(kt * 64 + c) * 64 + dq * 4);
            KsT[(dq * 4 + 0) * 64 + c] = kv.x;
            KsT[(dq * 4 + 1) * 64 + c] = kv.y;
            KsT[(dq * 4 + 2) * 64 + c] = kv.z;
            KsT[(dq * 4 + 3) * 64 + c] = kv.w;
            float4 vv = *(const float4*)(vbase + (size_t)(kt * 64 + c) * 128 + dq * 4);
            *(float4*)&Vs[c * 64 + dq * 4] = vv;
        }
        __syncthreads();

        // S = Q @ K^T  (4x4 per thread)
        float s[4][4] = {};
        #pragma unroll 16
        for (int d = 0; d < 64; d++) {
            float a[4], bb[4];
            #pragma unroll
            for (int i = 0; i < 4; i++) a[i] = QsT[d * 64 + ty * 4 + i];
            #pragma unroll
            for (int j = 0; j < 4; j++) bb[j] = KsT[d * 64 + tx * 4 + j];
            #pragma unroll
            for (int i = 0; i < 4; i++)
                #pragma unroll
                for (int j = 0; j < 4; j++)
                    s[i][j] += a[i] * bb[j];
        }

        const int rbase = qt * 64 + ty * 4;
        const int cbase = kt * 64 + tx * 4;
        #pragma unroll
        for (int i = 0; i < 4; i++)
            #pragma unroll
            for (int j = 0; j < 4; j++) {
                s[i][j] *= 0.125f;                         // 64^-0.5
                if (kt == qt && cbase + j > rbase + i) s[i][j] = -1e30f;
            }

        // online softmax; row stats replicated across the 16 tx lanes
        float corr[4];
        #pragma unroll
        for (int i = 0; i < 4; i++) {
            float rm = fmaxf(fmaxf(s[i][0], s[i][1]), fmaxf(s[i][2], s[i][3]));
            #pragma unroll
            for (int off = 8; off; off >>= 1)
                rm = fmaxf(rm, __shfl_xor_sync(0xffffffffu, rm, off));
            float nm = fmaxf(m[i], rm);
            float su = 0.f;
            #pragma unroll
            for (int j = 0; j < 4; j++) {
                s[i][j] = __expf(s[i][j] - nm);
                su += s[i][j];
            }
            #pragma unroll
            for (int off = 8; off; off >>= 1)
                su += __shfl_xor_sync(0xffffffffu, su, off);
            corr[i] = __expf(m[i] - nm);
            m[i] = nm;
            l[i] = l[i] * corr[i] + su;
        }

        __syncthreads();   // everyone done reading KsT for S
        // store P transposed into the K buffer: PsT[c][r]
        #pragma unroll
        for (int i = 0; i < 4; i++)
            #pragma unroll
            for (int j = 0; j < 4; j++)
                KsT[(tx * 4 + j) * 64 + ty * 4 + i] = s[i][j];
        __syncthreads();

        #pragma unroll
        for (int i = 0; i < 4; i++)
            #pragma unroll
            for (int jj = 0; jj < 4; jj++)
                o[i][jj] *= corr[i];

        // O += P @ V
        #pragma unroll 16
        for (int c = 0; c < 64; c++) {
            float p[4], vv[4];
            #pragma unroll
            for (int i = 0; i < 4; i++) p[i] = KsT[c * 64 + ty * 4 + i];
            #pragma unroll
            for (int jj = 0; jj < 4; jj++) vv[jj] = Vs[c * 64 + tx * 4 + jj];
            #pragma unroll
            for (int i = 0; i < 4; i++)
                #pragma unroll
                for (int jj = 0; jj < 4; jj++)
                    o[i][jj] += p[i] * vv[jj];
        }
    }

    // epilogue: normalize, add value-residual, write [tok, h*64+d]
    #pragma unroll
    for (int i = 0; i < 4; i++) {
        float invl = 1.f / l[i];
        int qrow = qt * 64 + ty * 4 + i;
        size_t base = ((size_t)(b * T_ + qrow)) * 512 + h * 64 + tx * 4;
        #pragma unroll
        for (int jj = 0; jj < 4; jj++)
            ao[base + jj] = o[i][jj] * invl + vres[base + jj];
    }
}

// ---------------- launch ----------------------------------------------------------
extern "C" void kernel_launch(void* const* d_in, const int* in_sizes, int n_in,
                              void* d_out, int out_size) {
    const float* x      = (const float*)d_in[0];
    const float* W_DQ   = (const float*)d_in[1];
    const float* W_UQ   = (const float*)d_in[2];
    const float* W_QR   = (const float*)d_in[3];
    const float* W_DKV  = (const float*)d_in[4];
    const float* W_UK   = (const float*)d_in[5];
    const float* W_UV   = (const float*)d_in[6];
    const float* W_KR   = (const float*)d_in[7];
    const float* W_VR   = (const float*)d_in[8];
    const float* W_O    = (const float*)d_in[9];
    const float* q_ln_w = (const float*)d_in[10];
    const float* kv_ln_w = (const float*)d_in[11];
    const float* q_head_w = (const float*)d_in[12];
    const float* k_head_w = (const float*)d_in[13];
    float* out = (float*)d_out;

    float *cq, *ckv, *qnope, *qrope, *knope, *krope, *vproj, *vres, *gq, *gk, *gao;
    cudaGetSymbolAddress((void**)&cq,    g_cq);
    cudaGetSymbolAddress((void**)&ckv,   g_ckv);
    cudaGetSymbolAddress((void**)&qnope, g_qnope);
    cudaGetSymbolAddress((void**)&qrope, g_qrope);
    cudaGetSymbolAddress((void**)&knope, g_knope);
    cudaGetSymbolAddress((void**)&krope, g_krope);
    cudaGetSymbolAddress((void**)&vproj, g_vproj);
    cudaGetSymbolAddress((void**)&vres,  g_vres);
    cudaGetSymbolAddress((void**)&gq,    g_q);
    cudaGetSymbolAddress((void**)&gk,    g_k);
    cudaGetSymbolAddress((void**)&gao,   g_ao);

    dim3 blk(16, 16);

    rope_tables_kernel<<<(T_ * 16 + 255) / 256, 256>>>();

    // x projections
    sgemm64_kernel<<<dim3(256 / 64, BT_ / 64), blk>>>(x, W_DQ,  cq,    BT_, 256, 512);
    sgemm64_kernel<<<dim3(128 / 64, BT_ / 64), blk>>>(x, W_DKV, ckv,   BT_, 128, 512);
    sgemm64_kernel<<<dim3( 64 / 64, BT_ / 64), blk>>>(x, W_KR,  krope, BT_,  64, 512);
    sgemm64_kernel<<<dim3(512 / 64, BT_ / 64), blk>>>(x, W_VR,  vres,  BT_, 512, 512);

    // latent RMSNorms (in place)
    rmsnorm_kernel<<<BT_ / 8, 256>>>(cq,  q_ln_w,  256, BT_);
    rmsnorm_kernel<<<BT_ / 8, 256>>>(ckv, kv_ln_w, 128, BT_);

    // up-projections
    sgemm64_kernel<<<dim3(256 / 64, BT_ / 64), blk>>>(cq,  W_UQ, qnope, BT_, 256, 256);
    sgemm64_kernel<<<dim3(256 / 64, BT_ / 64), blk>>>(cq,  W_QR, qrope, BT_, 256, 256);
    sgemm64_kernel<<<dim3( 64 / 64, BT_ / 64), blk>>>(ckv, W_UK, knope, BT_,  64, 128);
    sgemm64_kernel<<<dim3(128 / 64, BT_ / 64), blk>>>(ckv, W_UV, vproj, BT_, 128, 128);

    // RoPE + concat + head RMSNorm into [B,NH,T,64]
    assemble_qk_kernel<<<B_ * H_   * T_ / 8, 256>>>(qnope, qrope, q_head_w, gq, H_);
    assemble_qk_kernel<<<B_ * KVH_ * T_ / 8, 256>>>(knope, krope, k_head_w, gk, KVH_);

    // causal flash attention + value residual
    flash_kernel<<<dim3(T_ / 64, B_ * H_), blk>>>(gq, gk, vproj, vres, gao);

    // output projection
    sgemm64_kernel<<<dim3(512 / 64, BT_ / 64), blk>>>(gao, W_O, out, BT_, 512, 512);
}

// round 3
// speedup vs baseline: 1.7256x; 1.7256x over previous
#include <cuda_runtime.h>
#include <cstdint>
#include <math.h>

#define B_   4
#define T_   2048
#define H_   8
#define KVH_ 2
#define BT_  (B_ * T_)   // 8192
#define GQA_ (H_ / KVH_) // 4

// ---------------- scratch (device globals; no allocation allowed) ----------------
__device__ float g_cq   [BT_ * 256];
__device__ float g_ckv  [BT_ * 128];
__device__ float g_qnope[BT_ * 256];
__device__ float g_qrope[BT_ * 256];
__device__ float g_knope[BT_ * 64];
__device__ float g_krope[BT_ * 64];
__device__ float g_vproj[BT_ * 128];
__device__ float g_vres [BT_ * 512];
__device__ float g_q    [B_ * H_   * T_ * 64];
__device__ float g_k    [B_ * KVH_ * T_ * 64];
__device__ float g_ao   [BT_ * 512];
__device__ float g_cos  [T_ * 16];
__device__ float g_sin  [T_ * 16];

// transposed weights [N, K]
__device__ float g_wt_dq [256 * 512];
__device__ float g_wt_uq [256 * 256];
__device__ float g_wt_qr [256 * 256];
__device__ float g_wt_dkv[128 * 512];
__device__ float g_wt_uk [ 64 * 128];
__device__ float g_wt_uv [128 * 128];
__device__ float g_wt_kr [ 64 * 512];
__device__ float g_wt_vr [512 * 512];
__device__ float g_wt_o  [512 * 512];

// ---------------- helpers ---------------------------------------------------------
__device__ __forceinline__ uint32_t tf32r(float v) {
    uint32_t r;
    asm("cvt.rna.tf32.f32 %0, %1;" : "=r"(r) : "f"(v));
    return r;
}

__device__ __forceinline__ void mma_tf32(float* c, const uint32_t* a,
                                         uint32_t b0, uint32_t b1) {
    asm volatile(
        "mma.sync.aligned.m16n8k8.row.col.f32.tf32.tf32.f32 "
        "{%0,%1,%2,%3}, {%4,%5,%6,%7}, {%8,%9}, {%0,%1,%2,%3};\n"
        : "+f"(c[0]), "+f"(c[1]), "+f"(c[2]), "+f"(c[3])
        : "r"(a[0]), "r"(a[1]), "r"(a[2]), "r"(a[3]), "r"(b0), "r"(b1));
}

__device__ __forceinline__ uint32_t fbits(float v) { return __float_as_uint(v); }

// ---------------- RoPE tables -----------------------------------------------------
__global__ void rope_tables_kernel() {
    int idx = blockIdx.x * blockDim.x + threadIdx.x;
    if (idx >= T_ * 16) return;
    int t = idx >> 4, i = idx & 15;
    double invf = pow(500000.0, -((double)(2 * i)) / 32.0);
    double ang  = (double)t * invf;
    g_cos[idx] = (float)cos(ang);
    g_sin[idx] = (float)sin(ang);
}

// ---------------- weight transpose: in [K,N] -> out [N,K] -------------------------
__global__ void transpose_kernel(const float* __restrict__ in, float* __restrict__ out,
                                 int K, int N) {
    __shared__ float t[32][33];
    int n0 = blockIdx.x * 32, k0 = blockIdx.y * 32;
    int x = threadIdx.x, y = threadIdx.y;
    #pragma unroll
    for (int d = 0; d < 32; d += 8)
        t[y + d][x] = in[(size_t)(k0 + y + d) * N + n0 + x];
    __syncthreads();
    #pragma unroll
    for (int d = 0; d < 32; d += 8)
        out[(size_t)(n0 + y + d) * K + k0 + x] = t[x][y + d];
}

// ---------------- 3xTF32 mma GEMM: C[M,N] = A[M,K] @ BT[N,K]^T ---------------------
// block tile 128 x TN, 256 threads, K chunks of 32. Padded smem, stride 36.
__device__ __forceinline__ void split_store(float* hp, float* lp, float4 v) {
    float hx = __uint_as_float(tf32r(v.x));
    float hy = __uint_as_float(tf32r(v.y));
    float hz = __uint_as_float(tf32r(v.z));
    float hw = __uint_as_float(tf32r(v.w));
    *(float4*)hp = make_float4(hx, hy, hz, hw);
    *(float4*)lp = make_float4(__uint_as_float(tf32r(v.x - hx)),
                               __uint_as_float(tf32r(v.y - hy)),
                               __uint_as_float(tf32r(v.z - hz)),
                               __uint_as_float(tf32r(v.w - hw)));
}

template <int TN>
__global__ void __launch_bounds__(256)
mma_gemm(const float* __restrict__ A, const float* __restrict__ BT,
         float* __restrict__ C, int M, int N, int K) {
    extern __shared__ float sm[];
    constexpr int SP = 36;
    float* Ah = sm;
    float* Al = Ah + 128 * SP;
    float* Bh = Al + 128 * SP;
    float* Bl = Bh + TN * SP;

    constexpr int WMW    = (TN == 128) ? 2 : 4;   // warps along M
    constexpr int WARP_M = 128 / WMW;             // 64 or 32
    constexpr int MI     = WARP_M / 16;           // 4 or 2

    const int tid = threadIdx.x, wid = tid >> 5, lane = tid & 31;
    const int wm = wid % WMW, wn = wid / WMW;
    const int g = lane >> 2, t4 = lane & 3;
    const int m0 = blockIdx.y * 128, n0 = blockIdx.x * TN;

    float c[MI][4][4];
    #pragma unroll
    for (int mi = 0; mi < MI; mi++)
        #pragma unroll
        for (int ni = 0; ni < 4; ni++)
            #pragma unroll
            for (int j = 0; j < 4; j++) c[mi][ni][j] = 0.f;

    for (int k0 = 0; k0 < K; k0 += 32) {
        __syncthreads();
        // A tile [128,32]
        #pragma unroll
        for (int j = 0; j < 4; j++) {
            int idx = tid + 256 * j;
            int row = idx >> 3, q = idx & 7;
            float4 v = *(const float4*)(A + (size_t)(m0 + row) * K + k0 + q * 4);
            split_store(Ah + row * SP + q * 4, Al + row * SP + q * 4, v);
        }
        // B tile [TN,32]
        #pragma unroll
        for (int j = 0; j < TN / 32; j++) {
            int idx = tid + 256 * j;
            int row = idx >> 3, q = idx & 7;
            float4 v = *(const float4*)(BT + (size_t)(n0 + row) * K + k0 + q * 4);
            split_store(Bh + row * SP + q * 4, Bl + row * SP + q * 4, v);
        }
        __syncthreads();

        #pragma unroll
        for (int ks = 0; ks < 4; ks++) {
            const int col = ks * 8 + t4;
            uint32_t ah[MI][4], al[MI][4];
            #pragma unroll
            for (int mi = 0; mi < MI; mi++) {
                int r = wm * WARP_M + mi * 16 + g;
                ah[mi][0] = fbits(Ah[r * SP + col]);
                ah[mi][1] = fbits(Ah[(r + 8) * SP + col]);
                ah[mi][2] = fbits(Ah[r * SP + col + 4]);
                ah[mi][3] = fbits(Ah[(r + 8) * SP + col + 4]);
                al[mi][0] = fbits(Al[r * SP + col]);
                al[mi][1] = fbits(Al[(r + 8) * SP + col]);
                al[mi][2] = fbits(Al[r * SP + col + 4]);
                al[mi][3] = fbits(Al[(r + 8) * SP + col + 4]);
            }
            #pragma unroll
            for (int ni = 0; ni < 4; ni++) {
                int nr = wn * 32 + ni * 8 + g;
                uint32_t bh0 = fbits(Bh[nr * SP + col]);
                uint32_t bh1 = fbits(Bh[nr * SP + col + 4]);
                uint32_t bl0 = fbits(Bl[nr * SP + col]);
                uint32_t bl1 = fbits(Bl[nr * SP + col + 4]);
                #pragma unroll
                for (int mi = 0; mi < MI; mi++) {
                    mma_tf32(c[mi][ni], ah[mi], bh0, bh1);
                    mma_tf32(c[mi][ni], ah[mi], bl0, bl1);
                    mma_tf32(c[mi][ni], al[mi], bh0, bh1);
                }
            }
        }
    }

    #pragma unroll
    for (int mi = 0; mi < MI; mi++) {
        int row = m0 + wm * WARP_M + mi * 16 + g;
        #pragma unroll
        for (int ni = 0; ni < 4; ni++) {
            int col = n0 + wn * 32 + ni * 8 + t4 * 2;
            *(float2*)(C + (size_t)row * N + col) =
                make_float2(c[mi][ni][0], c[mi][ni][1]);
            *(float2*)(C + (size_t)(row + 8) * N + col) =
                make_float2(c[mi][ni][2], c[mi][ni][3]);
        }
    }
}

// ---------------- in-place row RMSNorm --------------------------------------------
__global__ void rmsnorm_kernel(float* __restrict__ X, const float* __restrict__ w,
                               int N, int rows) {
    int warp = (blockIdx.x * blockDim.x + threadIdx.x) >> 5;
    int lane = threadIdx.x & 31;
    if (warp >= rows) return;
    float* row = X + (size_t)warp * N;
    float ss = 0.f;
    for (int c = lane; c < N; c += 32) { float v = row[c]; ss += v * v; }
    #pragma unroll
    for (int o = 16; o; o >>= 1) ss += __shfl_xor_sync(0xffffffffu, ss, o);
    float inv = rsqrtf(ss / (float)N + 1e-6f);
    for (int c = lane; c < N; c += 32) row[c] = row[c] * inv * w[c];
}

// ---------------- assemble q/k: RoPE + concat + per-head RMSNorm -------------------
__global__ void assemble_qk_kernel(const float* __restrict__ nope,
                                   const float* __restrict__ rope,
                                   const float* __restrict__ w,
                                   float* __restrict__ out, int NH) {
    int gw   = (blockIdx.x * blockDim.x + threadIdx.x) >> 5;
    int lane = threadIdx.x & 31;
    if (gw >= B_ * NH * T_) return;
    int t  = gw % T_;
    int bh = gw / T_;
    int h  = bh % NH;
    int b  = bh / NH;
    int tok = b * T_ + t;
    const float* np = nope + (size_t)tok * NH * 32 + h * 32;
    const float* rp = rope + (size_t)tok * NH * 32 + h * 32;

    float v0 = np[lane];
    int j = lane;
    float cs = g_cos[t * 16 + (j & 15)];
    float sn = g_sin[t * 16 + (j & 15)];
    float xj = rp[j];
    float xp = (j < 16) ? -rp[j + 16] : rp[j - 16];
    float v1 = xj * cs + xp * sn;

    float ss = v0 * v0 + v1 * v1;
    #pragma unroll
    for (int o = 16; o; o >>= 1) ss += __shfl_xor_sync(0xffffffffu, ss, o);
    float inv = rsqrtf(ss / 64.f + 1e-6f);

    float* op = out + (size_t)gw * 64;
    op[lane]      = v0 * inv * w[lane];
    op[lane + 32] = v1 * inv * w[lane + 32];
}

// ---------------- flash attention with mma.sync tf32 ------------------------------
// 64 q-rows x 64 k-cols per block, 256 threads (8 warps).
// Warp w: S rows wr=(w>>1)*16, S cols wc=(w&1)*32; O rows wr, O dcols wd=(w&1)*32.
// S uses 3xTF32 split; PV uses single tf32. Row max/sum exchanged between the
// two warps sharing a row block via small smem arrays.
#define FSP 68   // padded row stride (floats)
#define QHI 0
#define QLO (64 * FSP)
#define KHI (2 * 64 * FSP)
#define KLO (3 * 64 * FSP)
#define VTT (4 * 64 * FSP)
#define PSS (5 * 64 * FSP)
#define MXX (6 * 64 * FSP)        // 2 x 64 floats
#define SXX (6 * 64 * FSP + 128)  // 2 x 64 floats
#define FSM_FLOATS (6 * 64 * FSP + 256)

__global__ void __launch_bounds__(256)
flash_kernel(const float* __restrict__ q,
             const float* __restrict__ k,
             const float* __restrict__ vproj,
             const float* __restrict__ vres,
             float* __restrict__ ao) {
    extern __shared__ float fs[];

    const int tid = threadIdx.x, wid = tid >> 5, lane = tid & 31;
    const int g = lane >> 2, t4 = lane & 3;
    const int wr = (wid >> 1) * 16;
    const int wcol = wid & 1;
    const int wc = wcol * 32;        // S col block == O d block

    const int qt = blockIdx.x;
    const int bh = blockIdx.y;
    const int b = bh / H_, h = bh % H_;
    const int kvh = h / GQA_;

    // load Q tile once (split hi/lo)
    const float* qbase = q + (((size_t)(b * H_ + h)) * T_ + qt * 64) * 64;
    #pragma unroll
    for (int j = 0; j < 4; j++) {
        int e = tid + 256 * j;
        int r = e >> 4, dq = e & 15;
        float4 v = *(const float4*)(qbase + r * 64 + dq * 4);
        split_store(fs + QHI + r * FSP + dq * 4, fs + QLO + r * FSP + dq * 4, v);
    }

    float m0 = -1e30f, m1 = -1e30f, l0 = 0.f, l1 = 0.f;
    float o[4][4];
    #pragma unroll
    for (int ni = 0; ni < 4; ni++)
        #pragma unroll
        for (int j = 0; j < 4; j++) o[ni][j] = 0.f;

    const float* kbase = k + ((size_t)(b * KVH_ + kvh)) * T_ * 64;
    const float* vbase = vproj + (size_t)b * T_ * 128 + kvh * 64;

    for (int kt = 0; kt <= qt; kt++) {
        __syncthreads();   // previous iteration's readers done
        // K tile [c][d] split hi/lo ; V^T [d][c] single tf32
        #pragma unroll
        for (int j = 0; j < 4; j++) {
            int e = tid + 256 * j;
            int c = e >> 4, dq = e & 15;
            float4 kv = *(const float4*)(kbase + (size_t)(kt * 64 + c) * 64 + dq * 4);
            split_store(fs + KHI + c * FSP + dq * 4, fs + KLO + c * FSP + dq * 4, kv);
            float4 vv = *(const float4*)(vbase + (size_t)(kt * 64 + c) * 128 + dq * 4);
            fs[VTT + (dq * 4 + 0) * FSP + c] = __uint_as_float(tf32r(vv.x));
            fs[VTT + (dq * 4 + 1) * FSP + c] = __uint_as_float(tf32r(vv.y));
            fs[VTT + (dq * 4 + 2) * FSP + c] = __uint_as_float(tf32r(vv.z));
            fs[VTT + (dq * 4 + 3) * FSP + c] = __uint_as_float(tf32r(vv.w));
        }
        __syncthreads();

        // ---- S = Q @ K^T (3xTF32) ----
        float s[4][4];
        #pragma unroll
        for (int ni = 0; ni < 4; ni++)
            #pragma unroll
            for (int j = 0; j < 4; j++) s[ni][j] = 0.f;

        #pragma unroll
        for (int ks = 0; ks < 8; ks++) {
            const int col = ks * 8 + t4;
            const int r = wr + g;
            uint32_t ah[4], al[4];
            ah[0] = fbits(fs[QHI + r * FSP + col]);
            ah[1] = fbits(fs[QHI + (r + 8) * FSP + col]);
            ah[2] = fbits(fs[QHI + r * FSP + col + 4]);
            ah[3] = fbits(fs[QHI + (r + 8) * FSP + col + 4]);
            al[0] = fbits(fs[QLO + r * FSP + col]);
            al[1] = fbits(fs[QLO + (r + 8) * FSP + col]);
            al[2] = fbits(fs[QLO + r * FSP + col + 4]);
            al[3] = fbits(fs[QLO + (r + 8) * FSP + col + 4]);
            #pragma unroll
            for (int ni = 0; ni < 4; ni++) {
                int nr = wc + ni * 8 + g;
                uint32_t bh0 = fbits(fs[KHI + nr * FSP + col]);
                uint32_t bh1 = fbits(fs[KHI + nr * FSP + col + 4]);
                uint32_t bl0 = fbits(fs[KLO + nr * FSP + col]);
                uint32_t bl1 = fbits(fs[KLO + nr * FSP + col + 4]);
                mma_tf32(s[ni], ah, bh0, bh1);
                mma_tf32(s[ni], ah, bl0, bl1);
                mma_tf32(s[ni], al, bh0, bh1);
            }
        }

        // scale + causal mask
        const int rg0 = qt * 64 + wr + g;
        const int rg1 = rg0 + 8;
        #pragma unroll
        for (int ni = 0; ni < 4; ni++) {
            int cg = kt * 64 + wc + ni * 8 + t4 * 2;
            #pragma unroll
            for (int j = 0; j < 4; j++) {
                s[ni][j] *= 0.125f;
                int cc = cg + (j & 1);
                int rr = (j < 2) ? rg0 : rg1;
                if (cc > rr) s[ni][j] = -1e30f;
            }
        }

        // local row max over this warp's 32 cols
        float rm0 = fmaxf(fmaxf(s[0][0], s[0][1]), fmaxf(s[1][0], s[1][1]));
        rm0 = fmaxf(rm0, fmaxf(fmaxf(s[2][0], s[2][1]), fmaxf(s[3][0], s[3][1])));
        float rm1 = fmaxf(fmaxf(s[0][2], s[0][3]), fmaxf(s[1][2], s[1][3]));
        rm1 = fmaxf(rm1, fmaxf(fmaxf(s[2][2], s[2][3]), fmaxf(s[3][2], s[3][3])));
        #pragma unroll
        for (int off = 1; off <= 2; off <<= 1) {
            rm0 = fmaxf(rm0, __shfl_xor_sync(0xffffffffu, rm0, off));
            rm1 = fmaxf(rm1, __shfl_xor_sync(0xffffffffu, rm1, off));
        }
        if (t4 == 0) {
            fs[MXX + wcol * 64 + wr + g]     = rm0;
            fs[MXX + wcol * 64 + wr + g + 8] = rm1;
        }
        __syncthreads();
        float tm0 = fmaxf(fs[MXX + (wr + g)],      fs[MXX + 64 + (wr + g)]);
        float tm1 = fmaxf(fs[MXX + (wr + g + 8)],  fs[MXX + 64 + (wr + g + 8)]);
        float nm0 = fmaxf(m0, tm0);
        float nm1 = fmaxf(m1, tm1);

        // exp + local row sums
        float su0 = 0.f, su1 = 0.f;
        #pragma unroll
        for (int ni = 0; ni < 4; ni++) {
            s[ni][0] = __expf(s[ni][0] - nm0);
            s[ni][1] = __expf(s[ni][1] - nm0);
            s[ni][2] = __expf(s[ni][2] - nm1);
            s[ni][3] = __expf(s[ni][3] - nm1);
            su0 += s[ni][0] + s[ni][1];
            su1 += s[ni][2] + s[ni][3];
        }
        #pragma unroll
        for (int off = 1; off <= 2; off <<= 1) {
            su0 += __shfl_xor_sync(0xffffffffu, su0, off);
            su1 += __shfl_xor_sync(0xffffffffu, su1, off);
        }
        if (t4 == 0) {
            fs[SXX + wcol * 64 + wr + g]     = su0;
            fs[SXX + wcol * 64 + wr + g + 8] = su1;
        }
        // write P to smem [r][c]
        #pragma unroll
        for (int ni = 0; ni < 4; ni++) {
            int cb = wc + ni * 8 + t4 * 2;
            *(float2*)&fs[PSS + (wr + g) * FSP + cb]     = make_float2(s[ni][0], s[ni][1]);
            *(float2*)&fs[PSS + (wr + g + 8) * FSP + cb] = make_float2(s[ni][2], s[ni][3]);
        }
        float corr0 = __expf(m0 - nm0);
        float corr1 = __expf(m1 - nm1);
        m0 = nm0; m1 = nm1;
        #pragma unroll
        for (int ni = 0; ni < 4; ni++) {
            o[ni][0] *= corr0; o[ni][1] *= corr0;
            o[ni][2] *= corr1; o[ni][3] *= corr1;
        }
        __syncthreads();   // P + sums visible

        l0 = l0 * corr0 + fs[SXX + (wr + g)]     + fs[SXX + 64 + (wr + g)];
        l1 = l1 * corr1 + fs[SXX + (wr + g + 8)] + fs[SXX + 64 + (wr + g + 8)];

        // ---- O += P @ V ----
        #pragma unroll
        for (int ks = 0; ks < 8; ks++) {
            const int col = ks * 8 + t4;
            const int r = wr + g;
            uint32_t ap[4];
            ap[0] = fbits(fs[PSS + r * FSP + col]);
            ap[1] = fbits(fs[PSS + (r + 8) * FSP + col]);
            ap[2] = fbits(fs[PSS + r * FSP + col + 4]);
            ap[3] = fbits(fs[PSS + (r + 8) * FSP + col + 4]);
            #pragma unroll
            for (int ni = 0; ni < 4; ni++) {
                int nr = wc + ni * 8 + g;
                uint32_t b0 = fbits(fs[VTT + nr * FSP + col]);
                uint32_t b1 = fbits(fs[VTT + nr * FSP + col + 4]);
                mma_tf32(o[ni], ap, b0, b1);
            }
        }
    }

    // epilogue: normalize, add v_res, write [tok, h*64+d]
    float invl0 = 1.f / l0, invl1 = 1.f / l1;
    int r0 = qt * 64 + wr + g;
    #pragma unroll
    for (int ni = 0; ni < 4; ni++) {
        int dcol = h * 64 + wc + ni * 8 + t4 * 2;
        size_t base0 = ((size_t)(b * T_ + r0)) * 512 + dcol;
        size_t base1 = ((size_t)(b * T_ + r0 + 8)) * 512 + dcol;
        float2 vr0 = *(const float2*)(vres + base0);
        float2 vr1 = *(const float2*)(vres + base1);
        *(float2*)(ao + base0) = make_float2(o[ni][0] * invl0 + vr0.x,
                                             o[ni][1] * invl0 + vr0.y);
        *(float2*)(ao + base1) = make_float2(o[ni][2] * invl1 + vr1.x,
                                             o[ni][3] * invl1 + vr1.y);
    }
}

// ---------------- launch ----------------------------------------------------------
extern "C" void kernel_launch(void* const* d_in, const int* in_sizes, int n_in,
                              void* d_out, int out_size) {
    const float* x        = (const float*)d_in[0];
    const float* W_DQ     = (const float*)d_in[1];
    const float* W_UQ     = (const float*)d_in[2];
    const float* W_QR     = (const float*)d_in[3];
    const float* W_DKV    = (const float*)d_in[4];
    const float* W_UK     = (const float*)d_in[5];
    const float* W_UV     = (const float*)d_in[6];
    const float* W_KR     = (const float*)d_in[7];
    const float* W_VR     = (const float*)d_in[8];
    const float* W_O      = (const float*)d_in[9];
    const float* q_ln_w   = (const float*)d_in[10];
    const float* kv_ln_w  = (const float*)d_in[11];
    const float* q_head_w = (const float*)d_in[12];
    const float* k_head_w = (const float*)d_in[13];
    float* out = (float*)d_out;

    float *cq, *ckv, *qnope, *qrope, *knope, *krope, *vproj, *vres, *gq, *gk, *gao;
    float *wt_dq, *wt_uq, *wt_qr, *wt_dkv, *wt_uk, *wt_uv, *wt_kr, *wt_vr, *wt_o;
    cudaGetSymbolAddress((void**)&cq,    g_cq);
    cudaGetSymbolAddress((void**)&ckv,   g_ckv);
    cudaGetSymbolAddress((void**)&qnope, g_qnope);
    cudaGetSymbolAddress((void**)&qrope, g_qrope);
    cudaGetSymbolAddress((void**)&knope, g_knope);
    cudaGetSymbolAddress((void**)&krope, g_krope);
    cudaGetSymbolAddress((void**)&vproj, g_vproj);
    cudaGetSymbolAddress((void**)&vres,  g_vres);
    cudaGetSymbolAddress((void**)&gq,    g_q);
    cudaGetSymbolAddress((void**)&gk,    g_k);
    cudaGetSymbolAddress((void**)&gao,   g_ao);
    cudaGetSymbolAddress((void**)&wt_dq,  g_wt_dq);
    cudaGetSymbolAddress((void**)&wt_uq,  g_wt_uq);
    cudaGetSymbolAddress((void**)&wt_qr,  g_wt_qr);
    cudaGetSymbolAddress((void**)&wt_dkv, g_wt_dkv);
    cudaGetSymbolAddress((void**)&wt_uk,  g_wt_uk);
    cudaGetSymbolAddress((void**)&wt_uv,  g_wt_uv);
    cudaGetSymbolAddress((void**)&wt_kr,  g_wt_kr);
    cudaGetSymbolAddress((void**)&wt_vr,  g_wt_vr);
    cudaGetSymbolAddress((void**)&wt_o,   g_wt_o);

    const int SMEM_G128 = (2 * 128 + 2 * 128) * 36 * 4;   // 73728
    const int SMEM_G64  = (2 * 128 + 2 * 64)  * 36 * 4;   // 55296
    const int SMEM_FL   = FSM_FLOATS * 4;                 // 105472
    cudaFuncSetAttribute(mma_gemm<128>, cudaFuncAttributeMaxDynamicSharedMemorySize, SMEM_G128);
    cudaFuncSetAttribute(mma_gemm<64>,  cudaFuncAttributeMaxDynamicSharedMemorySize, SMEM_G64);
    cudaFuncSetAttribute(flash_kernel,  cudaFuncAttributeMaxDynamicSharedMemorySize, SMEM_FL);

    rope_tables_kernel<<<(T_ * 16 + 255) / 256, 256>>>();

    dim3 tb(32, 8);
    transpose_kernel<<<dim3(256 / 32, 512 / 32), tb>>>(W_DQ,  wt_dq,  512, 256);
    transpose_kernel<<<dim3(256 / 32, 256 / 32), tb>>>(W_UQ,  wt_uq,  256, 256);
    transpose_kernel<<<dim3(256 / 32, 256 / 32), tb>>>(W_QR,  wt_qr,  256, 256);
    transpose_kernel<<<dim3(128 / 32, 512 / 32), tb>>>(W_DKV, wt_dkv, 512, 128);
    transpose_kernel<<<dim3( 64 / 32, 128 / 32), tb>>>(W_UK,  wt_uk,  128,  64);
    transpose_kernel<<<dim3(128 / 32, 128 / 32), tb>>>(W_UV,  wt_uv,  128, 128);
    transpose_kernel<<<dim3( 64 / 32, 512 / 32), tb>>>(W_KR,  wt_kr,  512,  64);
    transpose_kernel<<<dim3(512 / 32, 512 / 32), tb>>>(W_VR,  wt_vr,  512, 512);
    transpose_kernel<<<dim3(512 / 32, 512 / 32), tb>>>(W_O,   wt_o,   512, 512);

    // x projections
    mma_gemm<128><<<dim3(2, 64), 256, SMEM_G128>>>(x, wt_dq,  cq,    BT_, 256, 512);
    mma_gemm<128><<<dim3(1, 64), 256, SMEM_G128>>>(x, wt_dkv, ckv,   BT_, 128, 512);
    mma_gemm< 64><<<dim3(1, 64), 256, SMEM_G64 >>>(x, wt_kr,  krope, BT_,  64, 512);
    mma_gemm<128><<<dim3(4, 64), 256, SMEM_G128>>>(x, wt_vr,  vres,  BT_, 512, 512);

    // latent RMSNorms
    rmsnorm_kernel<<<BT_ / 8, 256>>>(cq,  q_ln_w,  256, BT_);
    rmsnorm_kernel<<<BT_ / 8, 256>>>(ckv, kv_ln_w, 128, BT_);

    // up-projections
    mma_gemm<128><<<dim3(2, 64), 256, SMEM_G128>>>(cq,  wt_uq, qnope, BT_, 256, 256);
    mma_gemm<128><<<dim3(2, 64), 256, SMEM_G128>>>(cq,  wt_qr, qrope, BT_, 256, 256);
    mma_gemm< 64><<<dim3(1, 64), 256, SMEM_G64 >>>(ckv, wt_uk, knope, BT_,  64, 128);
    mma_gemm<128><<<dim3(1, 64), 256, SMEM_G128>>>(ckv, wt_uv, vproj, BT_, 128, 128);

    // RoPE + concat + head RMSNorm
    assemble_qk_kernel<<<B_ * H_   * T_ / 8, 256>>>(qnope, qrope, q_head_w, gq, H_);
    assemble_qk_kernel<<<B_ * KVH_ * T_ / 8, 256>>>(knope, krope, k_head_w, gk, KVH_);

    // causal flash attention + value residual
    flash_kernel<<<dim3(T_ / 64, B_ * H_), 256, SMEM_FL>>>(gq, gk, vproj, vres, gao);

    // output projection
    mma_gemm<128><<<dim3(4, 64), 256, SMEM_G128>>>(gao, wt_o, out, BT_, 512, 512);
}

// round 4
// speedup vs baseline: 2.6705x; 1.5476x over previous
#include <cuda_runtime.h>
#include <cuda_bf16.h>
#include <cstdint>
#include <math.h>

#define B_   4
#define T_   2048
#define H_   8
#define KVH_ 2
#define BT_  (B_ * T_)   // 8192
#define GQA_ (H_ / KVH_) // 4

// ---------------- scratch (device globals) ----------------------------------------
__device__ float g_xall [BT_ * 960];   // [DQ 0:256 | DKV 256:384 | KR 384:448 | VR 448:960]
__device__ float g_uqr  [BT_ * 512];   // [qnope 0:256 | qrope 256:512]
__device__ float g_ukv  [BT_ * 192];   // [knope 0:64 | vproj 64:192]
__device__ float g_q    [B_ * H_   * T_ * 64];
__device__ float g_k    [B_ * KVH_ * T_ * 64];
__device__ float g_ao   [BT_ * 512];
__device__ float g_cos  [T_ * 16];
__device__ float g_sin  [T_ * 16];

// combined transposed weights [N, K]
__device__ float g_wt_x  [960 * 512];
__device__ float g_wt_uqr[512 * 256];
__device__ float g_wt_ukv[192 * 128];
__device__ float g_wt_o  [512 * 512];

// ---------------- helpers ---------------------------------------------------------
__device__ __forceinline__ uint32_t tf32r(float v) {
    uint32_t r;
    asm("cvt.rna.tf32.f32 %0, %1;" : "=r"(r) : "f"(v));
    return r;
}
__device__ __forceinline__ uint32_t fbits(float v) { return __float_as_uint(v); }

// pack (x,y) -> bf16x2 hi + residual bf16x2 lo  (x in low half)
__device__ __forceinline__ void bf16split2(float x, float y, uint32_t& h, uint32_t& l) {
    asm("cvt.rn.bf16x2.f32 %0, %1, %2;" : "=r"(h) : "f"(y), "f"(x));
    __nv_bfloat162 hb = *reinterpret_cast<__nv_bfloat162*>(&h);
    float rx = x - __low2float(hb);
    float ry = y - __high2float(hb);
    asm("cvt.rn.bf16x2.f32 %0, %1, %2;" : "=r"(l) : "f"(ry), "f"(rx));
}

__device__ __forceinline__ void mma_bf16(float* c, const uint32_t* a,
                                         uint32_t b0, uint32_t b1) {
    asm volatile(
        "mma.sync.aligned.m16n8k16.row.col.f32.bf16.bf16.f32 "
        "{%0,%1,%2,%3}, {%4,%5,%6,%7}, {%8,%9}, {%0,%1,%2,%3};\n"
        : "+f"(c[0]), "+f"(c[1]), "+f"(c[2]), "+f"(c[3])
        : "r"(a[0]), "r"(a[1]), "r"(a[2]), "r"(a[3]), "r"(b0), "r"(b1));
}
__device__ __forceinline__ void mma_tf32(float* c, const uint32_t* a,
                                         uint32_t b0, uint32_t b1) {
    asm volatile(
        "mma.sync.aligned.m16n8k8.row.col.f32.tf32.tf32.f32 "
        "{%0,%1,%2,%3}, {%4,%5,%6,%7}, {%8,%9}, {%0,%1,%2,%3};\n"
        : "+f"(c[0]), "+f"(c[1]), "+f"(c[2]), "+f"(c[3])
        : "r"(a[0]), "r"(a[1]), "r"(a[2]), "r"(a[3]), "r"(b0), "r"(b1));
}

// ---------------- RoPE tables -----------------------------------------------------
__global__ void rope_tables_kernel() {
    int idx = blockIdx.x * blockDim.x + threadIdx.x;
    if (idx >= T_ * 16) return;
    int t = idx >> 4, i = idx & 15;
    double invf = pow(500000.0, -((double)(2 * i)) / 32.0);
    double ang  = (double)t * invf;
    g_cos[idx] = (float)cos(ang);
    g_sin[idx] = (float)sin(ang);
}

// ---------------- weight transpose: in [K,N] -> out [N,K] -------------------------
__global__ void transpose_kernel(const float* __restrict__ in, float* __restrict__ out,
                                 int K, int N) {
    __shared__ float t[32][33];
    int n0 = blockIdx.x * 32, k0 = blockIdx.y * 32;
    int x = threadIdx.x, y = threadIdx.y;
    #pragma unroll
    for (int d = 0; d < 32; d += 8)
        t[y + d][x] = in[(size_t)(k0 + y + d) * N + n0 + x];
    __syncthreads();
    #pragma unroll
    for (int d = 0; d < 32; d += 8)
        out[(size_t)(n0 + y + d) * K + k0 + x] = t[x][y + d];
}

// ---------------- bf16-3x mma GEMM: C[?,N] = A[128-rows,K] @ BT[N,K]^T --------------
// block 128 x TN, 256 threads, K chunks of 32, register-pipelined gmem loads.
// smem: packed bf16x2 hi/lo, row stride 20 u32 (conflict-free fragment loads).
template <int TN>
__global__ void __launch_bounds__(256)
mma_gemm(const float* __restrict__ A, const float* __restrict__ BT,
         float* __restrict__ C, int N, int K, int lda, int ldc) {
    extern __shared__ uint32_t us[];
    constexpr int SPU = 20;
    uint32_t* Ah = us;
    uint32_t* Al = Ah + 128 * SPU;
    uint32_t* Bh = Al + 128 * SPU;
    uint32_t* Bl = Bh + TN * SPU;

    constexpr int WMW    = (TN == 128) ? 2 : 4;
    constexpr int WARP_M = 128 / WMW;
    constexpr int MI     = WARP_M / 16;
    constexpr int BR     = TN / 32;   // B float4 loads per thread

    const int tid = threadIdx.x, wid = tid >> 5, lane = tid & 31;
    const int wm = wid % WMW, wn = wid / WMW;
    const int g = lane >> 2, t4 = lane & 3;
    const int m0 = blockIdx.y * 128, n0 = blockIdx.x * TN;

    const float* Ab = A + (size_t)m0 * lda;
    const float* Bb = BT + (size_t)n0 * K;

    float4 areg[4], breg[BR];
    #pragma unroll
    for (int j = 0; j < 4; j++) {
        int idx = tid + 256 * j, row = idx >> 3, q = idx & 7;
        areg[j] = *(const float4*)(Ab + (size_t)row * lda + q * 4);
    }
    #pragma unroll
    for (int j = 0; j < BR; j++) {
        int idx = tid + 256 * j, row = idx >> 3, q = idx & 7;
        breg[j] = *(const float4*)(Bb + (size_t)row * K + q * 4);
    }

    float c[MI][4][4];
    #pragma unroll
    for (int mi = 0; mi < MI; mi++)
        #pragma unroll
        for (int ni = 0; ni < 4; ni++)
            #pragma unroll
            for (int j = 0; j < 4; j++) c[mi][ni][j] = 0.f;

    const int NC = K >> 5;
    for (int ch = 0; ch < NC; ch++) {
        // convert staged regs -> smem
        #pragma unroll
        for (int j = 0; j < 4; j++) {
            int idx = tid + 256 * j, row = idx >> 3, q = idx & 7;
            uint32_t h0, l0, h1, l1;
            bf16split2(areg[j].x, areg[j].y, h0, l0);
            bf16split2(areg[j].z, areg[j].w, h1, l1);
            Ah[row * SPU + 2 * q]     = h0;
            Ah[row * SPU + 2 * q + 1] = h1;
            Al[row * SPU + 2 * q]     = l0;
            Al[row * SPU + 2 * q + 1] = l1;
        }
        #pragma unroll
        for (int j = 0; j < BR; j++) {
            int idx = tid + 256 * j, row = idx >> 3, q = idx & 7;
            uint32_t h0, l0, h1, l1;
            bf16split2(breg[j].x, breg[j].y, h0, l0);
            bf16split2(breg[j].z, breg[j].w, h1, l1);
            Bh[row * SPU + 2 * q]     = h0;
            Bh[row * SPU + 2 * q + 1] = h1;
            Bl[row * SPU + 2 * q]     = l0;
            Bl[row * SPU + 2 * q + 1] = l1;
        }
        __syncthreads();

        // prefetch next chunk into regs (latency overlaps compute)
        if (ch + 1 < NC) {
            int k0 = (ch + 1) * 32;
            #pragma unroll
            for (int j = 0; j < 4; j++) {
                int idx = tid + 256 * j, row = idx >> 3, q = idx & 7;
                areg[j] = *(const float4*)(Ab + (size_t)row * lda + k0 + q * 4);
            }
            #pragma unroll
            for (int j = 0; j < BR; j++) {
                int idx = tid + 256 * j, row = idx >> 3, q = idx & 7;
                breg[j] = *(const float4*)(Bb + (size_t)row * K + k0 + q * 4);
            }
        }

        #pragma unroll
        for (int ks = 0; ks < 2; ks++) {
            const int kp = ks * 8 + t4;
            uint32_t ah[MI][4], al[MI][4];
            #pragma unroll
            for (int mi = 0; mi < MI; mi++) {
                int r = wm * WARP_M + mi * 16 + g;
                ah[mi][0] = Ah[r * SPU + kp];
                ah[mi][1] = Ah[(r + 8) * SPU + kp];
                ah[mi][2] = Ah[r * SPU + kp + 4];
                ah[mi][3] = Ah[(r + 8) * SPU + kp + 4];
                al[mi][0] = Al[r * SPU + kp];
                al[mi][1] = Al[(r + 8) * SPU + kp];
                al[mi][2] = Al[r * SPU + kp + 4];
                al[mi][3] = Al[(r + 8) * SPU + kp + 4];
            }
            #pragma unroll
            for (int ni = 0; ni < 4; ni++) {
                int nr = wn * 32 + ni * 8 + g;
                uint32_t bh0 = Bh[nr * SPU + kp];
                uint32_t bh1 = Bh[nr * SPU + kp + 4];
                uint32_t bl0 = Bl[nr * SPU + kp];
                uint32_t bl1 = Bl[nr * SPU + kp + 4];
                #pragma unroll
                for (int mi = 0; mi < MI; mi++) {
                    mma_bf16(c[mi][ni], ah[mi], bh0, bh1);
                    mma_bf16(c[mi][ni], ah[mi], bl0, bl1);
                    mma_bf16(c[mi][ni], al[mi], bh0, bh1);
                }
            }
        }
        __syncthreads();
    }

    #pragma unroll
    for (int mi = 0; mi < MI; mi++) {
        int row = m0 + wm * WARP_M + mi * 16 + g;
        #pragma unroll
        for (int ni = 0; ni < 4; ni++) {
            int col = n0 + wn * 32 + ni * 8 + t4 * 2;
            *(float2*)(C + (size_t)row * ldc + col) =
                make_float2(c[mi][ni][0], c[mi][ni][1]);
            *(float2*)(C + (size_t)(row + 8) * ldc + col) =
                make_float2(c[mi][ni][2], c[mi][ni][3]);
        }
    }
}

// ---------------- strided in-place row RMSNorm ------------------------------------
__global__ void rmsnorm_kernel(float* __restrict__ X, int ld,
                               const float* __restrict__ w, int N, int rows) {
    int warp = (blockIdx.x * blockDim.x + threadIdx.x) >> 5;
    int lane = threadIdx.x & 31;
    if (warp >= rows) return;
    float* row = X + (size_t)warp * ld;
    float ss = 0.f;
    for (int c = lane; c < N; c += 32) { float v = row[c]; ss += v * v; }
    #pragma unroll
    for (int o = 16; o; o >>= 1) ss += __shfl_xor_sync(0xffffffffu, ss, o);
    float inv = rsqrtf(ss / (float)N + 1e-6f);
    for (int c = lane; c < N; c += 32) row[c] = row[c] * inv * w[c];
}

// ---------------- assemble q/k: RoPE + concat + per-head RMSNorm -------------------
__global__ void assemble_qk_kernel(const float* __restrict__ nope, int ns,
                                   const float* __restrict__ rope, int rs,
                                   const float* __restrict__ w,
                                   float* __restrict__ out, int NH) {
    int gw   = (blockIdx.x * blockDim.x + threadIdx.x) >> 5;
    int lane = threadIdx.x & 31;
    if (gw >= B_ * NH * T_) return;
    int t  = gw % T_;
    int bh = gw / T_;
    int h  = bh % NH;
    int b  = bh / NH;
    int tok = b * T_ + t;
    const float* np = nope + (size_t)tok * ns + h * 32;
    const float* rp = rope + (size_t)tok * rs + h * 32;

    float v0 = np[lane];
    int j = lane;
    float cs = g_cos[t * 16 + (j & 15)];
    float sn = g_sin[t * 16 + (j & 15)];
    float xj = rp[j];
    float xp = (j < 16) ? -rp[j + 16] : rp[j - 16];
    float v1 = xj * cs + xp * sn;

    float ss = v0 * v0 + v1 * v1;
    #pragma unroll
    for (int o = 16; o; o >>= 1) ss += __shfl_xor_sync(0xffffffffu, ss, o);
    float inv = rsqrtf(ss / 64.f + 1e-6f);

    float* op = out + (size_t)gw * 64;
    op[lane]      = v0 * inv * w[lane];
    op[lane + 32] = v1 * inv * w[lane + 32];
}

// ---------------- flash attention: S = bf16-3x mma, PV = tf32 mma ------------------
// 64 q-rows x 64 k-cols, 256 threads (8 warps). Warp: rows (wid>>1)*16, cols (wid&1)*32.
#define FSP 68
__global__ void __launch_bounds__(256)
flash_kernel(const float* __restrict__ q,
             const float* __restrict__ k,
             const float* __restrict__ vp, int ldv,
             const float* __restrict__ vres, int ldvr,
             float* __restrict__ ao) {
    extern __shared__ uint32_t us[];
    constexpr int QSP = 36;                 // u32 row stride for bf16x2 tiles
    uint32_t* QH = us;
    uint32_t* QL = QH + 64 * QSP;
    uint32_t* KH = QL + 64 * QSP;
    uint32_t* KL = KH + 64 * QSP;
    float* VT = (float*)(KL + 64 * QSP);    // V^T tf32 [d][c], stride FSP
    float* PS = VT + 64 * FSP;              // P fp32 [r][c], stride FSP
    float* MX = PS + 64 * FSP;              // 2 x 64
    float* SX = MX + 128;                   // 2 x 64

    const int tid = threadIdx.x, wid = tid >> 5, lane = tid & 31;
    const int g = lane >> 2, t4 = lane & 3;
    const int wr = (wid >> 1) * 16;
    const int wcol = wid & 1;
    const int wc = wcol * 32;

    const int qt = gridDim.x - 1 - blockIdx.x;   // big tiles first
    const int bh = blockIdx.y;
    const int b = bh / H_, h = bh % H_;
    const int kvh = h / GQA_;

    // Q tile -> bf16 hi/lo (once)
    const float* qbase = q + (((size_t)(b * H_ + h)) * T_ + qt * 64) * 64;
    #pragma unroll
    for (int j = 0; j < 4; j++) {
        int e = tid + 256 * j;
        int r = e >> 4, qq = e & 15;
        float4 v = *(const float4*)(qbase + r * 64 + qq * 4);
        uint32_t h0, l0, h1, l1;
        bf16split2(v.x, v.y, h0, l0);
        bf16split2(v.z, v.w, h1, l1);
        QH[r * QSP + 2 * qq]     = h0;
        QH[r * QSP + 2 * qq + 1] = h1;
        QL[r * QSP + 2 * qq]     = l0;
        QL[r * QSP + 2 * qq + 1] = l1;
    }

    float m0 = -1e30f, m1 = -1e30f, l0a = 0.f, l1a = 0.f;
    float o[4][4];
    #pragma unroll
    for (int ni = 0; ni < 4; ni++)
        #pragma unroll
        for (int j = 0; j < 4; j++) o[ni][j] = 0.f;

    const float* kbase = k + ((size_t)(b * KVH_ + kvh)) * T_ * 64;
    const float* vbase = vp + (size_t)b * T_ * ldv + kvh * 64;

    for (int kt = 0; kt <= qt; kt++) {
        // stage K/V gmem loads in regs before the barrier (hides LDG latency)
        float4 kreg[4], vreg[4];
        #pragma unroll
        for (int j = 0; j < 4; j++) {
            int e = tid + 256 * j;
            int cr = e >> 4, qq = e & 15;
            kreg[j] = *(const float4*)(kbase + (size_t)(kt * 64 + cr) * 64 + qq * 4);
            vreg[j] = *(const float4*)(vbase + (size_t)(kt * 64 + cr) * ldv + qq * 4);
        }
        __syncthreads();   // previous iteration's readers done
        #pragma unroll
        for (int j = 0; j < 4; j++) {
            int e = tid + 256 * j;
            int cr = e >> 4, qq = e & 15;
            uint32_t h0, lo0, h1, lo1;
            bf16split2(kreg[j].x, kreg[j].y, h0, lo0);
            bf16split2(kreg[j].z, kreg[j].w, h1, lo1);
            KH[cr * QSP + 2 * qq]     = h0;
            KH[cr * QSP + 2 * qq + 1] = h1;
            KL[cr * QSP + 2 * qq]     = lo0;
            KL[cr * QSP + 2 * qq + 1] = lo1;
            VT[(qq * 4 + 0) * FSP + cr] = __uint_as_float(tf32r(vreg[j].x));
            VT[(qq * 4 + 1) * FSP + cr] = __uint_as_float(tf32r(vreg[j].y));
            VT[(qq * 4 + 2) * FSP + cr] = __uint_as_float(tf32r(vreg[j].z));
            VT[(qq * 4 + 3) * FSP + cr] = __uint_as_float(tf32r(vreg[j].w));
        }
        __syncthreads();

        // ---- S = Q @ K^T  (bf16 3-term, m16n8k16) ----
        float s[4][4];
        #pragma unroll
        for (int ni = 0; ni < 4; ni++)
            #pragma unroll
            for (int j = 0; j < 4; j++) s[ni][j] = 0.f;

        #pragma unroll
        for (int ks = 0; ks < 4; ks++) {
            const int kp = ks * 8 + t4;
            const int r = wr + g;
            uint32_t ah[4], al[4];
            ah[0] = QH[r * QSP + kp];
            ah[1] = QH[(r + 8) * QSP + kp];
            ah[2] = QH[r * QSP + kp + 4];
            ah[3] = QH[(r + 8) * QSP + kp + 4];
            al[0] = QL[r * QSP + kp];
            al[1] = QL[(r + 8) * QSP + kp];
            al[2] = QL[r * QSP + kp + 4];
            al[3] = QL[(r + 8) * QSP + kp + 4];
            #pragma unroll
            for (int ni = 0; ni < 4; ni++) {
                int nr = wc + ni * 8 + g;
                uint32_t bh0 = KH[nr * QSP + kp];
                uint32_t bh1 = KH[nr * QSP + kp + 4];
                uint32_t bl0 = KL[nr * QSP + kp];
                uint32_t bl1 = KL[nr * QSP + kp + 4];
                mma_bf16(s[ni], ah, bh0, bh1);
                mma_bf16(s[ni], ah, bl0, bl1);
                mma_bf16(s[ni], al, bh0, bh1);
            }
        }

        // scale + causal mask
        const int rg0 = qt * 64 + wr + g;
        const int rg1 = rg0 + 8;
        #pragma unroll
        for (int ni = 0; ni < 4; ni++) {
            int cg = kt * 64 + wc + ni * 8 + t4 * 2;
            #pragma unroll
            for (int j = 0; j < 4; j++) {
                s[ni][j] *= 0.125f;
                int cc = cg + (j & 1);
                int rr = (j < 2) ? rg0 : rg1;
                if (cc > rr) s[ni][j] = -1e30f;
            }
        }

        // online softmax, stats shared across the 2 col-warps via smem
        float rm0 = fmaxf(fmaxf(s[0][0], s[0][1]), fmaxf(s[1][0], s[1][1]));
        rm0 = fmaxf(rm0, fmaxf(fmaxf(s[2][0], s[2][1]), fmaxf(s[3][0], s[3][1])));
        float rm1 = fmaxf(fmaxf(s[0][2], s[0][3]), fmaxf(s[1][2], s[1][3]));
        rm1 = fmaxf(rm1, fmaxf(fmaxf(s[2][2], s[2][3]), fmaxf(s[3][2], s[3][3])));
        #pragma unroll
        for (int off = 1; off <= 2; off <<= 1) {
            rm0 = fmaxf(rm0, __shfl_xor_sync(0xffffffffu, rm0, off));
            rm1 = fmaxf(rm1, __shfl_xor_sync(0xffffffffu, rm1, off));
        }
        if (t4 == 0) {
            MX[wcol * 64 + wr + g]     = rm0;
            MX[wcol * 64 + wr + g + 8] = rm1;
        }
        __syncthreads();
        float nm0 = fmaxf(m0, fmaxf(MX[wr + g],     MX[64 + wr + g]));
        float nm1 = fmaxf(m1, fmaxf(MX[wr + g + 8], MX[64 + wr + g + 8]));

        float su0 = 0.f, su1 = 0.f;
        #pragma unroll
        for (int ni = 0; ni < 4; ni++) {
            s[ni][0] = __expf(s[ni][0] - nm0);
            s[ni][1] = __expf(s[ni][1] - nm0);
            s[ni][2] = __expf(s[ni][2] - nm1);
            s[ni][3] = __expf(s[ni][3] - nm1);
            su0 += s[ni][0] + s[ni][1];
            su1 += s[ni][2] + s[ni][3];
        }
        #pragma unroll
        for (int off = 1; off <= 2; off <<= 1) {
            su0 += __shfl_xor_sync(0xffffffffu, su0, off);
            su1 += __shfl_xor_sync(0xffffffffu, su1, off);
        }
        if (t4 == 0) {
            SX[wcol * 64 + wr + g]     = su0;
            SX[wcol * 64 + wr + g + 8] = su1;
        }
        #pragma unroll
        for (int ni = 0; ni < 4; ni++) {
            int cb = wc + ni * 8 + t4 * 2;
            *(float2*)&PS[(wr + g) * FSP + cb]     = make_float2(s[ni][0], s[ni][1]);
            *(float2*)&PS[(wr + g + 8) * FSP + cb] = make_float2(s[ni][2], s[ni][3]);
        }
        float corr0 = __expf(m0 - nm0);
        float corr1 = __expf(m1 - nm1);
        m0 = nm0; m1 = nm1;
        #pragma unroll
        for (int ni = 0; ni < 4; ni++) {
            o[ni][0] *= corr0; o[ni][1] *= corr0;
            o[ni][2] *= corr1; o[ni][3] *= corr1;
        }
        __syncthreads();   // P + sums visible

        l0a = l0a * corr0 + SX[wr + g]     + SX[64 + wr + g];
        l1a = l1a * corr1 + SX[wr + g + 8] + SX[64 + wr + g + 8];

        // ---- O += P @ V  (tf32, m16n8k8) ----
        #pragma unroll
        for (int ks = 0; ks < 8; ks++) {
            const int col = ks * 8 + t4;
            const int r = wr + g;
            uint32_t ap[4];
            ap[0] = fbits(PS[r * FSP + col]);
            ap[1] = fbits(PS[(r + 8) * FSP + col]);
            ap[2] = fbits(PS[r * FSP + col + 4]);
            ap[3] = fbits(PS[(r + 8) * FSP + col + 4]);
            #pragma unroll
            for (int ni = 0; ni < 4; ni++) {
                int nr = wc + ni * 8 + g;
                uint32_t b0 = fbits(VT[nr * FSP + col]);
                uint32_t b1 = fbits(VT[nr * FSP + col + 4]);
                mma_tf32(o[ni], ap, b0, b1);
            }
        }
    }

    // epilogue
    float invl0 = 1.f / l0a, invl1 = 1.f / l1a;
    int r0 = qt * 64 + wr + g;
    #pragma unroll
    for (int ni = 0; ni < 4; ni++) {
        int col = wc + ni * 8 + t4 * 2;
        size_t vb0 = ((size_t)(b * T_ + r0)) * ldvr + h * 64 + col;
        size_t vb1 = ((size_t)(b * T_ + r0 + 8)) * ldvr + h * 64 + col;
        float2 vr0 = *(const float2*)(vres + vb0);
        float2 vr1 = *(const float2*)(vres + vb1);
        size_t ab0 = ((size_t)(b * T_ + r0)) * 512 + h * 64 + col;
        size_t ab1 = ((size_t)(b * T_ + r0 + 8)) * 512 + h * 64 + col;
        *(float2*)(ao + ab0) = make_float2(o[ni][0] * invl0 + vr0.x,
                                           o[ni][1] * invl0 + vr0.y);
        *(float2*)(ao + ab1) = make_float2(o[ni][2] * invl1 + vr1.x,
                                           o[ni][3] * invl1 + vr1.y);
    }
}

// ---------------- launch ----------------------------------------------------------
extern "C" void kernel_launch(void* const* d_in, const int* in_sizes, int n_in,
                              void* d_out, int out_size) {
    const float* x        = (const float*)d_in[0];
    const float* W_DQ     = (const float*)d_in[1];
    const float* W_UQ     = (const float*)d_in[2];
    const float* W_QR     = (const float*)d_in[3];
    const float* W_DKV    = (const float*)d_in[4];
    const float* W_UK     = (const float*)d_in[5];
    const float* W_UV     = (const float*)d_in[6];
    const float* W_KR     = (const float*)d_in[7];
    const float* W_VR     = (const float*)d_in[8];
    const float* W_O      = (const float*)d_in[9];
    const float* q_ln_w   = (const float*)d_in[10];
    const float* kv_ln_w  = (const float*)d_in[11];
    const float* q_head_w = (const float*)d_in[12];
    const float* k_head_w = (const float*)d_in[13];
    float* out = (float*)d_out;

    float *xall, *uqr, *ukv, *gq, *gk, *gao, *wt_x, *wt_uqr, *wt_ukv, *wt_o;
    cudaGetSymbolAddress((void**)&xall,   g_xall);
    cudaGetSymbolAddress((void**)&uqr,    g_uqr);
    cudaGetSymbolAddress((void**)&ukv,    g_ukv);
    cudaGetSymbolAddress((void**)&gq,     g_q);
    cudaGetSymbolAddress((void**)&gk,     g_k);
    cudaGetSymbolAddress((void**)&gao,    g_ao);
    cudaGetSymbolAddress((void**)&wt_x,   g_wt_x);
    cudaGetSymbolAddress((void**)&wt_uqr, g_wt_uqr);
    cudaGetSymbolAddress((void**)&wt_ukv, g_wt_ukv);
    cudaGetSymbolAddress((void**)&wt_o,   g_wt_o);

    const int SMEM_G128 = (128 + 128 + 128 + 128) * 20 * 4;   // 40960
    const int SMEM_G64  = (128 + 128 + 64 + 64) * 20 * 4;     // 30720
    const int SMEM_FL   = (4 * 64 * 36) * 4 + (2 * 64 * 68 + 256) * 4;  // 72704
    cudaFuncSetAttribute(flash_kernel, cudaFuncAttributeMaxDynamicSharedMemorySize, SMEM_FL);

    rope_tables_kernel<<<(T_ * 16 + 255) / 256, 256>>>();

    dim3 tb(32, 8);
    // wt_x rows: [DQ 0:256 | DKV 256:384 | KR 384:448 | VR 448:960]
    transpose_kernel<<<dim3(8, 16),  tb>>>(W_DQ,  wt_x,              512, 256);
    transpose_kernel<<<dim3(4, 16),  tb>>>(W_DKV, wt_x + 256 * 512,  512, 128);
    transpose_kernel<<<dim3(2, 16),  tb>>>(W_KR,  wt_x + 384 * 512,  512,  64);
    transpose_kernel<<<dim3(16, 16), tb>>>(W_VR,  wt_x + 448 * 512,  512, 512);
    transpose_kernel<<<dim3(8, 8),   tb>>>(W_UQ,  wt_uqr,            256, 256);
    transpose_kernel<<<dim3(8, 8),   tb>>>(W_QR,  wt_uqr + 256 * 256, 256, 256);
    transpose_kernel<<<dim3(2, 4),   tb>>>(W_UK,  wt_ukv,            128,  64);
    transpose_kernel<<<dim3(4, 4),   tb>>>(W_UV,  wt_ukv + 64 * 128, 128, 128);
    transpose_kernel<<<dim3(16, 16), tb>>>(W_O,   wt_o,              512, 512);

    // all x-projections in one GEMM: [8192,512] @ [512,960]
    mma_gemm<64><<<dim3(15, 64), 256, SMEM_G64>>>(x, wt_x, xall, 960, 512, 512, 960);

    // latent RMSNorms (strided views into xall)
    rmsnorm_kernel<<<BT_ / 8, 256>>>(xall,       960, q_ln_w,  256, BT_);
    rmsnorm_kernel<<<BT_ / 8, 256>>>(xall + 256, 960, kv_ln_w, 128, BT_);

    // up-projections
    mma_gemm<128><<<dim3(4, 64), 256, SMEM_G128>>>(xall,       wt_uqr, uqr, 512, 256, 960, 512);
    mma_gemm<64> <<<dim3(3, 64), 256, SMEM_G64 >>>(xall + 256, wt_ukv, ukv, 192, 128, 960, 192);

    // RoPE + concat + head RMSNorm
    assemble_qk_kernel<<<B_ * H_   * T_ / 8, 256>>>(uqr, 512, uqr + 256, 512, q_head_w, gq, H_);
    assemble_qk_kernel<<<B_ * KVH_ * T_ / 8, 256>>>(ukv, 192, xall + 384, 960, k_head_w, gk, KVH_);

    // causal flash attention + value residual
    flash_kernel<<<dim3(T_ / 64, B_ * H_), 256, SMEM_FL>>>(
        gq, gk, ukv + 64, 192, xall + 448, 960, gao);

    // output projection
    mma_gemm<128><<<dim3(4, 64), 256, SMEM_G128>>>(gao, wt_o, out, 512, 512, 512, 512);
}

// round 6
// speedup vs baseline: 3.6786x; 1.3775x over previous
#include <cuda_runtime.h>
#include <cuda_bf16.h>
#include <cstdint>
#include <math.h>

#define B_   4
#define T_   2048
#define H_   8
#define KVH_ 2
#define BT_  (B_ * T_)   // 8192
#define GQA_ (H_ / KVH_) // 4

// ---------------- scratch (device globals) ----------------------------------------
__device__ float g_xall [BT_ * 960];   // [DQ 0:256 | DKV 256:384 | KR 384:448 | VR 448:960]
__device__ float g_uqr  [BT_ * 512];   // [qnope 0:256 | qrope 256:512]
__device__ float g_ukv  [BT_ * 192];   // [knope 0:64 | vproj 64:192]
__device__ float g_q    [B_ * H_   * T_ * 64];
__device__ float g_k    [B_ * KVH_ * T_ * 64];
__device__ float g_ao   [BT_ * 512];
__device__ float g_cos  [T_ * 16];
__device__ float g_sin  [T_ * 16];

__device__ float g_wt_x  [960 * 512];
__device__ float g_wt_uqr[512 * 256];
__device__ float g_wt_ukv[192 * 128];
__device__ float g_wt_o  [512 * 512];

// ---------------- helpers ---------------------------------------------------------
__device__ __forceinline__ uint32_t sptr(const void* p) {
    return (uint32_t)__cvta_generic_to_shared(p);
}
__device__ __forceinline__ uint32_t pack2(float x, float y) {   // x -> low half
    uint32_t r;
    asm("cvt.rn.bf16x2.f32 %0, %1, %2;" : "=r"(r) : "f"(y), "f"(x));
    return r;
}
__device__ __forceinline__ void bf16split2(float x, float y, uint32_t& h, uint32_t& l) {
    asm("cvt.rn.bf16x2.f32 %0, %1, %2;" : "=r"(h) : "f"(y), "f"(x));
    __nv_bfloat162 hb = *reinterpret_cast<__nv_bfloat162*>(&h);
    float rx = x - __low2float(hb);
    float ry = y - __high2float(hb);
    asm("cvt.rn.bf16x2.f32 %0, %1, %2;" : "=r"(l) : "f"(ry), "f"(rx));
}
__device__ __forceinline__ void mma_bf16(float* c, const uint32_t* a,
                                         uint32_t b0, uint32_t b1) {
    asm volatile(
        "mma.sync.aligned.m16n8k16.row.col.f32.bf16.bf16.f32 "
        "{%0,%1,%2,%3}, {%4,%5,%6,%7}, {%8,%9}, {%0,%1,%2,%3};\n"
        : "+f"(c[0]), "+f"(c[1]), "+f"(c[2]), "+f"(c[3])
        : "r"(a[0]), "r"(a[1]), "r"(a[2]), "r"(a[3]), "r"(b0), "r"(b1));
}
__device__ __forceinline__ void ldm4(uint32_t* r, uint32_t addr) {
    asm volatile("ldmatrix.sync.aligned.m8n8.x4.shared.b16 {%0,%1,%2,%3}, [%4];"
                 : "=r"(r[0]), "=r"(r[1]), "=r"(r[2]), "=r"(r[3]) : "r"(addr));
}
__device__ __forceinline__ void ldm4t(uint32_t* r, uint32_t addr) {
    asm volatile("ldmatrix.sync.aligned.m8n8.x4.trans.shared.b16 {%0,%1,%2,%3}, [%4];"
                 : "=r"(r[0]), "=r"(r[1]), "=r"(r[2]), "=r"(r[3]) : "r"(addr));
}

// ---------------- fused prep: 9 weight transposes + rope tables --------------------
struct PrepArgs {
    const float* src[9];
    float*       dst[9];
    int K[9], N[9];
    int off[10];
};

__global__ void prep_kernel(PrepArgs a) {
    __shared__ float tb[32][33];
    int bx = blockIdx.x;
    int x = threadIdx.x, y = threadIdx.y;
    if (bx >= a.off[9]) {
        int idx = (bx - a.off[9]) * 256 + y * 32 + x;
        if (idx < T_ * 16) {
            int t = idx >> 4, i = idx & 15;
            double invf = pow(500000.0, -((double)(2 * i)) / 32.0);
            double ang  = (double)t * invf;
            g_cos[idx] = (float)cos(ang);
            g_sin[idx] = (float)sin(ang);
        }
        return;
    }
    int m = 0;
    #pragma unroll
    for (int i = 1; i < 9; i++) if (bx >= a.off[i]) m = i;
    int lt = bx - a.off[m];
    int N = a.N[m], K = a.K[m];
    int ntx = N >> 5;
    int n0 = (lt % ntx) * 32, k0 = (lt / ntx) * 32;
    const float* in = a.src[m];
    float* out = a.dst[m];
    #pragma unroll
    for (int d = 0; d < 32; d += 8)
        tb[y + d][x] = in[(size_t)(k0 + y + d) * N + n0 + x];
    __syncthreads();
    #pragma unroll
    for (int d = 0; d < 32; d += 8)
        out[(size_t)(n0 + y + d) * K + k0 + x] = tb[x][y + d];
}

// ---------------- bf16-3x mma GEMM with ldmatrix ----------------------------------
// C[?,N] = A[128-rows,K] @ BT[N,K]^T. block 128 x TN, 256 threads, K chunks of 32.
template <int TN>
__global__ void __launch_bounds__(256)
mma_gemm(const float* __restrict__ A, const float* __restrict__ BT,
         float* __restrict__ C, int N, int K, int lda, int ldc) {
    extern __shared__ uint32_t us[];
    constexpr int SPU = 20;
    uint32_t* Ah = us;
    uint32_t* Al = Ah + 128 * SPU;
    uint32_t* Bh = Al + 128 * SPU;
    uint32_t* Bl = Bh + TN * SPU;

    constexpr int WMW    = (TN == 128) ? 2 : 4;
    constexpr int WARP_M = 128 / WMW;
    constexpr int MI     = WARP_M / 16;
    constexpr int BR     = TN / 32;

    const int tid = threadIdx.x, wid = tid >> 5, lane = tid & 31;
    const int wm = wid % WMW, wn = wid / WMW;
    const int g = lane >> 2, t4 = lane & 3;
    const int m0 = blockIdx.y * 128, n0 = blockIdx.x * TN;

    const uint32_t sAh = sptr(Ah), sBh = sptr(Bh);
    const uint32_t ALO = 128 * SPU * 4, BLO = TN * SPU * 4;
    const int      lrA = lane & 15;
    const uint32_t lcA = (uint32_t)(lane >> 4) * 16;
    const int      lrB = (lane & 7) | ((lane >> 4) << 3);
    const uint32_t lcB = (uint32_t)((lane >> 3) & 1) * 16;

    const float* Ab = A + (size_t)m0 * lda;
    const float* Bb = BT + (size_t)n0 * K;

    float4 areg[4], breg[BR];
    #pragma unroll
    for (int j = 0; j < 4; j++) {
        int idx = tid + 256 * j, row = idx >> 3, q = idx & 7;
        areg[j] = *(const float4*)(Ab + (size_t)row * lda + q * 4);
    }
    #pragma unroll
    for (int j = 0; j < BR; j++) {
        int idx = tid + 256 * j, row = idx >> 3, q = idx & 7;
        breg[j] = *(const float4*)(Bb + (size_t)row * K + q * 4);
    }

    float c[MI][4][4];
    #pragma unroll
    for (int mi = 0; mi < MI; mi++)
        #pragma unroll
        for (int ni = 0; ni < 4; ni++)
            #pragma unroll
            for (int j = 0; j < 4; j++) c[mi][ni][j] = 0.f;

    const int NC = K >> 5;
    for (int ch = 0; ch < NC; ch++) {
        #pragma unroll
        for (int j = 0; j < 4; j++) {
            int idx = tid + 256 * j, row = idx >> 3, q = idx & 7;
            uint32_t h0, l0, h1, l1;
            bf16split2(areg[j].x, areg[j].y, h0, l0);
            bf16split2(areg[j].z, areg[j].w, h1, l1);
            *(uint2*)&Ah[row * SPU + 2 * q] = make_uint2(h0, h1);
            *(uint2*)&Al[row * SPU + 2 * q] = make_uint2(l0, l1);
        }
        #pragma unroll
        for (int j = 0; j < BR; j++) {
            int idx = tid + 256 * j, row = idx >> 3, q = idx & 7;
            uint32_t h0, l0, h1, l1;
            bf16split2(breg[j].x, breg[j].y, h0, l0);
            bf16split2(breg[j].z, breg[j].w, h1, l1);
            *(uint2*)&Bh[row * SPU + 2 * q] = make_uint2(h0, h1);
            *(uint2*)&Bl[row * SPU + 2 * q] = make_uint2(l0, l1);
        }
        __syncthreads();

        if (ch + 1 < NC) {
            int k0 = (ch + 1) * 32;
            #pragma unroll
            for (int j = 0; j < 4; j++) {
                int idx = tid + 256 * j, row = idx >> 3, q = idx & 7;
                areg[j] = *(const float4*)(Ab + (size_t)row * lda + k0 + q * 4);
            }
            #pragma unroll
            for (int j = 0; j < BR; j++) {
                int idx = tid + 256 * j, row = idx >> 3, q = idx & 7;
                breg[j] = *(const float4*)(Bb + (size_t)row * K + k0 + q * 4);
            }
        }

        #pragma unroll
        for (int ks = 0; ks < 2; ks++) {
            uint32_t ah[MI][4], al[MI][4];
            #pragma unroll
            for (int mi = 0; mi < MI; mi++) {
                uint32_t ad = sAh + (uint32_t)((wm * WARP_M + mi * 16 + lrA) * SPU) * 4
                              + ks * 32 + lcA;
                ldm4(ah[mi], ad);
                ldm4(al[mi], ad + ALO);
            }
            #pragma unroll
            for (int p = 0; p < 2; p++) {
                uint32_t bd = sBh + (uint32_t)((wn * 32 + p * 16 + lrB) * SPU) * 4
                              + ks * 32 + lcB;
                uint32_t bh2[4], bl2[4];
                ldm4(bh2, bd);
                ldm4(bl2, bd + BLO);
                #pragma unroll
                for (int mi = 0; mi < MI; mi++) {
                    mma_bf16(c[mi][2 * p],     ah[mi], bh2[0], bh2[1]);
                    mma_bf16(c[mi][2 * p],     ah[mi], bl2[0], bl2[1]);
                    mma_bf16(c[mi][2 * p],     al[mi], bh2[0], bh2[1]);
                    mma_bf16(c[mi][2 * p + 1], ah[mi], bh2[2], bh2[3]);
                    mma_bf16(c[mi][2 * p + 1], ah[mi], bl2[2], bl2[3]);
                    mma_bf16(c[mi][2 * p + 1], al[mi], bh2[2], bh2[3]);
                }
            }
        }
        __syncthreads();
    }

    #pragma unroll
    for (int mi = 0; mi < MI; mi++) {
        int row = m0 + wm * WARP_M + mi * 16 + g;
        #pragma unroll
        for (int ni = 0; ni < 4; ni++) {
            int col = n0 + wn * 32 + ni * 8 + t4 * 2;
            *(float2*)(C + (size_t)row * ldc + col) =
                make_float2(c[mi][ni][0], c[mi][ni][1]);
            *(float2*)(C + (size_t)(row + 8) * ldc + col) =
                make_float2(c[mi][ni][2], c[mi][ni][3]);
        }
    }
}

// ---------------- strided in-place row RMSNorm ------------------------------------
__global__ void rmsnorm_kernel(float* __restrict__ X, int ld,
                               const float* __restrict__ w, int N, int rows) {
    int warp = (blockIdx.x * blockDim.x + threadIdx.x) >> 5;
    int lane = threadIdx.x & 31;
    if (warp >= rows) return;
    float* row = X + (size_t)warp * ld;
    float ss = 0.f;
    for (int c = lane; c < N; c += 32) { float v = row[c]; ss += v * v; }
    #pragma unroll
    for (int o = 16; o; o >>= 1) ss += __shfl_xor_sync(0xffffffffu, ss, o);
    float inv = rsqrtf(ss / (float)N + 1e-6f);
    for (int c = lane; c < N; c += 32) row[c] = row[c] * inv * w[c];
}

// ---------------- assemble q/k: RoPE + concat + per-head RMSNorm -------------------
__global__ void assemble_qk_kernel(const float* __restrict__ nope, int ns,
                                   const float* __restrict__ rope, int rs,
                                   const float* __restrict__ w,
                                   float* __restrict__ out, int NH) {
    int gw   = (blockIdx.x * blockDim.x + threadIdx.x) >> 5;
    int lane = threadIdx.x & 31;
    if (gw >= B_ * NH * T_) return;
    int t  = gw % T_;
    int bh = gw / T_;
    int h  = bh % NH;
    int b  = bh / NH;
    int tok = b * T_ + t;
    const float* np = nope + (size_t)tok * ns + h * 32;
    const float* rp = rope + (size_t)tok * rs + h * 32;

    float v0 = np[lane];
    int j = lane;
    float cs = g_cos[t * 16 + (j & 15)];
    float sn = g_sin[t * 16 + (j & 15)];
    float xj = rp[j];
    float xp = (j < 16) ? -rp[j + 16] : rp[j - 16];
    float v1 = xj * cs + xp * sn;

    float ss = v0 * v0 + v1 * v1;
    #pragma unroll
    for (int o = 16; o; o >>= 1) ss += __shfl_xor_sync(0xffffffffu, ss, o);
    float inv = rsqrtf(ss / 64.f + 1e-6f);

    float* op = out + (size_t)gw * 64;
    op[lane]      = v0 * inv * w[lane];
    op[lane + 32] = v1 * inv * w[lane + 32];
}

// ---------------- flash attention: all-bf16 mma, register-resident P ---------------
// 64x64 tiles, 256 threads. S: warp = rows (wid>>1)*16 x cols (wid&1)*32 (3-term bf16).
// PV: warp accumulates partial O(rows, ALL 64 d) over its 32-col c range; partials
// from the two col-warps are summed once at the end.
// NOTE: Q/K rows hold 64 floats -> 32 packed u32 -> stride 36 (NOT the GEMM's 20).
__global__ void __launch_bounds__(256)
flash_kernel(const float* __restrict__ q,
             const float* __restrict__ k,
             const float* __restrict__ vp, int ldv,
             const float* __restrict__ vres, int ldvr,
             float* __restrict__ ao) {
    extern __shared__ uint32_t us[];
    constexpr int SP = 36, VSP = 36, RSP = 66;
    uint32_t* QH = us;                  // 64*36
    uint32_t* QL = QH + 64 * SP;
    uint32_t* KH = QL + 64 * SP;
    uint32_t* KL = KH + 64 * SP;
    uint32_t* VS = KL + 64 * SP;        // [c][d packed bf16x2], 64*36
    float* MX = (float*)(VS + 64 * VSP);   // 2 x 64
    float* SX = MX + 128;                  // 2 x 64
    float* RD = SX + 128;                  // 64 x 66

    const int tid = threadIdx.x, wid = tid >> 5, lane = tid & 31;
    const int g = lane >> 2, t4 = lane & 3;
    const int wr = (wid >> 1) * 16;
    const int wcol = wid & 1;
    const int wc = wcol * 32;

    const int qt = gridDim.x - 1 - blockIdx.x;
    const int bh = blockIdx.y;
    const int b = bh / H_, h = bh % H_;
    const int kvh = h / GQA_;

    const uint32_t sQH = sptr(QH), sKH = sptr(KH), sVS = sptr(VS);
    const uint32_t QLO = 64 * SP * 4, KLO = 64 * SP * 4;
    const int      lrA = lane & 15;
    const uint32_t lcA = (uint32_t)(lane >> 4) * 16;
    const int      lrB = (lane & 7) | ((lane >> 4) << 3);
    const uint32_t lcB = (uint32_t)((lane >> 3) & 1) * 16;
    const int      lrV = (lane & 7) | (((lane >> 3) & 1) << 3);
    const uint32_t lcV = (uint32_t)(lane >> 4) * 16;

    // Q tile -> bf16 hi/lo (once)
    const float* qbase = q + (((size_t)(b * H_ + h)) * T_ + qt * 64) * 64;
    #pragma unroll
    for (int j = 0; j < 4; j++) {
        int e = tid + 256 * j;
        int r = e >> 4, qq = e & 15;
        float4 v = *(const float4*)(qbase + r * 64 + qq * 4);
        uint32_t h0, l0, h1, l1;
        bf16split2(v.x, v.y, h0, l0);
        bf16split2(v.z, v.w, h1, l1);
        *(uint2*)&QH[r * SP + 2 * qq] = make_uint2(h0, h1);
        *(uint2*)&QL[r * SP + 2 * qq] = make_uint2(l0, l1);
    }

    float mprev0 = -1e30f, mprev1 = -1e30f, l0a = 0.f, l1a = 0.f;
    float o[8][4];
    #pragma unroll
    for (int ni = 0; ni < 8; ni++)
        #pragma unroll
        for (int j = 0; j < 4; j++) o[ni][j] = 0.f;

    const float* kbase = k + ((size_t)(b * KVH_ + kvh)) * T_ * 64;
    const float* vbase = vp + (size_t)b * T_ * ldv + kvh * 64;

    for (int kt = 0; kt <= qt; kt++) {
        float4 kreg[4], vreg[4];
        #pragma unroll
        for (int j = 0; j < 4; j++) {
            int e = tid + 256 * j;
            int cr = e >> 4, qq = e & 15;
            kreg[j] = *(const float4*)(kbase + (size_t)(kt * 64 + cr) * 64 + qq * 4);
            vreg[j] = *(const float4*)(vbase + (size_t)(kt * 64 + cr) * ldv + qq * 4);
        }
        __syncthreads();   // previous iteration's readers done
        #pragma unroll
        for (int j = 0; j < 4; j++) {
            int e = tid + 256 * j;
            int cr = e >> 4, qq = e & 15;
            uint32_t h0, l0, h1, l1;
            bf16split2(kreg[j].x, kreg[j].y, h0, l0);
            bf16split2(kreg[j].z, kreg[j].w, h1, l1);
            *(uint2*)&KH[cr * SP + 2 * qq] = make_uint2(h0, h1);
            *(uint2*)&KL[cr * SP + 2 * qq] = make_uint2(l0, l1);
            *(uint2*)&VS[cr * VSP + 2 * qq] =
                make_uint2(pack2(vreg[j].x, vreg[j].y), pack2(vreg[j].z, vreg[j].w));
        }
        __syncthreads();

        // ---- S = Q @ K^T (3-term bf16, ldmatrix) ----
        float s[4][4];
        #pragma unroll
        for (int ni = 0; ni < 4; ni++)
            #pragma unroll
            for (int j = 0; j < 4; j++) s[ni][j] = 0.f;

        #pragma unroll
        for (int ks = 0; ks < 4; ks++) {
            uint32_t ad = sQH + (uint32_t)((wr + lrA) * SP) * 4 + ks * 32 + lcA;
            uint32_t ah[4], al[4];
            ldm4(ah, ad);
            ldm4(al, ad + QLO);
            #pragma unroll
            for (int p = 0; p < 2; p++) {
                uint32_t bd = sKH + (uint32_t)((wc + p * 16 + lrB) * SP) * 4
                              + ks * 32 + lcB;
                uint32_t bh2[4], bl2[4];
                ldm4(bh2, bd);
                ldm4(bl2, bd + KLO);
                mma_bf16(s[2 * p],     ah, bh2[0], bh2[1]);
                mma_bf16(s[2 * p],     ah, bl2[0], bl2[1]);
                mma_bf16(s[2 * p],     al, bh2[0], bh2[1]);
                mma_bf16(s[2 * p + 1], ah, bh2[2], bh2[3]);
                mma_bf16(s[2 * p + 1], ah, bl2[2], bl2[3]);
                mma_bf16(s[2 * p + 1], al, bh2[2], bh2[3]);
            }
        }

        // scale + causal mask
        const int rg0 = qt * 64 + wr + g;
        const int rg1 = rg0 + 8;
        #pragma unroll
        for (int ni = 0; ni < 4; ni++) {
            int cg = kt * 64 + wc + ni * 8 + t4 * 2;
            #pragma unroll
            for (int j = 0; j < 4; j++) {
                s[ni][j] *= 0.125f;
                int cc = cg + (j & 1);
                int rr = (j < 2) ? rg0 : rg1;
                if (cc > rr) s[ni][j] = -1e30f;
            }
        }

        // warp-local max + exp + local sum; single-barrier exchange
        float rm0 = fmaxf(fmaxf(s[0][0], s[0][1]), fmaxf(s[1][0], s[1][1]));
        rm0 = fmaxf(rm0, fmaxf(fmaxf(s[2][0], s[2][1]), fmaxf(s[3][0], s[3][1])));
        float rm1 = fmaxf(fmaxf(s[0][2], s[0][3]), fmaxf(s[1][2], s[1][3]));
        rm1 = fmaxf(rm1, fmaxf(fmaxf(s[2][2], s[2][3]), fmaxf(s[3][2], s[3][3])));
        #pragma unroll
        for (int off = 1; off <= 2; off <<= 1) {
            rm0 = fmaxf(rm0, __shfl_xor_sync(0xffffffffu, rm0, off));
            rm1 = fmaxf(rm1, __shfl_xor_sync(0xffffffffu, rm1, off));
        }
        float su0 = 0.f, su1 = 0.f;
        #pragma unroll
        for (int ni = 0; ni < 4; ni++) {
            s[ni][0] = __expf(s[ni][0] - rm0);
            s[ni][1] = __expf(s[ni][1] - rm0);
            s[ni][2] = __expf(s[ni][2] - rm1);
            s[ni][3] = __expf(s[ni][3] - rm1);
            su0 += s[ni][0] + s[ni][1];
            su1 += s[ni][2] + s[ni][3];
        }
        #pragma unroll
        for (int off = 1; off <= 2; off <<= 1) {
            su0 += __shfl_xor_sync(0xffffffffu, su0, off);
            su1 += __shfl_xor_sync(0xffffffffu, su1, off);
        }
        if (t4 == 0) {
            MX[wcol * 64 + wr + g]     = rm0;
            MX[wcol * 64 + wr + g + 8] = rm1;
            SX[wcol * 64 + wr + g]     = su0;
            SX[wcol * 64 + wr + g + 8] = su1;
        }
        __syncthreads();

        float ra0 = MX[wr + g],     rb0 = MX[64 + wr + g];
        float ra1 = MX[wr + g + 8], rb1 = MX[64 + wr + g + 8];
        float nm0 = fmaxf(mprev0, fmaxf(ra0, rb0));
        float nm1 = fmaxf(mprev1, fmaxf(ra1, rb1));
        float corr0 = __expf(mprev0 - nm0);
        float corr1 = __expf(mprev1 - nm1);
        l0a = l0a * corr0 + SX[wr + g] * __expf(ra0 - nm0)
                          + SX[64 + wr + g] * __expf(rb0 - nm0);
        l1a = l1a * corr1 + SX[wr + g + 8] * __expf(ra1 - nm1)
                          + SX[64 + wr + g + 8] * __expf(rb1 - nm1);
        float f0 = __expf(rm0 - nm0);
        float f1 = __expf(rm1 - nm1);
        mprev0 = nm0; mprev1 = nm1;

        #pragma unroll
        for (int ni = 0; ni < 4; ni++) {
            s[ni][0] *= f0; s[ni][1] *= f0;
            s[ni][2] *= f1; s[ni][3] *= f1;
        }
        #pragma unroll
        for (int ni = 0; ni < 8; ni++) {
            o[ni][0] *= corr0; o[ni][1] *= corr0;
            o[ni][2] *= corr1; o[ni][3] *= corr1;
        }

        // ---- O_partial += P(this warp's 32 cols) @ V  (bf16, register P) ----
        #pragma unroll
        for (int ks = 0; ks < 2; ks++) {
            uint32_t pa[4];
            pa[0] = pack2(s[2 * ks][0],     s[2 * ks][1]);
            pa[1] = pack2(s[2 * ks][2],     s[2 * ks][3]);
            pa[2] = pack2(s[2 * ks + 1][0], s[2 * ks + 1][1]);
            pa[3] = pack2(s[2 * ks + 1][2], s[2 * ks + 1][3]);
            #pragma unroll
            for (int db = 0; db < 4; db++) {
                uint32_t vd = sVS + (uint32_t)((wc + ks * 16 + lrV) * VSP) * 4
                              + db * 32 + lcV;
                uint32_t bv[4];
                ldm4t(bv, vd);
                mma_bf16(o[2 * db],     pa, bv[0], bv[1]);
                mma_bf16(o[2 * db + 1], pa, bv[2], bv[3]);
            }
        }
    }

    // cross-warp partial-O reduction + epilogue
    if (wcol == 1) {
        #pragma unroll
        for (int ni = 0; ni < 8; ni++) {
            int col = ni * 8 + 2 * t4;
            *(float2*)&RD[(wr + g) * RSP + col]     = make_float2(o[ni][0], o[ni][1]);
            *(float2*)&RD[(wr + g + 8) * RSP + col] = make_float2(o[ni][2], o[ni][3]);
        }
    }
    __syncthreads();
    if (wcol == 0) {
        float invl0 = 1.f / l0a, invl1 = 1.f / l1a;
        int r0 = qt * 64 + wr + g;
        #pragma unroll
        for (int ni = 0; ni < 8; ni++) {
            int col = ni * 8 + 2 * t4;
            float2 p0 = *(float2*)&RD[(wr + g) * RSP + col];
            float2 p1 = *(float2*)&RD[(wr + g + 8) * RSP + col];
            size_t vb0 = ((size_t)(b * T_ + r0)) * ldvr + h * 64 + col;
            size_t vb1 = ((size_t)(b * T_ + r0 + 8)) * ldvr + h * 64 + col;
            float2 vr0 = *(const float2*)(vres + vb0);
            float2 vr1 = *(const float2*)(vres + vb1);
            size_t ab0 = ((size_t)(b * T_ + r0)) * 512 + h * 64 + col;
            size_t ab1 = ((size_t)(b * T_ + r0 + 8)) * 512 + h * 64 + col;
            *(float2*)(ao + ab0) = make_float2((o[ni][0] + p0.x) * invl0 + vr0.x,
                                               (o[ni][1] + p0.y) * invl0 + vr0.y);
            *(float2*)(ao + ab1) = make_float2((o[ni][2] + p1.x) * invl1 + vr1.x,
                                               (o[ni][3] + p1.y) * invl1 + vr1.y);
        }
    }
}

// ---------------- launch ----------------------------------------------------------
extern "C" void kernel_launch(void* const* d_in, const int* in_sizes, int n_in,
                              void* d_out, int out_size) {
    const float* x        = (const float*)d_in[0];
    const float* W_DQ     = (const float*)d_in[1];
    const float* W_UQ     = (const float*)d_in[2];
    const float* W_QR     = (const float*)d_in[3];
    const float* W_DKV    = (const float*)d_in[4];
    const float* W_UK     = (const float*)d_in[5];
    const float* W_UV     = (const float*)d_in[6];
    const float* W_KR     = (const float*)d_in[7];
    const float* W_VR     = (const float*)d_in[8];
    const float* W_O      = (const float*)d_in[9];
    const float* q_ln_w   = (const float*)d_in[10];
    const float* kv_ln_w  = (const float*)d_in[11];
    const float* q_head_w = (const float*)d_in[12];
    const float* k_head_w = (const float*)d_in[13];
    float* out = (float*)d_out;

    float *xall, *uqr, *ukv, *gq, *gk, *gao, *wt_x, *wt_uqr, *wt_ukv, *wt_o;
    cudaGetSymbolAddress((void**)&xall,   g_xall);
    cudaGetSymbolAddress((void**)&uqr,    g_uqr);
    cudaGetSymbolAddress((void**)&ukv,    g_ukv);
    cudaGetSymbolAddress((void**)&gq,     g_q);
    cudaGetSymbolAddress((void**)&gk,     g_k);
    cudaGetSymbolAddress((void**)&gao,    g_ao);
    cudaGetSymbolAddress((void**)&wt_x,   g_wt_x);
    cudaGetSymbolAddress((void**)&wt_uqr, g_wt_uqr);
    cudaGetSymbolAddress((void**)&wt_ukv, g_wt_ukv);
    cudaGetSymbolAddress((void**)&wt_o,   g_wt_o);

    const int SMEM_G128 = (128 + 128 + 128 + 128) * 20 * 4;   // 40960
    const int SMEM_G64  = (128 + 128 + 64 + 64) * 20 * 4;     // 30720
    const int SMEM_FL   = (5 * 64 * 36) * 4 + (256 + 64 * 66) * 4;  // 64000
    cudaFuncSetAttribute(flash_kernel, cudaFuncAttributeMaxDynamicSharedMemorySize, SMEM_FL);

    // fused prep: 9 transposes + rope tables
    PrepArgs pa;
    const float* srcs[9] = {W_DQ, W_DKV, W_KR, W_VR, W_UQ, W_QR, W_UK, W_UV, W_O};
    float* dsts[9] = {wt_x, wt_x + 256 * 512, wt_x + 384 * 512, wt_x + 448 * 512,
                      wt_uqr, wt_uqr + 256 * 256, wt_ukv, wt_ukv + 64 * 128, wt_o};
    int Ks[9] = {512, 512, 512, 512, 256, 256, 128, 128, 512};
    int Ns[9] = {256, 128,  64, 512, 256, 256,  64, 128, 512};
    int off = 0;
    for (int i = 0; i < 9; i++) {
        pa.src[i] = srcs[i]; pa.dst[i] = dsts[i];
        pa.K[i] = Ks[i]; pa.N[i] = Ns[i];
        pa.off[i] = off;
        off += (Ks[i] / 32) * (Ns[i] / 32);
    }
    pa.off[9] = off;   // 888
    prep_kernel<<<off + 128, dim3(32, 8)>>>(pa);

    // all x-projections in one GEMM: [8192,512] @ [512,960]
    mma_gemm<64><<<dim3(15, 64), 256, SMEM_G64>>>(x, wt_x, xall, 960, 512, 512, 960);

    // latent RMSNorms (strided views into xall)
    rmsnorm_kernel<<<BT_ / 8, 256>>>(xall,       960, q_ln_w,  256, BT_);
    rmsnorm_kernel<<<BT_ / 8, 256>>>(xall + 256, 960, kv_ln_w, 128, BT_);

    // up-projections
    mma_gemm<128><<<dim3(4, 64), 256, SMEM_G128>>>(xall,       wt_uqr, uqr, 512, 256, 960, 512);
    mma_gemm<64> <<<dim3(3, 64), 256, SMEM_G64 >>>(xall + 256, wt_ukv, ukv, 192, 128, 960, 192);

    // RoPE + concat + head RMSNorm
    assemble_qk_kernel<<<B_ * H_   * T_ / 8, 256>>>(uqr, 512, uqr + 256, 512, q_head_w, gq, H_);
    assemble_qk_kernel<<<B_ * KVH_ * T_ / 8, 256>>>(ukv, 192, xall + 384, 960, k_head_w, gk, KVH_);

    // causal flash attention + value residual
    flash_kernel<<<dim3(T_ / 64, B_ * H_), 256, SMEM_FL>>>(
        gq, gk, ukv + 64, 192, xall + 448, 960, gao);

    // output projection
    mma_gemm<128><<<dim3(4, 64), 256, SMEM_G128>>>(gao, wt_o, out, 512, 512, 512, 512);
}

// round 8
// speedup vs baseline: 4.8374x; 1.3150x over previous
#include <cuda_runtime.h>
#include <cuda_fp16.h>
#include <cstdint>
#include <math.h>

#define B_   4
#define T_   2048
#define H_   8
#define KVH_ 2
#define BT_  (B_ * T_)   // 8192
#define GQA_ (H_ / KVH_) // 4

// ---------------- scratch (device globals) ----------------------------------------
__device__ float g_xall [BT_ * 960];   // [DQ 0:256 | DKV 256:384 | KR 384:448 | VR 448:960]
__device__ float g_uqr  [BT_ * 512];   // [qnope 0:256 | qrope 256:512]
__device__ float g_ukv  [BT_ * 192];   // [knope 0:64 | vproj 64:192]
__device__ float g_q    [B_ * H_   * T_ * 64];
__device__ float g_k    [B_ * KVH_ * T_ * 64];
__device__ float g_ao   [BT_ * 512];
__device__ float g_cos  [T_ * 16];
__device__ float g_sin  [T_ * 16];

__device__ float g_wt_x  [960 * 512];
__device__ float g_wt_uqr[512 * 256];
__device__ float g_wt_ukv[192 * 128];
__device__ float g_wt_o  [512 * 512];

// ---------------- helpers ---------------------------------------------------------
__device__ __forceinline__ uint32_t sptr(const void* p) {
    return (uint32_t)__cvta_generic_to_shared(p);
}
__device__ __forceinline__ uint32_t pack2f(float x, float y) {   // x -> low half
    uint32_t r;
    asm("cvt.rn.f16x2.f32 %0, %1, %2;" : "=r"(r) : "f"(y), "f"(x));
    return r;
}
__device__ __forceinline__ void f16split2(float x, float y, uint32_t& h, uint32_t& l) {
    asm("cvt.rn.f16x2.f32 %0, %1, %2;" : "=r"(h) : "f"(y), "f"(x));
    __half2 hb = *reinterpret_cast<__half2*>(&h);
    float rx = x - __low2float(hb);
    float ry = y - __high2float(hb);
    asm("cvt.rn.f16x2.f32 %0, %1, %2;" : "=r"(l) : "f"(ry), "f"(rx));
}
__device__ __forceinline__ void mma_f16(float* c, const uint32_t* a,
                                        uint32_t b0, uint32_t b1) {
    asm volatile(
        "mma.sync.aligned.m16n8k16.row.col.f32.f16.f16.f32 "
        "{%0,%1,%2,%3}, {%4,%5,%6,%7}, {%8,%9}, {%0,%1,%2,%3};\n"
        : "+f"(c[0]), "+f"(c[1]), "+f"(c[2]), "+f"(c[3])
        : "r"(a[0]), "r"(a[1]), "r"(a[2]), "r"(a[3]), "r"(b0), "r"(b1));
}
__device__ __forceinline__ void ldm4(uint32_t* r, uint32_t addr) {
    asm volatile("ldmatrix.sync.aligned.m8n8.x4.shared.b16 {%0,%1,%2,%3}, [%4];"
                 : "=r"(r[0]), "=r"(r[1]), "=r"(r[2]), "=r"(r[3]) : "r"(addr));
}
__device__ __forceinline__ void ldm4t(uint32_t* r, uint32_t addr) {
    asm volatile("ldmatrix.sync.aligned.m8n8.x4.trans.shared.b16 {%0,%1,%2,%3}, [%4];"
                 : "=r"(r[0]), "=r"(r[1]), "=r"(r[2]), "=r"(r[3]) : "r"(addr));
}

// ---------------- fused prep: 9 weight transposes + rope tables --------------------
struct PrepArgs {
    const float* src[9];
    float*       dst[9];
    int K[9], N[9];
    int off[10];
};

__global__ void prep_kernel(PrepArgs a) {
    __shared__ float tb[32][33];
    int bx = blockIdx.x;
    int x = threadIdx.x, y = threadIdx.y;
    if (bx >= a.off[9]) {
        int idx = (bx - a.off[9]) * 256 + y * 32 + x;
        if (idx < T_ * 16) {
            int t = idx >> 4, i = idx & 15;
            double invf = pow(500000.0, -((double)(2 * i)) / 32.0);
            double ang  = (double)t * invf;
            g_cos[idx] = (float)cos(ang);
            g_sin[idx] = (float)sin(ang);
        }
        return;
    }
    int m = 0;
    #pragma unroll
    for (int i = 1; i < 9; i++) if (bx >= a.off[i]) m = i;
    int lt = bx - a.off[m];
    int N = a.N[m], K = a.K[m];
    int ntx = N >> 5;
    int n0 = (lt % ntx) * 32, k0 = (lt / ntx) * 32;
    const float* in = a.src[m];
    float* out = a.dst[m];
    #pragma unroll
    for (int d = 0; d < 32; d += 8)
        tb[y + d][x] = in[(size_t)(k0 + y + d) * N + n0 + x];
    __syncthreads();
    #pragma unroll
    for (int d = 0; d < 32; d += 8)
        out[(size_t)(n0 + y + d) * K + k0 + x] = tb[x][y + d];
}

// ---------------- fp16 2-term mma GEMM (A split hi/lo, B single) -------------------
// C[?,N] = A[128-rows,K] @ BT[N,K]^T. block 128 x TN, 256 threads, K chunks of 32.
template <int TN>
__global__ void __launch_bounds__(256)
mma_gemm(const float* __restrict__ A, const float* __restrict__ BT,
         float* __restrict__ C, int N, int K, int lda, int ldc) {
    extern __shared__ uint32_t us[];
    constexpr int SPU = 20;
    uint32_t* Ah = us;
    uint32_t* Al = Ah + 128 * SPU;
    uint32_t* Bh = Al + 128 * SPU;

    constexpr int WMW    = (TN == 128) ? 2 : 4;
    constexpr int WARP_M = 128 / WMW;
    constexpr int MI     = WARP_M / 16;
    constexpr int BR     = TN / 32;

    const int tid = threadIdx.x, wid = tid >> 5, lane = tid & 31;
    const int wm = wid % WMW, wn = wid / WMW;
    const int g = lane >> 2, t4 = lane & 3;
    const int m0 = blockIdx.y * 128, n0 = blockIdx.x * TN;

    const uint32_t sAh = sptr(Ah), sBh = sptr(Bh);
    const uint32_t ALO = 128 * SPU * 4;
    const int      lrA = lane & 15;
    const uint32_t lcA = (uint32_t)(lane >> 4) * 16;
    const int      lrB = (lane & 7) | ((lane >> 4) << 3);
    const uint32_t lcB = (uint32_t)((lane >> 3) & 1) * 16;

    const float* Ab = A + (size_t)m0 * lda;
    const float* Bb = BT + (size_t)n0 * K;

    float4 areg[4], breg[BR];
    #pragma unroll
    for (int j = 0; j < 4; j++) {
        int idx = tid + 256 * j, row = idx >> 3, q = idx & 7;
        areg[j] = *(const float4*)(Ab + (size_t)row * lda + q * 4);
    }
    #pragma unroll
    for (int j = 0; j < BR; j++) {
        int idx = tid + 256 * j, row = idx >> 3, q = idx & 7;
        breg[j] = *(const float4*)(Bb + (size_t)row * K + q * 4);
    }

    float c[MI][4][4];
    #pragma unroll
    for (int mi = 0; mi < MI; mi++)
        #pragma unroll
        for (int ni = 0; ni < 4; ni++)
            #pragma unroll
            for (int j = 0; j < 4; j++) c[mi][ni][j] = 0.f;

    const int NC = K >> 5;
    for (int ch = 0; ch < NC; ch++) {
        #pragma unroll
        for (int j = 0; j < 4; j++) {
            int idx = tid + 256 * j, row = idx >> 3, q = idx & 7;
            uint32_t h0, l0, h1, l1;
            f16split2(areg[j].x, areg[j].y, h0, l0);
            f16split2(areg[j].z, areg[j].w, h1, l1);
            *(uint2*)&Ah[row * SPU + 2 * q] = make_uint2(h0, h1);
            *(uint2*)&Al[row * SPU + 2 * q] = make_uint2(l0, l1);
        }
        #pragma unroll
        for (int j = 0; j < BR; j++) {
            int idx = tid + 256 * j, row = idx >> 3, q = idx & 7;
            *(uint2*)&Bh[row * SPU + 2 * q] =
                make_uint2(pack2f(breg[j].x, breg[j].y), pack2f(breg[j].z, breg[j].w));
        }
        __syncthreads();

        if (ch + 1 < NC) {
            int k0 = (ch + 1) * 32;
            #pragma unroll
            for (int j = 0; j < 4; j++) {
                int idx = tid + 256 * j, row = idx >> 3, q = idx & 7;
                areg[j] = *(const float4*)(Ab + (size_t)row * lda + k0 + q * 4);
            }
            #pragma unroll
            for (int j = 0; j < BR; j++) {
                int idx = tid + 256 * j, row = idx >> 3, q = idx & 7;
                breg[j] = *(const float4*)(Bb + (size_t)row * K + k0 + q * 4);
            }
        }

        #pragma unroll
        for (int ks = 0; ks < 2; ks++) {
            uint32_t ah[MI][4], al[MI][4];
            #pragma unroll
            for (int mi = 0; mi < MI; mi++) {
                uint32_t ad = sAh + (uint32_t)((wm * WARP_M + mi * 16 + lrA) * SPU) * 4
                              + ks * 32 + lcA;
                ldm4(ah[mi], ad);
                ldm4(al[mi], ad + ALO);
            }
            #pragma unroll
            for (int p = 0; p < 2; p++) {
                uint32_t bd = sBh + (uint32_t)((wn * 32 + p * 16 + lrB) * SPU) * 4
                              + ks * 32 + lcB;
                uint32_t bh2[4];
                ldm4(bh2, bd);
                #pragma unroll
                for (int mi = 0; mi < MI; mi++) {
                    mma_f16(c[mi][2 * p],     ah[mi], bh2[0], bh2[1]);
                    mma_f16(c[mi][2 * p],     al[mi], bh2[0], bh2[1]);
                    mma_f16(c[mi][2 * p + 1], ah[mi], bh2[2], bh2[3]);
                    mma_f16(c[mi][2 * p + 1], al[mi], bh2[2], bh2[3]);
                }
            }
        }
        __syncthreads();
    }

    #pragma unroll
    for (int mi = 0; mi < MI; mi++) {
        int row = m0 + wm * WARP_M + mi * 16 + g;
        #pragma unroll
        for (int ni = 0; ni < 4; ni++) {
            int col = n0 + wn * 32 + ni * 8 + t4 * 2;
            *(float2*)(C + (size_t)row * ldc + col) =
                make_float2(c[mi][ni][0], c[mi][ni][1]);
            *(float2*)(C + (size_t)(row + 8) * ldc + col) =
                make_float2(c[mi][ni][2], c[mi][ni][3]);
        }
    }
}

// ---------------- strided in-place row RMSNorm ------------------------------------
__global__ void rmsnorm_kernel(float* __restrict__ X, int ld,
                               const float* __restrict__ w, int N, int rows) {
    int warp = (blockIdx.x * blockDim.x + threadIdx.x) >> 5;
    int lane = threadIdx.x & 31;
    if (warp >= rows) return;
    float* row = X + (size_t)warp * ld;
    float ss = 0.f;
    for (int c = lane; c < N; c += 32) { float v = row[c]; ss += v * v; }
    #pragma unroll
    for (int o = 16; o; o >>= 1) ss += __shfl_xor_sync(0xffffffffu, ss, o);
    float inv = rsqrtf(ss / (float)N + 1e-6f);
    for (int c = lane; c < N; c += 32) row[c] = row[c] * inv * w[c];
}

// ---------------- assemble q/k: RoPE + concat + per-head RMSNorm -------------------
__global__ void assemble_qk_kernel(const float* __restrict__ nope, int ns,
                                   const float* __restrict__ rope, int rs,
                                   const float* __restrict__ w,
                                   float* __restrict__ out, int NH) {
    int gw   = (blockIdx.x * blockDim.x + threadIdx.x) >> 5;
    int lane = threadIdx.x & 31;
    if (gw >= B_ * NH * T_) return;
    int t  = gw % T_;
    int bh = gw / T_;
    int h  = bh % NH;
    int b  = bh / NH;
    int tok = b * T_ + t;
    const float* np = nope + (size_t)tok * ns + h * 32;
    const float* rp = rope + (size_t)tok * rs + h * 32;

    float v0 = np[lane];
    int j = lane;
    float cs = g_cos[t * 16 + (j & 15)];
    float sn = g_sin[t * 16 + (j & 15)];
    float xj = rp[j];
    float xp = (j < 16) ? -rp[j + 16] : rp[j - 16];
    float v1 = xj * cs + xp * sn;

    float ss = v0 * v0 + v1 * v1;
    #pragma unroll
    for (int o = 16; o; o >>= 1) ss += __shfl_xor_sync(0xffffffffu, ss, o);
    float inv = rsqrtf(ss / 64.f + 1e-6f);

    float* op = out + (size_t)gw * 64;
    op[lane]      = v0 * inv * w[lane];
    op[lane + 32] = v1 * inv * w[lane + 32];
}

// ---------------- flash attention: fp16 mma, 128-row Q tiles -----------------------
// 128 q-rows x 64 k-cols per kt step, 256 threads (8 warps).
// Each warp owns 16 q-rows and the FULL 64 k-cols of S -> softmax is warp-internal
// (no smem stats, no cross-warp O reduction). Q split fp16 hi/lo; K, V, P single fp16.
__global__ void __launch_bounds__(256)
flash_kernel(const float* __restrict__ q,
             const float* __restrict__ k,
             const float* __restrict__ vp, int ldv,
             const float* __restrict__ vres, int ldvr,
             float* __restrict__ ao) {
    extern __shared__ uint32_t us[];
    constexpr int SP = 36;
    uint32_t* QH = us;                  // 128 x 36
    uint32_t* QL = QH + 128 * SP;       // 128 x 36
    uint32_t* KS = QL + 128 * SP;       // 64 x 36
    uint32_t* VS = KS + 64 * SP;        // 64 x 36

    const int tid = threadIdx.x, wid = tid >> 5, lane = tid & 31;
    const int g = lane >> 2, t4 = lane & 3;
    const int wr = wid * 16;

    const int qt = gridDim.x - 1 - blockIdx.x;   // big tiles first
    const int bh = blockIdx.y;
    const int b = bh / H_, h = bh % H_;
    const int kvh = h / GQA_;

    const uint32_t sQH = sptr(QH), sKS = sptr(KS), sVS = sptr(VS);
    const uint32_t QLO = 128 * SP * 4;
    const int      lrA = lane & 15;
    const uint32_t lcA = (uint32_t)(lane >> 4) * 16;
    const int      lrB = (lane & 7) | ((lane >> 4) << 3);
    const uint32_t lcB = (uint32_t)((lane >> 3) & 1) * 16;
    const int      lrV = (lane & 7) | (((lane >> 3) & 1) << 3);
    const uint32_t lcV = (uint32_t)(lane >> 4) * 16;

    // Q tile (128 rows) -> fp16 hi/lo (once)
    const float* qbase = q + (((size_t)(b * H_ + h)) * T_ + qt * 128) * 64;
    #pragma unroll
    for (int j = 0; j < 8; j++) {
        int e = tid + 256 * j;
        int r = e >> 4, qq = e & 15;
        float4 v = *(const float4*)(qbase + r * 64 + qq * 4);
        uint32_t h0, l0, h1, l1;
        f16split2(v.x, v.y, h0, l0);
        f16split2(v.z, v.w, h1, l1);
        *(uint2*)&QH[r * SP + 2 * qq] = make_uint2(h0, h1);
        *(uint2*)&QL[r * SP + 2 * qq] = make_uint2(l0, l1);
    }

    float m0 = -1e30f, m1 = -1e30f, l0a = 0.f, l1a = 0.f;
    float o[8][4];
    #pragma unroll
    for (int ni = 0; ni < 8; ni++)
        #pragma unroll
        for (int j = 0; j < 4; j++) o[ni][j] = 0.f;

    const float* kbase = k + ((size_t)(b * KVH_ + kvh)) * T_ * 64;
    const float* vbase = vp + (size_t)b * T_ * ldv + kvh * 64;

    const int ktmax = 2 * qt + 1;
    const int rowlim = qt * 128 + wr + 15;   // max q-row this warp owns

    for (int kt = 0; kt <= ktmax; kt++) {
        float4 kreg[4], vreg[4];
        #pragma unroll
        for (int j = 0; j < 4; j++) {
            int e = tid + 256 * j;
            int cr = e >> 4, qq = e & 15;
            kreg[j] = *(const float4*)(kbase + (size_t)(kt * 64 + cr) * 64 + qq * 4);
            vreg[j] = *(const float4*)(vbase + (size_t)(kt * 64 + cr) * ldv + qq * 4);
        }
        __syncthreads();   // previous iteration's readers done
        #pragma unroll
        for (int j = 0; j < 4; j++) {
            int e = tid + 256 * j;
            int cr = e >> 4, qq = e & 15;
            *(uint2*)&KS[cr * SP + 2 * qq] =
                make_uint2(pack2f(kreg[j].x, kreg[j].y), pack2f(kreg[j].z, kreg[j].w));
            *(uint2*)&VS[cr * SP + 2 * qq] =
                make_uint2(pack2f(vreg[j].x, vreg[j].y), pack2f(vreg[j].z, vreg[j].w));
        }
        __syncthreads();

        if (kt * 64 > rowlim) continue;   // fully masked for this warp

        // ---- S = Q @ K^T (2-term fp16: Q hi/lo, K single) ----
        float s[8][4];
        #pragma unroll
        for (int ni = 0; ni < 8; ni++)
            #pragma unroll
            for (int j = 0; j < 4; j++) s[ni][j] = 0.f;

        #pragma unroll
        for (int ks = 0; ks < 4; ks++) {
            uint32_t ad = sQH + (uint32_t)((wr + lrA) * SP) * 4 + ks * 32 + lcA;
            uint32_t ah[4], al[4];
            ldm4(ah, ad);
            ldm4(al, ad + QLO);
            #pragma unroll
            for (int p = 0; p < 4; p++) {
                uint32_t bd = sKS + (uint32_t)((p * 16 + lrB) * SP) * 4
                              + ks * 32 + lcB;
                uint32_t bh2[4];
                ldm4(bh2, bd);
                mma_f16(s[2 * p],     ah, bh2[0], bh2[1]);
                mma_f16(s[2 * p],     al, bh2[0], bh2[1]);
                mma_f16(s[2 * p + 1], ah, bh2[2], bh2[3]);
                mma_f16(s[2 * p + 1], al, bh2[2], bh2[3]);
            }
        }

        // scale + causal mask (only needed near the diagonal)
        const int rg0 = qt * 128 + wr + g;
        const int rg1 = rg0 + 8;
        if (kt * 64 + 63 > qt * 128 + wr) {
            #pragma unroll
            for (int ni = 0; ni < 8; ni++) {
                int cg = kt * 64 + ni * 8 + t4 * 2;
                #pragma unroll
                for (int j = 0; j < 4; j++) {
                    s[ni][j] *= 0.125f;
                    int cc = cg + (j & 1);
                    int rr = (j < 2) ? rg0 : rg1;
                    if (cc > rr) s[ni][j] = -1e30f;
                }
            }
        } else {
            #pragma unroll
            for (int ni = 0; ni < 8; ni++)
                #pragma unroll
                for (int j = 0; j < 4; j++) s[ni][j] *= 0.125f;
        }

        // warp-internal online softmax (full row per warp)
        float rm0 = -1e30f, rm1 = -1e30f;
        #pragma unroll
        for (int ni = 0; ni < 8; ni++) {
            rm0 = fmaxf(rm0, fmaxf(s[ni][0], s[ni][1]));
            rm1 = fmaxf(rm1, fmaxf(s[ni][2], s[ni][3]));
        }
        #pragma unroll
        for (int off = 1; off <= 2; off <<= 1) {
            rm0 = fmaxf(rm0, __shfl_xor_sync(0xffffffffu, rm0, off));
            rm1 = fmaxf(rm1, __shfl_xor_sync(0xffffffffu, rm1, off));
        }
        float nm0 = fmaxf(m0, rm0);
        float nm1 = fmaxf(m1, rm1);
        float corr0 = __expf(m0 - nm0);
        float corr1 = __expf(m1 - nm1);
        m0 = nm0; m1 = nm1;

        float su0 = 0.f, su1 = 0.f;
        #pragma unroll
        for (int ni = 0; ni < 8; ni++) {
            s[ni][0] = __expf(s[ni][0] - nm0);
            s[ni][1] = __expf(s[ni][1] - nm0);
            s[ni][2] = __expf(s[ni][2] - nm1);
            s[ni][3] = __expf(s[ni][3] - nm1);
            su0 += s[ni][0] + s[ni][1];
            su1 += s[ni][2] + s[ni][3];
        }
        #pragma unroll
        for (int off = 1; off <= 2; off <<= 1) {
            su0 += __shfl_xor_sync(0xffffffffu, su0, off);
            su1 += __shfl_xor_sync(0xffffffffu, su1, off);
        }
        l0a = l0a * corr0 + su0;
        l1a = l1a * corr1 + su1;

        #pragma unroll
        for (int ni = 0; ni < 8; ni++) {
            o[ni][0] *= corr0; o[ni][1] *= corr0;
            o[ni][2] *= corr1; o[ni][3] *= corr1;
        }

        // ---- O += P @ V (fp16, register-resident P) ----
        #pragma unroll
        for (int ks = 0; ks < 4; ks++) {
            uint32_t pa[4];
            pa[0] = pack2f(s[2 * ks][0],     s[2 * ks][1]);
            pa[1] = pack2f(s[2 * ks][2],     s[2 * ks][3]);
            pa[2] = pack2f(s[2 * ks + 1][0], s[2 * ks + 1][1]);
            pa[3] = pack2f(s[2 * ks + 1][2], s[2 * ks + 1][3]);
            #pragma unroll
            for (int db = 0; db < 4; db++) {
                uint32_t vd = sVS + (uint32_t)((ks * 16 + lrV) * SP) * 4
                              + db * 32 + lcV;
                uint32_t bv[4];
                ldm4t(bv, vd);
                mma_f16(o[2 * db],     pa, bv[0], bv[1]);
                mma_f16(o[2 * db + 1], pa, bv[2], bv[3]);
            }
        }
    }

    // epilogue: each warp writes its own 16 rows x 64 d
    float invl0 = 1.f / l0a, invl1 = 1.f / l1a;
    int r0 = qt * 128 + wr + g;
    #pragma unroll
    for (int ni = 0; ni < 8; ni++) {
        int col = ni * 8 + t4 * 2;
        size_t vb0 = ((size_t)(b * T_ + r0)) * ldvr + h * 64 + col;
        size_t vb1 = ((size_t)(b * T_ + r0 + 8)) * ldvr + h * 64 + col;
        float2 vr0 = *(const float2*)(vres + vb0);
        float2 vr1 = *(const float2*)(vres + vb1);
        size_t ab0 = ((size_t)(b * T_ + r0)) * 512 + h * 64 + col;
        size_t ab1 = ((size_t)(b * T_ + r0 + 8)) * 512 + h * 64 + col;
        *(float2*)(ao + ab0) = make_float2(o[ni][0] * invl0 + vr0.x,
                                           o[ni][1] * invl0 + vr0.y);
        *(float2*)(ao + ab1) = make_float2(o[ni][2] * invl1 + vr1.x,
                                           o[ni][3] * invl1 + vr1.y);
    }
}

// ---------------- launch ----------------------------------------------------------
extern "C" void kernel_launch(void* const* d_in, const int* in_sizes, int n_in,
                              void* d_out, int out_size) {
    const float* x        = (const float*)d_in[0];
    const float* W_DQ     = (const float*)d_in[1];
    const float* W_UQ     = (const float*)d_in[2];
    const float* W_QR     = (const float*)d_in[3];
    const float* W_DKV    = (const float*)d_in[4];
    const float* W_UK     = (const float*)d_in[5];
    const float* W_UV     = (const float*)d_in[6];
    const float* W_KR     = (const float*)d_in[7];
    const float* W_VR     = (const float*)d_in[8];
    const float* W_O      = (const float*)d_in[9];
    const float* q_ln_w   = (const float*)d_in[10];
    const float* kv_ln_w  = (const float*)d_in[11];
    const float* q_head_w = (const float*)d_in[12];
    const float* k_head_w = (const float*)d_in[13];
    float* out = (float*)d_out;

    float *xall, *uqr, *ukv, *gq, *gk, *gao, *wt_x, *wt_uqr, *wt_ukv, *wt_o;
    cudaGetSymbolAddress((void**)&xall,   g_xall);
    cudaGetSymbolAddress((void**)&uqr,    g_uqr);
    cudaGetSymbolAddress((void**)&ukv,    g_ukv);
    cudaGetSymbolAddress((void**)&gq,     g_q);
    cudaGetSymbolAddress((void**)&gk,     g_k);
    cudaGetSymbolAddress((void**)&gao,    g_ao);
    cudaGetSymbolAddress((void**)&wt_x,   g_wt_x);
    cudaGetSymbolAddress((void**)&wt_uqr, g_wt_uqr);
    cudaGetSymbolAddress((void**)&wt_ukv, g_wt_ukv);
    cudaGetSymbolAddress((void**)&wt_o,   g_wt_o);

    const int SMEM_G128 = (128 + 128 + 128) * 20 * 4;   // 30720
    const int SMEM_G64  = (128 + 128 + 64) * 20 * 4;    // 25600
    const int SMEM_FL   = (2 * 128 + 2 * 64) * 36 * 4;  // 55296
    cudaFuncSetAttribute(flash_kernel, cudaFuncAttributeMaxDynamicSharedMemorySize, SMEM_FL);

    // fused prep: 9 transposes + rope tables
    PrepArgs pa;
    const float* srcs[9] = {W_DQ, W_DKV, W_KR, W_VR, W_UQ, W_QR, W_UK, W_UV, W_O};
    float* dsts[9] = {wt_x, wt_x + 256 * 512, wt_x + 384 * 512, wt_x + 448 * 512,
                      wt_uqr, wt_uqr + 256 * 256, wt_ukv, wt_ukv + 64 * 128, wt_o};
    int Ks[9] = {512, 512, 512, 512, 256, 256, 128, 128, 512};
    int Ns[9] = {256, 128,  64, 512, 256, 256,  64, 128, 512};
    int off = 0;
    for (int i = 0; i < 9; i++) {
        pa.src[i] = srcs[i]; pa.dst[i] = dsts[i];
        pa.K[i] = Ks[i]; pa.N[i] = Ns[i];
        pa.off[i] = off;
        off += (Ks[i] / 32) * (Ns[i] / 32);
    }
    pa.off[9] = off;   // 888
    prep_kernel<<<off + 128, dim3(32, 8)>>>(pa);

    // all x-projections in one GEMM: [8192,512] @ [512,960]
    mma_gemm<64><<<dim3(15, 64), 256, SMEM_G64>>>(x, wt_x, xall, 960, 512, 512, 960);

    // latent RMSNorms (strided views into xall)
    rmsnorm_kernel<<<BT_ / 8, 256>>>(xall,       960, q_ln_w,  256, BT_);
    rmsnorm_kernel<<<BT_ / 8, 256>>>(xall + 256, 960, kv_ln_w, 128, BT_);

    // up-projections
    mma_gemm<128><<<dim3(4, 64), 256, SMEM_G128>>>(xall,       wt_uqr, uqr, 512, 256, 960, 512);
    mma_gemm<64> <<<dim3(3, 64), 256, SMEM_G64 >>>(xall + 256, wt_ukv, ukv, 192, 128, 960, 192);

    // RoPE + concat + head RMSNorm
    assemble_qk_kernel<<<B_ * H_   * T_ / 8, 256>>>(uqr, 512, uqr + 256, 512, q_head_w, gq, H_);
    assemble_qk_kernel<<<B_ * KVH_ * T_ / 8, 256>>>(ukv, 192, xall + 384, 960, k_head_w, gk, KVH_);

    // causal flash attention + value residual (128-row Q tiles)
    flash_kernel<<<dim3(T_ / 128, B_ * H_), 256, SMEM_FL>>>(
        gq, gk, ukv + 64, 192, xall + 448, 960, gao);

    // output projection
    mma_gemm<128><<<dim3(4, 64), 256, SMEM_G128>>>(gao, wt_o, out, 512, 512, 512, 512);
}

// round 9
// speedup vs baseline: 4.8389x; 1.0003x over previous
#include <cuda_runtime.h>
#include <cuda_fp16.h>
#include <cstdint>
#include <math.h>

#define B_   4
#define T_   2048
#define H_   8
#define KVH_ 2
#define BT_  (B_ * T_)   // 8192
#define GQA_ (H_ / KVH_) // 4

// ---------------- scratch (device globals) ----------------------------------------
__device__ float g_xall [BT_ * 960];   // [DQ 0:256 | DKV 256:384 | KR 384:448 | VR 448:960]
__device__ float g_uqr  [BT_ * 512];   // [qnope 0:256 | qrope 256:512]
__device__ float g_ukv  [BT_ * 192];   // [knope 0:64 | vproj 64:192]
__device__ float g_ao   [BT_ * 512];
__device__ float g_cos  [T_ * 16];
__device__ float g_sin  [T_ * 16];

// packed fp16x2 tensors for flash
__device__ uint32_t g_qh [B_ * H_   * T_ * 32];
__device__ uint32_t g_ql [B_ * H_   * T_ * 32];
__device__ uint32_t g_kh [B_ * KVH_ * T_ * 32];
__device__ uint32_t g_vh [B_ * KVH_ * T_ * 32];

// transposed + fp16x2-packed weights [N][K/2]
__device__ uint32_t g_wt_x  [960 * 256];
__device__ uint32_t g_wt_uqr[512 * 128];
__device__ uint32_t g_wt_ukv[192 * 64];
__device__ uint32_t g_wt_o  [512 * 256];

// ---------------- helpers ---------------------------------------------------------
__device__ __forceinline__ uint32_t sptr(const void* p) {
    return (uint32_t)__cvta_generic_to_shared(p);
}
__device__ __forceinline__ uint32_t pack2f(float x, float y) {   // x -> low half
    uint32_t r;
    asm("cvt.rn.f16x2.f32 %0, %1, %2;" : "=r"(r) : "f"(y), "f"(x));
    return r;
}
__device__ __forceinline__ void f16split2(float x, float y, uint32_t& h, uint32_t& l) {
    asm("cvt.rn.f16x2.f32 %0, %1, %2;" : "=r"(h) : "f"(y), "f"(x));
    __half2 hb = *reinterpret_cast<__half2*>(&h);
    float rx = x - __low2float(hb);
    float ry = y - __high2float(hb);
    asm("cvt.rn.f16x2.f32 %0, %1, %2;" : "=r"(l) : "f"(ry), "f"(rx));
}
__device__ __forceinline__ void mma_f16(float* c, const uint32_t* a,
                                        uint32_t b0, uint32_t b1) {
    asm volatile(
        "mma.sync.aligned.m16n8k16.row.col.f32.f16.f16.f32 "
        "{%0,%1,%2,%3}, {%4,%5,%6,%7}, {%8,%9}, {%0,%1,%2,%3};\n"
        : "+f"(c[0]), "+f"(c[1]), "+f"(c[2]), "+f"(c[3])
        : "r"(a[0]), "r"(a[1]), "r"(a[2]), "r"(a[3]), "r"(b0), "r"(b1));
}
__device__ __forceinline__ void ldm4(uint32_t* r, uint32_t addr) {
    asm volatile("ldmatrix.sync.aligned.m8n8.x4.shared.b16 {%0,%1,%2,%3}, [%4];"
                 : "=r"(r[0]), "=r"(r[1]), "=r"(r[2]), "=r"(r[3]) : "r"(addr));
}
__device__ __forceinline__ void ldm4t(uint32_t* r, uint32_t addr) {
    asm volatile("ldmatrix.sync.aligned.m8n8.x4.trans.shared.b16 {%0,%1,%2,%3}, [%4];"
                 : "=r"(r[0]), "=r"(r[1]), "=r"(r[2]), "=r"(r[3]) : "r"(addr));
}

// ---------------- fused prep: 9 weight transpose+pack + rope tables ----------------
struct PrepArgs {
    const float* src[9];
    uint32_t*    dst[9];
    int K[9], N[9];
    int off[10];
};

__global__ void prep_kernel(PrepArgs a) {
    __shared__ float tb[32][33];
    int bx = blockIdx.x;
    int x = threadIdx.x, y = threadIdx.y;
    if (bx >= a.off[9]) {
        int idx = (bx - a.off[9]) * 256 + y * 32 + x;
        if (idx < T_ * 16) {
            int t = idx >> 4, i = idx & 15;
            double invf = pow(500000.0, -((double)(2 * i)) / 32.0);
            double ang  = (double)t * invf;
            g_cos[idx] = (float)cos(ang);
            g_sin[idx] = (float)sin(ang);
        }
        return;
    }
    int m = 0;
    #pragma unroll
    for (int i = 1; i < 9; i++) if (bx >= a.off[i]) m = i;
    int lt = bx - a.off[m];
    int N = a.N[m], K = a.K[m];
    int ntx = N >> 5;
    int n0 = (lt % ntx) * 32, k0 = (lt / ntx) * 32;
    const float* in = a.src[m];
    uint32_t* out = a.dst[m];
    #pragma unroll
    for (int d = 0; d < 32; d += 8)
        tb[y + d][x] = in[(size_t)(k0 + y + d) * N + n0 + x];
    __syncthreads();
    if (x < 16) {
        int kd2 = K >> 1;
        #pragma unroll
        for (int d = 0; d < 32; d += 8)
            out[(size_t)(n0 + y + d) * kd2 + (k0 >> 1) + x] =
                pack2f(tb[2 * x][y + d], tb[2 * x + 1][y + d]);
    }
}

// ---------------- fp16 GEMM (A fp32 split hi/lo, B packed fp16 weights) ------------
// C[?,N] = A[128-rows,K] @ BT[N,K]^T. block 128 x TN, 256 threads, K chunks of 32.
template <int TN>
__global__ void __launch_bounds__(256)
mma_gemm(const float* __restrict__ A, const uint32_t* __restrict__ BT,
         float* __restrict__ C, int N, int K, int lda, int ldc) {
    extern __shared__ uint32_t us[];
    constexpr int SPU = 20;
    uint32_t* Ah = us;
    uint32_t* Al = Ah + 128 * SPU;
    uint32_t* Bh = Al + 128 * SPU;

    constexpr int WMW    = (TN == 128) ? 2 : 4;
    constexpr int WARP_M = 128 / WMW;
    constexpr int MI     = WARP_M / 16;
    constexpr int BR2    = TN / 64;   // uint4 loads per thread for B

    const int tid = threadIdx.x, wid = tid >> 5, lane = tid & 31;
    const int wm = wid % WMW, wn = wid / WMW;
    const int g = lane >> 2, t4 = lane & 3;
    const int m0 = blockIdx.y * 128, n0 = blockIdx.x * TN;

    const uint32_t sAh = sptr(Ah), sBh = sptr(Bh);
    const uint32_t ALO = 128 * SPU * 4;
    const int      lrA = lane & 15;
    const uint32_t lcA = (uint32_t)(lane >> 4) * 16;
    const int      lrB = (lane & 7) | ((lane >> 4) << 3);
    const uint32_t lcB = (uint32_t)((lane >> 3) & 1) * 16;

    const int ldb = K >> 1;
    const float*    Ab = A + (size_t)m0 * lda;
    const uint32_t* Bb = BT + (size_t)n0 * ldb;

    float4 areg[4];
    uint4  breg[BR2];
    #pragma unroll
    for (int j = 0; j < 4; j++) {
        int idx = tid + 256 * j, row = idx >> 3, q = idx & 7;
        areg[j] = *(const float4*)(Ab + (size_t)row * lda + q * 4);
    }
    #pragma unroll
    for (int j = 0; j < BR2; j++) {
        int idx = tid + 256 * j, row = idx >> 2, qu = idx & 3;
        breg[j] = *(const uint4*)(Bb + (size_t)row * ldb + qu * 4);
    }

    float c[MI][4][4];
    #pragma unroll
    for (int mi = 0; mi < MI; mi++)
        #pragma unroll
        for (int ni = 0; ni < 4; ni++)
            #pragma unroll
            for (int j = 0; j < 4; j++) c[mi][ni][j] = 0.f;

    const int NC = K >> 5;
    for (int ch = 0; ch < NC; ch++) {
        #pragma unroll
        for (int j = 0; j < 4; j++) {
            int idx = tid + 256 * j, row = idx >> 3, q = idx & 7;
            uint32_t h0, l0, h1, l1;
            f16split2(areg[j].x, areg[j].y, h0, l0);
            f16split2(areg[j].z, areg[j].w, h1, l1);
            *(uint2*)&Ah[row * SPU + 2 * q] = make_uint2(h0, h1);
            *(uint2*)&Al[row * SPU + 2 * q] = make_uint2(l0, l1);
        }
        #pragma unroll
        for (int j = 0; j < BR2; j++) {
            int idx = tid + 256 * j, row = idx >> 2, qu = idx & 3;
            *(uint4*)&Bh[row * SPU + qu * 4] = breg[j];
        }
        __syncthreads();

        if (ch + 1 < NC) {
            int k0 = (ch + 1) * 32;
            #pragma unroll
            for (int j = 0; j < 4; j++) {
                int idx = tid + 256 * j, row = idx >> 3, q = idx & 7;
                areg[j] = *(const float4*)(Ab + (size_t)row * lda + k0 + q * 4);
            }
            #pragma unroll
            for (int j = 0; j < BR2; j++) {
                int idx = tid + 256 * j, row = idx >> 2, qu = idx & 3;
                breg[j] = *(const uint4*)(Bb + (size_t)row * ldb + (k0 >> 1) + qu * 4);
            }
        }

        #pragma unroll
        for (int ks = 0; ks < 2; ks++) {
            uint32_t ah[MI][4], al[MI][4];
            #pragma unroll
            for (int mi = 0; mi < MI; mi++) {
                uint32_t ad = sAh + (uint32_t)((wm * WARP_M + mi * 16 + lrA) * SPU) * 4
                              + ks * 32 + lcA;
                ldm4(ah[mi], ad);
                ldm4(al[mi], ad + ALO);
            }
            #pragma unroll
            for (int p = 0; p < 2; p++) {
                uint32_t bd = sBh + (uint32_t)((wn * 32 + p * 16 + lrB) * SPU) * 4
                              + ks * 32 + lcB;
                uint32_t bh2[4];
                ldm4(bh2, bd);
                #pragma unroll
                for (int mi = 0; mi < MI; mi++) {
                    mma_f16(c[mi][2 * p],     ah[mi], bh2[0], bh2[1]);
                    mma_f16(c[mi][2 * p],     al[mi], bh2[0], bh2[1]);
                    mma_f16(c[mi][2 * p + 1], ah[mi], bh2[2], bh2[3]);
                    mma_f16(c[mi][2 * p + 1], al[mi], bh2[2], bh2[3]);
                }
            }
        }
        __syncthreads();
    }

    #pragma unroll
    for (int mi = 0; mi < MI; mi++) {
        int row = m0 + wm * WARP_M + mi * 16 + g;
        #pragma unroll
        for (int ni = 0; ni < 4; ni++) {
            int col = n0 + wn * 32 + ni * 8 + t4 * 2;
            *(float2*)(C + (size_t)row * ldc + col) =
                make_float2(c[mi][ni][0], c[mi][ni][1]);
            *(float2*)(C + (size_t)(row + 8) * ldc + col) =
                make_float2(c[mi][ni][2], c[mi][ni][3]);
        }
    }
}

// ---------------- strided in-place row RMSNorm ------------------------------------
__global__ void rmsnorm_kernel(float* __restrict__ X, int ld,
                               const float* __restrict__ w, int N, int rows) {
    int warp = (blockIdx.x * blockDim.x + threadIdx.x) >> 5;
    int lane = threadIdx.x & 31;
    if (warp >= rows) return;
    float* row = X + (size_t)warp * ld;
    float ss = 0.f;
    for (int c = lane; c < N; c += 32) { float v = row[c]; ss += v * v; }
    #pragma unroll
    for (int o = 16; o; o >>= 1) ss += __shfl_xor_sync(0xffffffffu, ss, o);
    float inv = rsqrtf(ss / (float)N + 1e-6f);
    for (int c = lane; c < N; c += 32) row[c] = row[c] * inv * w[c];
}

// ---------------- assemble q: RoPE + concat + head RMSNorm -> packed fp16 hi/lo ----
__global__ void assemble_q_kernel(const float* __restrict__ nope, int ns,
                                  const float* __restrict__ rope, int rs,
                                  const float* __restrict__ w,
                                  uint32_t* __restrict__ qh,
                                  uint32_t* __restrict__ ql) {
    int gw   = (blockIdx.x * blockDim.x + threadIdx.x) >> 5;
    int lane = threadIdx.x & 31;
    if (gw >= B_ * H_ * T_) return;
    int t  = gw % T_;
    int bh = gw / T_;
    int h  = bh % H_;
    int b  = bh / H_;
    int tok = b * T_ + t;
    const float* np = nope + (size_t)tok * ns + h * 32;
    const float* rp = rope + (size_t)tok * rs + h * 32;

    float v0 = np[lane];
    float cs = g_cos[t * 16 + (lane & 15)];
    float sn = g_sin[t * 16 + (lane & 15)];
    float xj = rp[lane];
    float xp = (lane < 16) ? -rp[lane + 16] : rp[lane - 16];
    float v1 = xj * cs + xp * sn;

    float ss = v0 * v0 + v1 * v1;
    #pragma unroll
    for (int o = 16; o; o >>= 1) ss += __shfl_xor_sync(0xffffffffu, ss, o);
    float inv = rsqrtf(ss / 64.f + 1e-6f);
    float v0n = v0 * inv * w[lane];
    float v1n = v1 * inv * w[lane + 32];

    // repack: u32 i covers dims (2i, 2i+1)
    float a0 = __shfl_sync(0xffffffffu, v0n, (2 * lane) & 31);
    float b0 = __shfl_sync(0xffffffffu, v0n, (2 * lane + 1) & 31);
    float a1 = __shfl_sync(0xffffffffu, v1n, (2 * lane) & 31);
    float b1 = __shfl_sync(0xffffffffu, v1n, (2 * lane + 1) & 31);
    float A  = (lane < 16) ? a0 : a1;
    float Bv = (lane < 16) ? b0 : b1;
    uint32_t hh, ll;
    f16split2(A, Bv, hh, ll);
    qh[(size_t)gw * 32 + lane] = hh;
    ql[(size_t)gw * 32 + lane] = ll;
}

// ---------------- assemble k (+ pack v): RoPE + concat + head RMSNorm --------------
__global__ void assemble_kv_kernel(const float* __restrict__ nope, int ns,
                                   const float* __restrict__ rope, int rs,
                                   const float* __restrict__ vsrc, int vs,
                                   const float* __restrict__ w,
                                   uint32_t* __restrict__ kh,
                                   uint32_t* __restrict__ vh) {
    int gw   = (blockIdx.x * blockDim.x + threadIdx.x) >> 5;
    int lane = threadIdx.x & 31;
    if (gw >= B_ * KVH_ * T_) return;
    int t  = gw % T_;
    int bh = gw / T_;
    int h  = bh % KVH_;
    int b  = bh / KVH_;
    int tok = b * T_ + t;
    const float* np = nope + (size_t)tok * ns + h * 32;
    const float* rp = rope + (size_t)tok * rs + h * 32;

    float v0 = np[lane];
    float cs = g_cos[t * 16 + (lane & 15)];
    float sn = g_sin[t * 16 + (lane & 15)];
    float xj = rp[lane];
    float xp = (lane < 16) ? -rp[lane + 16] : rp[lane - 16];
    float v1 = xj * cs + xp * sn;

    float ss = v0 * v0 + v1 * v1;
    #pragma unroll
    for (int o = 16; o; o >>= 1) ss += __shfl_xor_sync(0xffffffffu, ss, o);
    float inv = rsqrtf(ss / 64.f + 1e-6f);
    float v0n = v0 * inv * w[lane];
    float v1n = v1 * inv * w[lane + 32];

    float a0 = __shfl_sync(0xffffffffu, v0n, (2 * lane) & 31);
    float b0 = __shfl_sync(0xffffffffu, v0n, (2 * lane + 1) & 31);
    float a1 = __shfl_sync(0xffffffffu, v1n, (2 * lane) & 31);
    float b1 = __shfl_sync(0xffffffffu, v1n, (2 * lane + 1) & 31);
    float A  = (lane < 16) ? a0 : a1;
    float Bv = (lane < 16) ? b0 : b1;
    kh[(size_t)gw * 32 + lane] = pack2f(A, Bv);

    // pack V row (same (b,kvh,t) indexing)
    const float* vp = vsrc + (size_t)tok * vs + h * 64;
    float2 vv = *(const float2*)(vp + 2 * lane);
    vh[(size_t)gw * 32 + lane] = pack2f(vv.x, vv.y);
}

// ---------------- flash attention: fp16 mma, pre-packed operands -------------------
// 128 q-rows x 64 k-cols per kt step, 256 threads (8 warps).
// Each warp owns 16 q-rows x all 64 k-cols; softmax warp-internal.
__global__ void __launch_bounds__(256)
flash_kernel(const uint32_t* __restrict__ qh, const uint32_t* __restrict__ ql,
             const uint32_t* __restrict__ kh, const uint32_t* __restrict__ vh,
             const float* __restrict__ vres, int ldvr,
             float* __restrict__ ao) {
    extern __shared__ uint32_t us[];
    constexpr int SP = 36;
    uint32_t* QH = us;                  // 128 x 36
    uint32_t* QL = QH + 128 * SP;
    uint32_t* KS = QL + 128 * SP;       // 64 x 36
    uint32_t* VS = KS + 64 * SP;

    const int tid = threadIdx.x, wid = tid >> 5, lane = tid & 31;
    const int g = lane >> 2, t4 = lane & 3;
    const int wr = wid * 16;

    const int qt = gridDim.x - 1 - blockIdx.x;   // big tiles first
    const int bh = blockIdx.y;
    const int b = bh / H_, h = bh % H_;
    const int kvh = h / GQA_;

    const uint32_t sQH = sptr(QH), sKS = sptr(KS), sVS = sptr(VS);
    const uint32_t QLO = 128 * SP * 4;
    const int      lrA = lane & 15;
    const uint32_t lcA = (uint32_t)(lane >> 4) * 16;
    const int      lrB = (lane & 7) | ((lane >> 4) << 3);
    const uint32_t lcB = (uint32_t)((lane >> 3) & 1) * 16;
    const int      lrV = (lane & 7) | (((lane >> 3) & 1) << 3);
    const uint32_t lcV = (uint32_t)(lane >> 4) * 16;

    // Q tile (128 rows) load: raw packed copies
    const uint32_t* qb  = qh + ((size_t)(b * H_ + h) * T_ + qt * 128) * 32;
    const uint32_t* qlb = ql + ((size_t)(b * H_ + h) * T_ + qt * 128) * 32;
    #pragma unroll
    for (int j = 0; j < 4; j++) {
        int idx = tid + 256 * j, row = idx >> 3, qu = idx & 7;
        *(uint4*)&QH[row * SP + qu * 4] = *(const uint4*)(qb + (size_t)row * 32 + qu * 4);
        *(uint4*)&QL[row * SP + qu * 4] = *(const uint4*)(qlb + (size_t)row * 32 + qu * 4);
    }

    float m0 = -1e30f, m1 = -1e30f, l0a = 0.f, l1a = 0.f;
    float o[8][4];
    #pragma unroll
    for (int ni = 0; ni < 8; ni++)
        #pragma unroll
        for (int j = 0; j < 4; j++) o[ni][j] = 0.f;

    const uint32_t* kb = kh + ((size_t)(b * KVH_ + kvh) * T_) * 32;
    const uint32_t* vb = vh + ((size_t)(b * KVH_ + kvh) * T_) * 32;

    const int ktmax = 2 * qt + 1;
    const int rowlim = qt * 128 + wr + 15;

    for (int kt = 0; kt <= ktmax; kt++) {
        uint4 kreg[2], vreg[2];
        #pragma unroll
        for (int j = 0; j < 2; j++) {
            int idx = tid + 256 * j, row = idx >> 3, qu = idx & 7;
            kreg[j] = *(const uint4*)(kb + (size_t)(kt * 64 + row) * 32 + qu * 4);
            vreg[j] = *(const uint4*)(vb + (size_t)(kt * 64 + row) * 32 + qu * 4);
        }
        __syncthreads();   // previous iteration's readers done
        #pragma unroll
        for (int j = 0; j < 2; j++) {
            int idx = tid + 256 * j, row = idx >> 3, qu = idx & 7;
            *(uint4*)&KS[row * SP + qu * 4] = kreg[j];
            *(uint4*)&VS[row * SP + qu * 4] = vreg[j];
        }
        __syncthreads();

        if (kt * 64 > rowlim) continue;   // fully masked for this warp

        // ---- S = Q @ K^T (2-term fp16: Q hi/lo, K single) ----
        float s[8][4];
        #pragma unroll
        for (int ni = 0; ni < 8; ni++)
            #pragma unroll
            for (int j = 0; j < 4; j++) s[ni][j] = 0.f;

        #pragma unroll
        for (int ks = 0; ks < 4; ks++) {
            uint32_t ad = sQH + (uint32_t)((wr + lrA) * SP) * 4 + ks * 32 + lcA;
            uint32_t ah[4], al[4];
            ldm4(ah, ad);
            ldm4(al, ad + QLO);
            #pragma unroll
            for (int p = 0; p < 4; p++) {
                uint32_t bd = sKS + (uint32_t)((p * 16 + lrB) * SP) * 4
                              + ks * 32 + lcB;
                uint32_t bh2[4];
                ldm4(bh2, bd);
                mma_f16(s[2 * p],     ah, bh2[0], bh2[1]);
                mma_f16(s[2 * p],     al, bh2[0], bh2[1]);
                mma_f16(s[2 * p + 1], ah, bh2[2], bh2[3]);
                mma_f16(s[2 * p + 1], al, bh2[2], bh2[3]);
            }
        }

        // scale + causal mask (only needed near the diagonal)
        const int rg0 = qt * 128 + wr + g;
        const int rg1 = rg0 + 8;
        if (kt * 64 + 63 > qt * 128 + wr) {
            #pragma unroll
            for (int ni = 0; ni < 8; ni++) {
                int cg = kt * 64 + ni * 8 + t4 * 2;
                #pragma unroll
                for (int j = 0; j < 4; j++) {
                    s[ni][j] *= 0.125f;
                    int cc = cg + (j & 1);
                    int rr = (j < 2) ? rg0 : rg1;
                    if (cc > rr) s[ni][j] = -1e30f;
                }
            }
        } else {
            #pragma unroll
            for (int ni = 0; ni < 8; ni++)
                #pragma unroll
                for (int j = 0; j < 4; j++) s[ni][j] *= 0.125f;
        }

        // warp-internal online softmax
        float rm0 = -1e30f, rm1 = -1e30f;
        #pragma unroll
        for (int ni = 0; ni < 8; ni++) {
            rm0 = fmaxf(rm0, fmaxf(s[ni][0], s[ni][1]));
            rm1 = fmaxf(rm1, fmaxf(s[ni][2], s[ni][3]));
        }
        #pragma unroll
        for (int off = 1; off <= 2; off <<= 1) {
            rm0 = fmaxf(rm0, __shfl_xor_sync(0xffffffffu, rm0, off));
            rm1 = fmaxf(rm1, __shfl_xor_sync(0xffffffffu, rm1, off));
        }
        float nm0 = fmaxf(m0, rm0);
        float nm1 = fmaxf(m1, rm1);
        float corr0 = __expf(m0 - nm0);
        float corr1 = __expf(m1 - nm1);
        m0 = nm0; m1 = nm1;

        float su0 = 0.f, su1 = 0.f;
        #pragma unroll
        for (int ni = 0; ni < 8; ni++) {
            s[ni][0] = __expf(s[ni][0] - nm0);
            s[ni][1] = __expf(s[ni][1] - nm0);
            s[ni][2] = __expf(s[ni][2] - nm1);
            s[ni][3] = __expf(s[ni][3] - nm1);
            su0 += s[ni][0] + s[ni][1];
            su1 += s[ni][2] + s[ni][3];
        }
        #pragma unroll
        for (int off = 1; off <= 2; off <<= 1) {
            su0 += __shfl_xor_sync(0xffffffffu, su0, off);
            su1 += __shfl_xor_sync(0xffffffffu, su1, off);
        }
        l0a = l0a * corr0 + su0;
        l1a = l1a * corr1 + su1;

        #pragma unroll
        for (int ni = 0; ni < 8; ni++) {
            o[ni][0] *= corr0; o[ni][1] *= corr0;
            o[ni][2] *= corr1; o[ni][3] *= corr1;
        }

        // ---- O += P @ V (fp16, register-resident P) ----
        #pragma unroll
        for (int ks = 0; ks < 4; ks++) {
            uint32_t pa[4];
            pa[0] = pack2f(s[2 * ks][0],     s[2 * ks][1]);
            pa[1] = pack2f(s[2 * ks][2],     s[2 * ks][3]);
            pa[2] = pack2f(s[2 * ks + 1][0], s[2 * ks + 1][1]);
            pa[3] = pack2f(s[2 * ks + 1][2], s[2 * ks + 1][3]);
            #pragma unroll
            for (int db = 0; db < 4; db++) {
                uint32_t vd = sVS + (uint32_t)((ks * 16 + lrV) * SP) * 4
                              + db * 32 + lcV;
                uint32_t bv[4];
                ldm4t(bv, vd);
                mma_f16(o[2 * db],     pa, bv[0], bv[1]);
                mma_f16(o[2 * db + 1], pa, bv[2], bv[3]);
            }
        }
    }

    // epilogue: each warp writes its own 16 rows x 64 d
    float invl0 = 1.f / l0a, invl1 = 1.f / l1a;
    int r0 = qt * 128 + wr + g;
    #pragma unroll
    for (int ni = 0; ni < 8; ni++) {
        int col = ni * 8 + t4 * 2;
        size_t vb0 = ((size_t)(b * T_ + r0)) * ldvr + h * 64 + col;
        size_t vb1 = ((size_t)(b * T_ + r0 + 8)) * ldvr + h * 64 + col;
        float2 vr0 = *(const float2*)(vres + vb0);
        float2 vr1 = *(const float2*)(vres + vb1);
        size_t ab0 = ((size_t)(b * T_ + r0)) * 512 + h * 64 + col;
        size_t ab1 = ((size_t)(b * T_ + r0 + 8)) * 512 + h * 64 + col;
        *(float2*)(ao + ab0) = make_float2(o[ni][0] * invl0 + vr0.x,
                                           o[ni][1] * invl0 + vr0.y);
        *(float2*)(ao + ab1) = make_float2(o[ni][2] * invl1 + vr1.x,
                                           o[ni][3] * invl1 + vr1.y);
    }
}

// ---------------- launch ----------------------------------------------------------
extern "C" void kernel_launch(void* const* d_in, const int* in_sizes, int n_in,
                              void* d_out, int out_size) {
    const float* x        = (const float*)d_in[0];
    const float* W_DQ     = (const float*)d_in[1];
    const float* W_UQ     = (const float*)d_in[2];
    const float* W_QR     = (const float*)d_in[3];
    const float* W_DKV    = (const float*)d_in[4];
    const float* W_UK     = (const float*)d_in[5];
    const float* W_UV     = (const float*)d_in[6];
    const float* W_KR     = (const float*)d_in[7];
    const float* W_VR     = (const float*)d_in[8];
    const float* W_O      = (const float*)d_in[9];
    const float* q_ln_w   = (const float*)d_in[10];
    const float* kv_ln_w  = (const float*)d_in[11];
    const float* q_head_w = (const float*)d_in[12];
    const float* k_head_w = (const float*)d_in[13];
    float* out = (float*)d_out;

    float *xall, *uqr, *ukv, *gao;
    uint32_t *qhp, *qlp, *khp, *vhp, *wt_x, *wt_uqr, *wt_ukv, *wt_o;
    cudaGetSymbolAddress((void**)&xall,   g_xall);
    cudaGetSymbolAddress((void**)&uqr,    g_uqr);
    cudaGetSymbolAddress((void**)&ukv,    g_ukv);
    cudaGetSymbolAddress((void**)&gao,    g_ao);
    cudaGetSymbolAddress((void**)&qhp,    g_qh);
    cudaGetSymbolAddress((void**)&qlp,    g_ql);
    cudaGetSymbolAddress((void**)&khp,    g_kh);
    cudaGetSymbolAddress((void**)&vhp,    g_vh);
    cudaGetSymbolAddress((void**)&wt_x,   g_wt_x);
    cudaGetSymbolAddress((void**)&wt_uqr, g_wt_uqr);
    cudaGetSymbolAddress((void**)&wt_ukv, g_wt_ukv);
    cudaGetSymbolAddress((void**)&wt_o,   g_wt_o);

    const int SMEM_G128 = (128 + 128 + 128) * 20 * 4;   // 30720
    const int SMEM_G64  = (128 + 128 + 64) * 20 * 4;    // 25600
    const int SMEM_FL   = (2 * 128 + 2 * 64) * 36 * 4;  // 55296
    cudaFuncSetAttribute(flash_kernel, cudaFuncAttributeMaxDynamicSharedMemorySize, SMEM_FL);

    // fused prep: 9 transpose+pack + rope tables
    PrepArgs pa;
    const float* srcs[9] = {W_DQ, W_DKV, W_KR, W_VR, W_UQ, W_QR, W_UK, W_UV, W_O};
    uint32_t* dsts[9] = {wt_x, wt_x + 256 * 256, wt_x + 384 * 256, wt_x + 448 * 256,
                         wt_uqr, wt_uqr + 256 * 128, wt_ukv, wt_ukv + 64 * 64, wt_o};
    int Ks[9] = {512, 512, 512, 512, 256, 256, 128, 128, 512};
    int Ns[9] = {256, 128,  64, 512, 256, 256,  64, 128, 512};
    int off = 0;
    for (int i = 0; i < 9; i++) {
        pa.src[i] = srcs[i]; pa.dst[i] = dsts[i];
        pa.K[i] = Ks[i]; pa.N[i] = Ns[i];
        pa.off[i] = off;
        off += (Ks[i] / 32) * (Ns[i] / 32);
    }
    pa.off[9] = off;   // 888
    prep_kernel<<<off + 128, dim3(32, 8)>>>(pa);

    // all x-projections in one GEMM: [8192,512] @ [512,960]
    mma_gemm<64><<<dim3(15, 64), 256, SMEM_G64>>>(x, wt_x, xall, 960, 512, 512, 960);

    // latent RMSNorms (strided views into xall)
    rmsnorm_kernel<<<BT_ / 8, 256>>>(xall,       960, q_ln_w,  256, BT_);
    rmsnorm_kernel<<<BT_ / 8, 256>>>(xall + 256, 960, kv_ln_w, 128, BT_);

    // up-projections
    mma_gemm<128><<<dim3(4, 64), 256, SMEM_G128>>>(xall,       wt_uqr, uqr, 512, 256, 960, 512);
    mma_gemm<64> <<<dim3(3, 64), 256, SMEM_G64 >>>(xall + 256, wt_ukv, ukv, 192, 128, 960, 192);

    // RoPE + concat + head RMSNorm -> packed fp16
    assemble_q_kernel <<<B_ * H_   * T_ / 8, 256>>>(uqr, 512, uqr + 256, 512, q_head_w, qhp, qlp);
    assemble_kv_kernel<<<B_ * KVH_ * T_ / 8, 256>>>(ukv, 192, xall + 384, 960,
                                                    ukv + 64, 192, k_head_w, khp, vhp);

    // causal flash attention + value residual (128-row Q tiles)
    flash_kernel<<<dim3(T_ / 128, B_ * H_), 256, SMEM_FL>>>(
        qhp, qlp, khp, vhp, xall + 448, 960, gao);

    // output projection
    mma_gemm<128><<<dim3(4, 64), 256, SMEM_G128>>>(gao, wt_o, out, 512, 512, 512, 512);
}

// round 10
// speedup vs baseline: 4.9729x; 1.0277x over previous
#include <cuda_runtime.h>
#include <cuda_fp16.h>
#include <cstdint>
#include <math.h>

#define B_   4
#define T_   2048
#define H_   8
#define KVH_ 2
#define BT_  (B_ * T_)   // 8192
#define GQA_ (H_ / KVH_) // 4

// ---------------- scratch (device globals) ----------------------------------------
__device__ float g_xall [BT_ * 960];   // [DQ 0:256 | DKV 256:384 | KR 384:448 | VR 448:960]
__device__ float g_uqr  [BT_ * 512];   // [qnope 0:256 | qrope 256:512]
__device__ float g_ukv  [BT_ * 192];   // [knope 0:64 | vproj 64:192]
__device__ float g_ao   [BT_ * 512];
__device__ float g_cos  [T_ * 16];
__device__ float g_sin  [T_ * 16];

// packed fp16x2 tensors for flash
__device__ uint32_t g_qh [B_ * H_   * T_ * 32];
__device__ uint32_t g_ql [B_ * H_   * T_ * 32];
__device__ uint32_t g_kh [B_ * KVH_ * T_ * 32];
__device__ uint32_t g_vh [B_ * KVH_ * T_ * 32];

// transposed + fp16x2-packed weights [N][K/2]
__device__ uint32_t g_wt_x  [960 * 256];
__device__ uint32_t g_wt_uqr[512 * 128];
__device__ uint32_t g_wt_ukv[192 * 64];
__device__ uint32_t g_wt_o  [512 * 256];

// ---------------- helpers ---------------------------------------------------------
__device__ __forceinline__ uint32_t sptr(const void* p) {
    return (uint32_t)__cvta_generic_to_shared(p);
}
__device__ __forceinline__ uint32_t pack2f(float x, float y) {   // x -> low half
    uint32_t r;
    asm("cvt.rn.f16x2.f32 %0, %1, %2;" : "=r"(r) : "f"(y), "f"(x));
    return r;
}
__device__ __forceinline__ void f16split2(float x, float y, uint32_t& h, uint32_t& l) {
    asm("cvt.rn.f16x2.f32 %0, %1, %2;" : "=r"(h) : "f"(y), "f"(x));
    __half2 hb = *reinterpret_cast<__half2*>(&h);
    float rx = x - __low2float(hb);
    float ry = y - __high2float(hb);
    asm("cvt.rn.f16x2.f32 %0, %1, %2;" : "=r"(l) : "f"(ry), "f"(rx));
}
__device__ __forceinline__ void mma_f16(float* c, const uint32_t* a,
                                        uint32_t b0, uint32_t b1) {
    asm volatile(
        "mma.sync.aligned.m16n8k16.row.col.f32.f16.f16.f32 "
        "{%0,%1,%2,%3}, {%4,%5,%6,%7}, {%8,%9}, {%0,%1,%2,%3};\n"
        : "+f"(c[0]), "+f"(c[1]), "+f"(c[2]), "+f"(c[3])
        : "r"(a[0]), "r"(a[1]), "r"(a[2]), "r"(a[3]), "r"(b0), "r"(b1));
}
__device__ __forceinline__ void ldm4(uint32_t* r, uint32_t addr) {
    asm volatile("ldmatrix.sync.aligned.m8n8.x4.shared.b16 {%0,%1,%2,%3}, [%4];"
                 : "=r"(r[0]), "=r"(r[1]), "=r"(r[2]), "=r"(r[3]) : "r"(addr));
}
__device__ __forceinline__ void ldm4t(uint32_t* r, uint32_t addr) {
    asm volatile("ldmatrix.sync.aligned.m8n8.x4.trans.shared.b16 {%0,%1,%2,%3}, [%4];"
                 : "=r"(r[0]), "=r"(r[1]), "=r"(r[2]), "=r"(r[3]) : "r"(addr));
}
__device__ __forceinline__ void cpa16(uint32_t saddr, const void* g) {
    asm volatile("cp.async.cg.shared.global [%0], [%1], 16;" :: "r"(saddr), "l"(g) : "memory");
}
#define CP_COMMIT() asm volatile("cp.async.commit_group;" ::: "memory")
#define CP_WAIT0()  asm volatile("cp.async.wait_group 0;"  ::: "memory")

// ---------------- fused prep: 9 weight transpose+pack + rope tables ----------------
struct PrepArgs {
    const float* src[9];
    uint32_t*    dst[9];
    int K[9], N[9];
    int off[10];
};

__global__ void prep_kernel(PrepArgs a) {
    __shared__ float tb[32][33];
    int bx = blockIdx.x;
    int x = threadIdx.x, y = threadIdx.y;
    if (bx >= a.off[9]) {
        int idx = (bx - a.off[9]) * 256 + y * 32 + x;
        if (idx < T_ * 16) {
            int t = idx >> 4, i = idx & 15;
            double invf = pow(500000.0, -((double)(2 * i)) / 32.0);
            double ang  = (double)t * invf;
            g_cos[idx] = (float)cos(ang);
            g_sin[idx] = (float)sin(ang);
        }
        return;
    }
    int m = 0;
    #pragma unroll
    for (int i = 1; i < 9; i++) if (bx >= a.off[i]) m = i;
    int lt = bx - a.off[m];
    int N = a.N[m], K = a.K[m];
    int ntx = N >> 5;
    int n0 = (lt % ntx) * 32, k0 = (lt / ntx) * 32;
    const float* in = a.src[m];
    uint32_t* out = a.dst[m];
    #pragma unroll
    for (int d = 0; d < 32; d += 8)
        tb[y + d][x] = in[(size_t)(k0 + y + d) * N + n0 + x];
    __syncthreads();
    if (x < 16) {
        int kd2 = K >> 1;
        #pragma unroll
        for (int d = 0; d < 32; d += 8)
            out[(size_t)(n0 + y + d) * kd2 + (k0 >> 1) + x] =
                pack2f(tb[2 * x][y + d], tb[2 * x + 1][y + d]);
    }
}

// ---------------- fp16 GEMM, double-buffered, 1 barrier/chunk ----------------------
// C[?,N] = A[128-rows,K] @ BT[N,K]^T. block 128 x TN, 256 threads, K chunks of 32.
// Stage layout (u32): [Ah 128*20 | Al 128*20 | Bh TN*20] x 2 stages.
template <int TN>
__global__ void __launch_bounds__(256)
mma_gemm(const float* __restrict__ A, const uint32_t* __restrict__ BT,
         float* __restrict__ C, int N, int K, int lda, int ldc) {
    extern __shared__ uint32_t us[];
    constexpr int SPU    = 20;
    constexpr int ALOu   = 128 * SPU;           // Al offset within stage (u32)
    constexpr int BOFFu  = 256 * SPU;           // Bh offset within stage (u32)
    constexpr int STGu   = (256 + TN) * SPU;    // stage stride (u32)

    constexpr int WMW    = (TN == 128) ? 2 : 4;
    constexpr int WARP_M = 128 / WMW;
    constexpr int MI     = WARP_M / 16;
    constexpr int BR2    = TN / 64;   // 16B cp.async chunks per thread for B

    const int tid = threadIdx.x, wid = tid >> 5, lane = tid & 31;
    const int wm = wid % WMW, wn = wid / WMW;
    const int g = lane >> 2, t4 = lane & 3;
    const int m0 = blockIdx.y * 128, n0 = blockIdx.x * TN;

    const uint32_t sBase = sptr(us);
    const int      lrA = lane & 15;
    const uint32_t lcA = (uint32_t)(lane >> 4) * 16;
    const int      lrB = (lane & 7) | ((lane >> 4) << 3);
    const uint32_t lcB = (uint32_t)((lane >> 3) & 1) * 16;

    const int ldb = K >> 1;
    const float*    Ab = A + (size_t)m0 * lda;
    const uint32_t* Bb = BT + (size_t)n0 * ldb;

    // prologue: A regs chunk0; cp.async B chunk0 -> stage 0
    float4 areg[4];
    #pragma unroll
    for (int j = 0; j < 4; j++) {
        int idx = tid + 256 * j, row = idx >> 3, q = idx & 7;
        areg[j] = *(const float4*)(Ab + (size_t)row * lda + q * 4);
    }
    #pragma unroll
    for (int j = 0; j < BR2; j++) {
        int idx = tid + 256 * j, row = idx >> 2, qu = idx & 3;
        cpa16(sBase + (BOFFu + row * SPU + qu * 4) * 4,
              Bb + (size_t)row * ldb + qu * 4);
    }
    CP_COMMIT();

    float c[MI][4][4];
    #pragma unroll
    for (int mi = 0; mi < MI; mi++)
        #pragma unroll
        for (int ni = 0; ni < 4; ni++)
            #pragma unroll
            for (int j = 0; j < 4; j++) c[mi][ni][j] = 0.f;

    const int NC = K >> 5;
    for (int ch = 0; ch < NC; ch++) {
        const int sg = ch & 1;
        uint32_t* stg = us + sg * STGu;
        const uint32_t stb = sBase + (uint32_t)(sg * STGu) * 4;

        // convert+store A chunk ch into this stage
        #pragma unroll
        for (int j = 0; j < 4; j++) {
            int idx = tid + 256 * j, row = idx >> 3, q = idx & 7;
            uint32_t h0, l0, h1, l1;
            f16split2(areg[j].x, areg[j].y, h0, l0);
            f16split2(areg[j].z, areg[j].w, h1, l1);
            *(uint2*)&stg[row * SPU + 2 * q]        = make_uint2(h0, h1);
            *(uint2*)&stg[ALOu + row * SPU + 2 * q] = make_uint2(l0, l1);
        }
        CP_WAIT0();
        __syncthreads();

        // prefetch chunk ch+1 (A regs + B cp.async into other stage)
        if (ch + 1 < NC) {
            int k0 = (ch + 1) * 32;
            #pragma unroll
            for (int j = 0; j < 4; j++) {
                int idx = tid + 256 * j, row = idx >> 3, q = idx & 7;
                areg[j] = *(const float4*)(Ab + (size_t)row * lda + k0 + q * 4);
            }
            uint32_t ob = sBase + (uint32_t)((1 - sg) * STGu) * 4;
            #pragma unroll
            for (int j = 0; j < BR2; j++) {
                int idx = tid + 256 * j, row = idx >> 2, qu = idx & 3;
                cpa16(ob + (BOFFu + row * SPU + qu * 4) * 4,
                      Bb + (size_t)row * ldb + (k0 >> 1) + qu * 4);
            }
            CP_COMMIT();
        }

        #pragma unroll
        for (int ks = 0; ks < 2; ks++) {
            uint32_t ah[MI][4], al[MI][4];
            #pragma unroll
            for (int mi = 0; mi < MI; mi++) {
                uint32_t ad = stb + (uint32_t)((wm * WARP_M + mi * 16 + lrA) * SPU) * 4
                              + ks * 32 + lcA;
                ldm4(ah[mi], ad);
                ldm4(al[mi], ad + ALOu * 4);
            }
            #pragma unroll
            for (int p = 0; p < 2; p++) {
                uint32_t bd = stb + (uint32_t)(BOFFu + (wn * 32 + p * 16 + lrB) * SPU) * 4
                              + ks * 32 + lcB;
                uint32_t bh2[4];
                ldm4(bh2, bd);
                #pragma unroll
                for (int mi = 0; mi < MI; mi++) {
                    mma_f16(c[mi][2 * p],     ah[mi], bh2[0], bh2[1]);
                    mma_f16(c[mi][2 * p],     al[mi], bh2[0], bh2[1]);
                    mma_f16(c[mi][2 * p + 1], ah[mi], bh2[2], bh2[3]);
                    mma_f16(c[mi][2 * p + 1], al[mi], bh2[2], bh2[3]);
                }
            }
        }
        // no trailing barrier: next chunk writes the OTHER stage
        __syncthreads();   // still needed: next iter's A-STS targets stage read 2 iters ago
    }

    #pragma unroll
    for (int mi = 0; mi < MI; mi++) {
        int row = m0 + wm * WARP_M + mi * 16 + g;
        #pragma unroll
        for (int ni = 0; ni < 4; ni++) {
            int col = n0 + wn * 32 + ni * 8 + t4 * 2;
            *(float2*)(C + (size_t)row * ldc + col) =
                make_float2(c[mi][ni][0], c[mi][ni][1]);
            *(float2*)(C + (size_t)(row + 8) * ldc + col) =
                make_float2(c[mi][ni][2], c[mi][ni][3]);
        }
    }
}

// ---------------- strided in-place row RMSNorm ------------------------------------
__global__ void rmsnorm_kernel(float* __restrict__ X, int ld,
                               const float* __restrict__ w, int N, int rows) {
    int warp = (blockIdx.x * blockDim.x + threadIdx.x) >> 5;
    int lane = threadIdx.x & 31;
    if (warp >= rows) return;
    float* row = X + (size_t)warp * ld;
    float ss = 0.f;
    for (int c = lane; c < N; c += 32) { float v = row[c]; ss += v * v; }
    #pragma unroll
    for (int o = 16; o; o >>= 1) ss += __shfl_xor_sync(0xffffffffu, ss, o);
    float inv = rsqrtf(ss / (float)N + 1e-6f);
    for (int c = lane; c < N; c += 32) row[c] = row[c] * inv * w[c];
}

// ---------------- assemble q: RoPE + concat + head RMSNorm -> packed fp16 hi/lo ----
__global__ void assemble_q_kernel(const float* __restrict__ nope, int ns,
                                  const float* __restrict__ rope, int rs,
                                  const float* __restrict__ w,
                                  uint32_t* __restrict__ qh,
                                  uint32_t* __restrict__ ql) {
    int gw   = (blockIdx.x * blockDim.x + threadIdx.x) >> 5;
    int lane = threadIdx.x & 31;
    if (gw >= B_ * H_ * T_) return;
    int t  = gw % T_;
    int bh = gw / T_;
    int h  = bh % H_;
    int b  = bh / H_;
    int tok = b * T_ + t;
    const float* np = nope + (size_t)tok * ns + h * 32;
    const float* rp = rope + (size_t)tok * rs + h * 32;

    float v0 = np[lane];
    float cs = g_cos[t * 16 + (lane & 15)];
    float sn = g_sin[t * 16 + (lane & 15)];
    float xj = rp[lane];
    float xp = (lane < 16) ? -rp[lane + 16] : rp[lane - 16];
    float v1 = xj * cs + xp * sn;

    float ss = v0 * v0 + v1 * v1;
    #pragma unroll
    for (int o = 16; o; o >>= 1) ss += __shfl_xor_sync(0xffffffffu, ss, o);
    float inv = rsqrtf(ss / 64.f + 1e-6f);
    float v0n = v0 * inv * w[lane];
    float v1n = v1 * inv * w[lane + 32];

    float a0 = __shfl_sync(0xffffffffu, v0n, (2 * lane) & 31);
    float b0 = __shfl_sync(0xffffffffu, v0n, (2 * lane + 1) & 31);
    float a1 = __shfl_sync(0xffffffffu, v1n, (2 * lane) & 31);
    float b1 = __shfl_sync(0xffffffffu, v1n, (2 * lane + 1) & 31);
    float A  = (lane < 16) ? a0 : a1;
    float Bv = (lane < 16) ? b0 : b1;
    uint32_t hh, ll;
    f16split2(A, Bv, hh, ll);
    qh[(size_t)gw * 32 + lane] = hh;
    ql[(size_t)gw * 32 + lane] = ll;
}

// ---------------- assemble k (+ pack v): RoPE + concat + head RMSNorm --------------
__global__ void assemble_kv_kernel(const float* __restrict__ nope, int ns,
                                   const float* __restrict__ rope, int rs,
                                   const float* __restrict__ vsrc, int vs,
                                   const float* __restrict__ w,
                                   uint32_t* __restrict__ kh,
                                   uint32_t* __restrict__ vh) {
    int gw   = (blockIdx.x * blockDim.x + threadIdx.x) >> 5;
    int lane = threadIdx.x & 31;
    if (gw >= B_ * KVH_ * T_) return;
    int t  = gw % T_;
    int bh = gw / T_;
    int h  = bh % KVH_;
    int b  = bh / KVH_;
    int tok = b * T_ + t;
    const float* np = nope + (size_t)tok * ns + h * 32;
    const float* rp = rope + (size_t)tok * rs + h * 32;

    float v0 = np[lane];
    float cs = g_cos[t * 16 + (lane & 15)];
    float sn = g_sin[t * 16 + (lane & 15)];
    float xj = rp[lane];
    float xp = (lane < 16) ? -rp[lane + 16] : rp[lane - 16];
    float v1 = xj * cs + xp * sn;

    float ss = v0 * v0 + v1 * v1;
    #pragma unroll
    for (int o = 16; o; o >>= 1) ss += __shfl_xor_sync(0xffffffffu, ss, o);
    float inv = rsqrtf(ss / 64.f + 1e-6f);
    float v0n = v0 * inv * w[lane];
    float v1n = v1 * inv * w[lane + 32];

    float a0 = __shfl_sync(0xffffffffu, v0n, (2 * lane) & 31);
    float b0 = __shfl_sync(0xffffffffu, v0n, (2 * lane + 1) & 31);
    float a1 = __shfl_sync(0xffffffffu, v1n, (2 * lane) & 31);
    float b1 = __shfl_sync(0xffffffffu, v1n, (2 * lane + 1) & 31);
    float A  = (lane < 16) ? a0 : a1;
    float Bv = (lane < 16) ? b0 : b1;
    kh[(size_t)gw * 32 + lane] = pack2f(A, Bv);

    const float* vp = vsrc + (size_t)tok * vs + h * 64;
    float2 vv = *(const float2*)(vp + 2 * lane);
    vh[(size_t)gw * 32 + lane] = pack2f(vv.x, vv.y);
}

// ---------------- flash attention: fp16 mma, cp.async double-buffered K/V ----------
// 128 q-rows x 64 k-cols per kt step, 256 threads (8 warps).
// Each warp owns 16 q-rows x all 64 k-cols; softmax warp-internal.
// smem: QH(128*36) QL(128*36) then 2 stages of [K 64*36 | V 64*36].
__global__ void __launch_bounds__(256)
flash_kernel(const uint32_t* __restrict__ qh, const uint32_t* __restrict__ ql,
             const uint32_t* __restrict__ kh, const uint32_t* __restrict__ vh,
             const float* __restrict__ vres, int ldvr,
             float* __restrict__ ao) {
    extern __shared__ uint32_t us[];
    constexpr int SP = 36;
    constexpr int KVu   = 64 * SP;          // one K (or V) tile in u32
    constexpr int KV0u  = 2 * 128 * SP;     // stage0 base (u32)
    constexpr int STGu  = 2 * KVu;          // stage stride
    uint32_t* QH = us;
    uint32_t* QL = QH + 128 * SP;

    const int tid = threadIdx.x, wid = tid >> 5, lane = tid & 31;
    const int g = lane >> 2, t4 = lane & 3;
    const int wr = wid * 16;

    const int qt = gridDim.x - 1 - blockIdx.x;   // big tiles first
    const int bh = blockIdx.y;
    const int b = bh / H_, h = bh % H_;
    const int kvh = h / GQA_;

    const uint32_t sBase = sptr(us);
    const uint32_t sQH = sBase;
    const uint32_t QLO = 128 * SP * 4;
    const int      lrA = lane & 15;
    const uint32_t lcA = (uint32_t)(lane >> 4) * 16;
    const int      lrB = (lane & 7) | ((lane >> 4) << 3);
    const uint32_t lcB = (uint32_t)((lane >> 3) & 1) * 16;
    const int      lrV = (lane & 7) | (((lane >> 3) & 1) << 3);
    const uint32_t lcV = (uint32_t)(lane >> 4) * 16;

    const uint32_t* kb = kh + ((size_t)(b * KVH_ + kvh) * T_) * 32;
    const uint32_t* vb = vh + ((size_t)(b * KVH_ + kvh) * T_) * 32;

    // stage tile 0 via cp.async
    {
        uint32_t s0 = sBase + KV0u * 4;
        int idx = tid, row = idx >> 3, qu = idx & 7;
        cpa16(s0 + (row * SP + qu * 4) * 4,       kb + (size_t)row * 32 + qu * 4);
        cpa16(s0 + (KVu + row * SP + qu * 4) * 4, vb + (size_t)row * 32 + qu * 4);
        idx = tid + 256; row = idx >> 3; qu = idx & 7;
        cpa16(s0 + (row * SP + qu * 4) * 4,       kb + (size_t)row * 32 + qu * 4);
        cpa16(s0 + (KVu + row * SP + qu * 4) * 4, vb + (size_t)row * 32 + qu * 4);
        CP_COMMIT();
    }

    // Q tile (128 rows) load: raw packed copies
    const uint32_t* qb  = qh + ((size_t)(b * H_ + h) * T_ + qt * 128) * 32;
    const uint32_t* qlb = ql + ((size_t)(b * H_ + h) * T_ + qt * 128) * 32;
    #pragma unroll
    for (int j = 0; j < 4; j++) {
        int idx = tid + 256 * j, row = idx >> 3, qu = idx & 7;
        *(uint4*)&QH[row * SP + qu * 4] = *(const uint4*)(qb + (size_t)row * 32 + qu * 4);
        *(uint4*)&QL[row * SP + qu * 4] = *(const uint4*)(qlb + (size_t)row * 32 + qu * 4);
    }

    float m0 = -1e30f, m1 = -1e30f, l0a = 0.f, l1a = 0.f;
    float o[8][4];
    #pragma unroll
    for (int ni = 0; ni < 8; ni++)
        #pragma unroll
        for (int j = 0; j < 4; j++) o[ni][j] = 0.f;

    const int ktmax = 2 * qt + 1;
    const int rowlim = qt * 128 + wr + 15;

    for (int kt = 0; kt <= ktmax; kt++) {
        const int sg = kt & 1;
        const uint32_t stg = sBase + (uint32_t)(KV0u + sg * STGu) * 4;
        const uint32_t sKS = stg;
        const uint32_t sVS = stg + KVu * 4;

        CP_WAIT0();
        __syncthreads();

        // prefetch tile kt+1 into the other stage (overlaps compute below)
        if (kt + 1 <= ktmax) {
            uint32_t ob = sBase + (uint32_t)(KV0u + (1 - sg) * STGu) * 4;
            const uint32_t* kn = kb + (size_t)(kt + 1) * 64 * 32;
            const uint32_t* vn = vb + (size_t)(kt + 1) * 64 * 32;
            #pragma unroll
            for (int j = 0; j < 2; j++) {
                int idx = tid + 256 * j, row = idx >> 3, qu = idx & 7;
                cpa16(ob + (row * SP + qu * 4) * 4,       kn + (size_t)row * 32 + qu * 4);
                cpa16(ob + (KVu + row * SP + qu * 4) * 4, vn + (size_t)row * 32 + qu * 4);
            }
            CP_COMMIT();
        }

        if (kt * 64 > rowlim) continue;   // fully masked for this warp

        // ---- S = Q @ K^T (2-term fp16: Q hi/lo, K single) ----
        float s[8][4];
        #pragma unroll
        for (int ni = 0; ni < 8; ni++)
            #pragma unroll
            for (int j = 0; j < 4; j++) s[ni][j] = 0.f;

        #pragma unroll
        for (int ks = 0; ks < 4; ks++) {
            uint32_t ad = sQH + (uint32_t)((wr + lrA) * SP) * 4 + ks * 32 + lcA;
            uint32_t ah[4], al[4];
            ldm4(ah, ad);
            ldm4(al, ad + QLO);
            #pragma unroll
            for (int p = 0; p < 4; p++) {
                uint32_t bd = sKS + (uint32_t)((p * 16 + lrB) * SP) * 4
                              + ks * 32 + lcB;
                uint32_t bh2[4];
                ldm4(bh2, bd);
                mma_f16(s[2 * p],     ah, bh2[0], bh2[1]);
                mma_f16(s[2 * p],     al, bh2[0], bh2[1]);
                mma_f16(s[2 * p + 1], ah, bh2[2], bh2[3]);
                mma_f16(s[2 * p + 1], al, bh2[2], bh2[3]);
            }
        }

        // scale + causal mask (only needed near the diagonal)
        const int rg0 = qt * 128 + wr + g;
        const int rg1 = rg0 + 8;
        if (kt * 64 + 63 > qt * 128 + wr) {
            #pragma unroll
            for (int ni = 0; ni < 8; ni++) {
                int cg = kt * 64 + ni * 8 + t4 * 2;
                #pragma unroll
                for (int j = 0; j < 4; j++) {
                    s[ni][j] *= 0.125f;
                    int cc = cg + (j & 1);
                    int rr = (j < 2) ? rg0 : rg1;
                    if (cc > rr) s[ni][j] = -1e30f;
                }
            }
        } else {
            #pragma unroll
            for (int ni = 0; ni < 8; ni++)
                #pragma unroll
                for (int j = 0; j < 4; j++) s[ni][j] *= 0.125f;
        }

        // warp-internal online softmax
        float rm0 = -1e30f, rm1 = -1e30f;
        #pragma unroll
        for (int ni = 0; ni < 8; ni++) {
            rm0 = fmaxf(rm0, fmaxf(s[ni][0], s[ni][1]));
            rm1 = fmaxf(rm1, fmaxf(s[ni][2], s[ni][3]));
        }
        #pragma unroll
        for (int off = 1; off <= 2; off <<= 1) {
            rm0 = fmaxf(rm0, __shfl_xor_sync(0xffffffffu, rm0, off));
            rm1 = fmaxf(rm1, __shfl_xor_sync(0xffffffffu, rm1, off));
        }
        float nm0 = fmaxf(m0, rm0);
        float nm1 = fmaxf(m1, rm1);
        float corr0 = __expf(m0 - nm0);
        float corr1 = __expf(m1 - nm1);
        m0 = nm0; m1 = nm1;

        float su0 = 0.f, su1 = 0.f;
        #pragma unroll
        for (int ni = 0; ni < 8; ni++) {
            s[ni][0] = __expf(s[ni][0] - nm0);
            s[ni][1] = __expf(s[ni][1] - nm0);
            s[ni][2] = __expf(s[ni][2] - nm1);
            s[ni][3] = __expf(s[ni][3] - nm1);
            su0 += s[ni][0] + s[ni][1];
            su1 += s[ni][2] + s[ni][3];
        }
        #pragma unroll
        for (int off = 1; off <= 2; off <<= 1) {
            su0 += __shfl_xor_sync(0xffffffffu, su0, off);
            su1 += __shfl_xor_sync(0xffffffffu, su1, off);
        }
        l0a = l0a * corr0 + su0;
        l1a = l1a * corr1 + su1;

        #pragma unroll
        for (int ni = 0; ni < 8; ni++) {
            o[ni][0] *= corr0; o[ni][1] *= corr0;
            o[ni][2] *= corr1; o[ni][3] *= corr1;
        }

        // ---- O += P @ V (fp16, register-resident P) ----
        #pragma unroll
        for (int ks = 0; ks < 4; ks++) {
            uint32_t pa[4];
            pa[0] = pack2f(s[2 * ks][0],     s[2 * ks][1]);
            pa[1] = pack2f(s[2 * ks][2],     s[2 * ks][3]);
            pa[2] = pack2f(s[2 * ks + 1][0], s[2 * ks + 1][1]);
            pa[3] = pack2f(s[2 * ks + 1][2], s[2 * ks + 1][3]);
            #pragma unroll
            for (int db = 0; db < 4; db++) {
                uint32_t vd = sVS + (uint32_t)((ks * 16 + lrV) * SP) * 4
                              + db * 32 + lcV;
                uint32_t bv[4];
                ldm4t(bv, vd);
                mma_f16(o[2 * db],     pa, bv[0], bv[1]);
                mma_f16(o[2 * db + 1], pa, bv[2], bv[3]);
            }
        }
    }

    // epilogue: each warp writes its own 16 rows x 64 d
    float invl0 = 1.f / l0a, invl1 = 1.f / l1a;
    int r0 = qt * 128 + wr + g;
    #pragma unroll
    for (int ni = 0; ni < 8; ni++) {
        int col = ni * 8 + t4 * 2;
        size_t vb0 = ((size_t)(b * T_ + r0)) * ldvr + h * 64 + col;
        size_t vb1 = ((size_t)(b * T_ + r0 + 8)) * ldvr + h * 64 + col;
        float2 vr0 = *(const float2*)(vres + vb0);
        float2 vr1 = *(const float2*)(vres + vb1);
        size_t ab0 = ((size_t)(b * T_ + r0)) * 512 + h * 64 + col;
        size_t ab1 = ((size_t)(b * T_ + r0 + 8)) * 512 + h * 64 + col;
        *(float2*)(ao + ab0) = make_float2(o[ni][0] * invl0 + vr0.x,
                                           o[ni][1] * invl0 + vr0.y);
        *(float2*)(ao + ab1) = make_float2(o[ni][2] * invl1 + vr1.x,
                                           o[ni][3] * invl1 + vr1.y);
    }
}

// ---------------- launch ----------------------------------------------------------
extern "C" void kernel_launch(void* const* d_in, const int* in_sizes, int n_in,
                              void* d_out, int out_size) {
    const float* x        = (const float*)d_in[0];
    const float* W_DQ     = (const float*)d_in[1];
    const float* W_UQ     = (const float*)d_in[2];
    const float* W_QR     = (const float*)d_in[3];
    const float* W_DKV    = (const float*)d_in[4];
    const float* W_UK     = (const float*)d_in[5];
    const float* W_UV     = (const float*)d_in[6];
    const float* W_KR     = (const float*)d_in[7];
    const float* W_VR     = (const float*)d_in[8];
    const float* W_O      = (const float*)d_in[9];
    const float* q_ln_w   = (const float*)d_in[10];
    const float* kv_ln_w  = (const float*)d_in[11];
    const float* q_head_w = (const float*)d_in[12];
    const float* k_head_w = (const float*)d_in[13];
    float* out = (float*)d_out;

    float *xall, *uqr, *ukv, *gao;
    uint32_t *qhp, *qlp, *khp, *vhp, *wt_x, *wt_uqr, *wt_ukv, *wt_o;
    cudaGetSymbolAddress((void**)&xall,   g_xall);
    cudaGetSymbolAddress((void**)&uqr,    g_uqr);
    cudaGetSymbolAddress((void**)&ukv,    g_ukv);
    cudaGetSymbolAddress((void**)&gao,    g_ao);
    cudaGetSymbolAddress((void**)&qhp,    g_qh);
    cudaGetSymbolAddress((void**)&qlp,    g_ql);
    cudaGetSymbolAddress((void**)&khp,    g_kh);
    cudaGetSymbolAddress((void**)&vhp,    g_vh);
    cudaGetSymbolAddress((void**)&wt_x,   g_wt_x);
    cudaGetSymbolAddress((void**)&wt_uqr, g_wt_uqr);
    cudaGetSymbolAddress((void**)&wt_ukv, g_wt_ukv);
    cudaGetSymbolAddress((void**)&wt_o,   g_wt_o);

    const int SMEM_G128 = 2 * (256 + 128) * 20 * 4;     // 61440
    const int SMEM_G64  = 2 * (256 + 64) * 20 * 4;      // 51200
    const int SMEM_FL   = (2 * 128 * 36 + 2 * 2 * 64 * 36) * 4;  // 73728
    cudaFuncSetAttribute(mma_gemm<128>, cudaFuncAttributeMaxDynamicSharedMemorySize, SMEM_G128);
    cudaFuncSetAttribute(mma_gemm<64>,  cudaFuncAttributeMaxDynamicSharedMemorySize, SMEM_G64);
    cudaFuncSetAttribute(flash_kernel,  cudaFuncAttributeMaxDynamicSharedMemorySize, SMEM_FL);

    // fused prep: 9 transpose+pack + rope tables
    PrepArgs pa;
    const float* srcs[9] = {W_DQ, W_DKV, W_KR, W_VR, W_UQ, W_QR, W_UK, W_UV, W_O};
    uint32_t* dsts[9] = {wt_x, wt_x + 256 * 256, wt_x + 384 * 256, wt_x + 448 * 256,
                         wt_uqr, wt_uqr + 256 * 128, wt_ukv, wt_ukv + 64 * 64, wt_o};
    int Ks[9] = {512, 512, 512, 512, 256, 256, 128, 128, 512};
    int Ns[9] = {256, 128,  64, 512, 256, 256,  64, 128, 512};
    int off = 0;
    for (int i = 0; i < 9; i++) {
        pa.src[i] = srcs[i]; pa.dst[i] = dsts[i];
        pa.K[i] = Ks[i]; pa.N[i] = Ns[i];
        pa.off[i] = off;
        off += (Ks[i] / 32) * (Ns[i] / 32);
    }
    pa.off[9] = off;   // 888
    prep_kernel<<<off + 128, dim3(32, 8)>>>(pa);

    // all x-projections in one GEMM: [8192,512] @ [512,960]
    mma_gemm<64><<<dim3(15, 64), 256, SMEM_G64>>>(x, wt_x, xall, 960, 512, 512, 960);

    // latent RMSNorms (strided views into xall)
    rmsnorm_kernel<<<BT_ / 8, 256>>>(xall,       960, q_ln_w,  256, BT_);
    rmsnorm_kernel<<<BT_ / 8, 256>>>(xall + 256, 960, kv_ln_w, 128, BT_);

    // up-projections
    mma_gemm<128><<<dim3(4, 64), 256, SMEM_G128>>>(xall,       wt_uqr, uqr, 512, 256, 960, 512);
    mma_gemm<64> <<<dim3(3, 64), 256, SMEM_G64 >>>(xall + 256, wt_ukv, ukv, 192, 128, 960, 192);

    // RoPE + concat + head RMSNorm -> packed fp16
    assemble_q_kernel <<<B_ * H_   * T_ / 8, 256>>>(uqr, 512, uqr + 256, 512, q_head_w, qhp, qlp);
    assemble_kv_kernel<<<B_ * KVH_ * T_ / 8, 256>>>(ukv, 192, xall + 384, 960,
                                                    ukv + 64, 192, k_head_w, khp, vhp);

    // causal flash attention + value residual (128-row Q tiles)
    flash_kernel<<<dim3(T_ / 128, B_ * H_), 256, SMEM_FL>>>(
        qhp, qlp, khp, vhp, xall + 448, 960, gao);

    // output projection
    mma_gemm<128><<<dim3(4, 64), 256, SMEM_G128>>>(gao, wt_o, out, 512, 512, 512, 512);
}

// round 11
// speedup vs baseline: 5.1876x; 1.0432x over previous
#include <cuda_runtime.h>
#include <cuda_fp16.h>
#include <cstdint>
#include <math.h>

#define B_   4
#define T_   2048
#define H_   8
#define KVH_ 2
#define BT_  (B_ * T_)   // 8192
#define GQA_ (H_ / KVH_) // 4

// ---------------- scratch (device globals) ----------------------------------------
__device__ float g_xall [BT_ * 960];   // [DQ 0:256 | DKV 256:384 | KR 384:448 | VR 448:960]
__device__ float g_uqr  [BT_ * 512];   // [qnope 0:256 | qrope 256:512]
__device__ float g_ukv  [BT_ * 192];   // [knope 0:64 | vproj 64:192]
__device__ float g_ao   [BT_ * 512];
__device__ float g_cos  [T_ * 16];
__device__ float g_sin  [T_ * 16];

// packed fp16x2 tensors for flash
__device__ uint32_t g_qh [B_ * H_   * T_ * 32];
__device__ uint32_t g_ql [B_ * H_   * T_ * 32];
__device__ uint32_t g_kh [B_ * KVH_ * T_ * 32];
__device__ uint32_t g_vh [B_ * KVH_ * T_ * 32];

// transposed + fp16x2-packed weights [N][K/2]
__device__ uint32_t g_wt_x  [960 * 256];
__device__ uint32_t g_wt_uqr[512 * 128];
__device__ uint32_t g_wt_ukv[192 * 64];
__device__ uint32_t g_wt_o  [512 * 256];

// ---------------- helpers ---------------------------------------------------------
__device__ __forceinline__ uint32_t sptr(const void* p) {
    return (uint32_t)__cvta_generic_to_shared(p);
}
__device__ __forceinline__ uint32_t pack2f(float x, float y) {   // x -> low half
    uint32_t r;
    asm("cvt.rn.f16x2.f32 %0, %1, %2;" : "=r"(r) : "f"(y), "f"(x));
    return r;
}
__device__ __forceinline__ void f16split2(float x, float y, uint32_t& h, uint32_t& l) {
    asm("cvt.rn.f16x2.f32 %0, %1, %2;" : "=r"(h) : "f"(y), "f"(x));
    __half2 hb = *reinterpret_cast<__half2*>(&h);
    float rx = x - __low2float(hb);
    float ry = y - __high2float(hb);
    asm("cvt.rn.f16x2.f32 %0, %1, %2;" : "=r"(l) : "f"(ry), "f"(rx));
}
__device__ __forceinline__ void mma_f16(float* c, const uint32_t* a,
                                        uint32_t b0, uint32_t b1) {
    asm volatile(
        "mma.sync.aligned.m16n8k16.row.col.f32.f16.f16.f32 "
        "{%0,%1,%2,%3}, {%4,%5,%6,%7}, {%8,%9}, {%0,%1,%2,%3};\n"
        : "+f"(c[0]), "+f"(c[1]), "+f"(c[2]), "+f"(c[3])
        : "r"(a[0]), "r"(a[1]), "r"(a[2]), "r"(a[3]), "r"(b0), "r"(b1));
}
__device__ __forceinline__ void ldm4(uint32_t* r, uint32_t addr) {
    asm volatile("ldmatrix.sync.aligned.m8n8.x4.shared.b16 {%0,%1,%2,%3}, [%4];"
                 : "=r"(r[0]), "=r"(r[1]), "=r"(r[2]), "=r"(r[3]) : "r"(addr));
}
__device__ __forceinline__ void ldm4t(uint32_t* r, uint32_t addr) {
    asm volatile("ldmatrix.sync.aligned.m8n8.x4.trans.shared.b16 {%0,%1,%2,%3}, [%4];"
                 : "=r"(r[0]), "=r"(r[1]), "=r"(r[2]), "=r"(r[3]) : "r"(addr));
}
__device__ __forceinline__ void cpa16(uint32_t saddr, const void* g) {
    asm volatile("cp.async.cg.shared.global [%0], [%1], 16;" :: "r"(saddr), "l"(g) : "memory");
}
#define CP_COMMIT() asm volatile("cp.async.commit_group;" ::: "memory")
#define CP_WAIT0()  asm volatile("cp.async.wait_group 0;"  ::: "memory")

// ---------------- fused prep: 9 weight transpose+pack + rope tables ----------------
struct PrepArgs {
    const float* src[9];
    uint32_t*    dst[9];
    int K[9], N[9];
    int off[10];
};

__global__ void prep_kernel(PrepArgs a) {
    __shared__ float tb[32][33];
    int bx = blockIdx.x;
    int x = threadIdx.x, y = threadIdx.y;
    if (bx >= a.off[9]) {
        int idx = (bx - a.off[9]) * 256 + y * 32 + x;
        if (idx < T_ * 16) {
            int t = idx >> 4, i = idx & 15;
            double invf = pow(500000.0, -((double)(2 * i)) / 32.0);
            double ang  = (double)t * invf;
            g_cos[idx] = (float)cos(ang);
            g_sin[idx] = (float)sin(ang);
        }
        return;
    }
    int m = 0;
    #pragma unroll
    for (int i = 1; i < 9; i++) if (bx >= a.off[i]) m = i;
    int lt = bx - a.off[m];
    int N = a.N[m], K = a.K[m];
    int ntx = N >> 5;
    int n0 = (lt % ntx) * 32, k0 = (lt / ntx) * 32;
    const float* in = a.src[m];
    uint32_t* out = a.dst[m];
    #pragma unroll
    for (int d = 0; d < 32; d += 8)
        tb[y + d][x] = in[(size_t)(k0 + y + d) * N + n0 + x];
    __syncthreads();
    if (x < 16) {
        int kd2 = K >> 1;
        #pragma unroll
        for (int d = 0; d < 32; d += 8)
            out[(size_t)(n0 + y + d) * kd2 + (k0 >> 1) + x] =
                pack2f(tb[2 * x][y + d], tb[2 * x + 1][y + d]);
    }
}

// ---------------- fp16 GEMM, double-buffered, 1 barrier/chunk ----------------------
// C[?,N] = A[128-rows,K] @ BT[N,K]^T. block 128 x TN, 256 threads, K chunks of 32.
// Stage layout (u32): [Ah 128*20 | Al 128*20 | Bh TN*20] x 2 stages.
template <int TN>
__global__ void __launch_bounds__(256)
mma_gemm(const float* __restrict__ A, const uint32_t* __restrict__ BT,
         float* __restrict__ C, int N, int K, int lda, int ldc) {
    extern __shared__ uint32_t us[];
    constexpr int SPU    = 20;
    constexpr int ALOu   = 128 * SPU;
    constexpr int BOFFu  = 256 * SPU;
    constexpr int STGu   = (256 + TN) * SPU;

    constexpr int WMW    = (TN == 128) ? 2 : 4;
    constexpr int WARP_M = 128 / WMW;
    constexpr int MI     = WARP_M / 16;
    constexpr int BR2    = TN / 64;

    const int tid = threadIdx.x, wid = tid >> 5, lane = tid & 31;
    const int wm = wid % WMW, wn = wid / WMW;
    const int g = lane >> 2, t4 = lane & 3;
    const int m0 = blockIdx.y * 128, n0 = blockIdx.x * TN;

    const uint32_t sBase = sptr(us);
    const int      lrA = lane & 15;
    const uint32_t lcA = (uint32_t)(lane >> 4) * 16;
    const int      lrB = (lane & 7) | ((lane >> 4) << 3);
    const uint32_t lcB = (uint32_t)((lane >> 3) & 1) * 16;

    const int ldb = K >> 1;
    const float*    Ab = A + (size_t)m0 * lda;
    const uint32_t* Bb = BT + (size_t)n0 * ldb;

    float4 areg[4];
    #pragma unroll
    for (int j = 0; j < 4; j++) {
        int idx = tid + 256 * j, row = idx >> 3, q = idx & 7;
        areg[j] = *(const float4*)(Ab + (size_t)row * lda + q * 4);
    }
    #pragma unroll
    for (int j = 0; j < BR2; j++) {
        int idx = tid + 256 * j, row = idx >> 2, qu = idx & 3;
        cpa16(sBase + (BOFFu + row * SPU + qu * 4) * 4,
              Bb + (size_t)row * ldb + qu * 4);
    }
    CP_COMMIT();

    float c[MI][4][4];
    #pragma unroll
    for (int mi = 0; mi < MI; mi++)
        #pragma unroll
        for (int ni = 0; ni < 4; ni++)
            #pragma unroll
            for (int j = 0; j < 4; j++) c[mi][ni][j] = 0.f;

    const int NC = K >> 5;
    for (int ch = 0; ch < NC; ch++) {
        const int sg = ch & 1;
        uint32_t* stg = us + sg * STGu;
        const uint32_t stb = sBase + (uint32_t)(sg * STGu) * 4;

        #pragma unroll
        for (int j = 0; j < 4; j++) {
            int idx = tid + 256 * j, row = idx >> 3, q = idx & 7;
            uint32_t h0, l0, h1, l1;
            f16split2(areg[j].x, areg[j].y, h0, l0);
            f16split2(areg[j].z, areg[j].w, h1, l1);
            *(uint2*)&stg[row * SPU + 2 * q]        = make_uint2(h0, h1);
            *(uint2*)&stg[ALOu + row * SPU + 2 * q] = make_uint2(l0, l1);
        }
        CP_WAIT0();
        __syncthreads();

        if (ch + 1 < NC) {
            int k0 = (ch + 1) * 32;
            #pragma unroll
            for (int j = 0; j < 4; j++) {
                int idx = tid + 256 * j, row = idx >> 3, q = idx & 7;
                areg[j] = *(const float4*)(Ab + (size_t)row * lda + k0 + q * 4);
            }
            uint32_t ob = sBase + (uint32_t)((1 - sg) * STGu) * 4;
            #pragma unroll
            for (int j = 0; j < BR2; j++) {
                int idx = tid + 256 * j, row = idx >> 2, qu = idx & 3;
                cpa16(ob + (BOFFu + row * SPU + qu * 4) * 4,
                      Bb + (size_t)row * ldb + (k0 >> 1) + qu * 4);
            }
            CP_COMMIT();
        }

        #pragma unroll
        for (int ks = 0; ks < 2; ks++) {
            uint32_t ah[MI][4], al[MI][4];
            #pragma unroll
            for (int mi = 0; mi < MI; mi++) {
                uint32_t ad = stb + (uint32_t)((wm * WARP_M + mi * 16 + lrA) * SPU) * 4
                              + ks * 32 + lcA;
                ldm4(ah[mi], ad);
                ldm4(al[mi], ad + ALOu * 4);
            }
            #pragma unroll
            for (int p = 0; p < 2; p++) {
                uint32_t bd = stb + (uint32_t)(BOFFu + (wn * 32 + p * 16 + lrB) * SPU) * 4
                              + ks * 32 + lcB;
                uint32_t bh2[4];
                ldm4(bh2, bd);
                #pragma unroll
                for (int mi = 0; mi < MI; mi++) {
                    mma_f16(c[mi][2 * p],     ah[mi], bh2[0], bh2[1]);
                    mma_f16(c[mi][2 * p],     al[mi], bh2[0], bh2[1]);
                    mma_f16(c[mi][2 * p + 1], ah[mi], bh2[2], bh2[3]);
                    mma_f16(c[mi][2 * p + 1], al[mi], bh2[2], bh2[3]);
                }
            }
        }
        // no trailing barrier: stage sg is next written at ch+2, whose writers
        // must first pass ch+1's barrier, which post-dates all ch reads.
    }

    #pragma unroll
    for (int mi = 0; mi < MI; mi++) {
        int row = m0 + wm * WARP_M + mi * 16 + g;
        #pragma unroll
        for (int ni = 0; ni < 4; ni++) {
            int col = n0 + wn * 32 + ni * 8 + t4 * 2;
            *(float2*)(C + (size_t)row * ldc + col) =
                make_float2(c[mi][ni][0], c[mi][ni][1]);
            *(float2*)(C + (size_t)(row + 8) * ldc + col) =
                make_float2(c[mi][ni][2], c[mi][ni][3]);
        }
    }
}

// ---------------- strided in-place row RMSNorm ------------------------------------
__global__ void rmsnorm_kernel(float* __restrict__ X, int ld,
                               const float* __restrict__ w, int N, int rows) {
    int warp = (blockIdx.x * blockDim.x + threadIdx.x) >> 5;
    int lane = threadIdx.x & 31;
    if (warp >= rows) return;
    float* row = X + (size_t)warp * ld;
    float ss = 0.f;
    for (int c = lane; c < N; c += 32) { float v = row[c]; ss += v * v; }
    #pragma unroll
    for (int o = 16; o; o >>= 1) ss += __shfl_xor_sync(0xffffffffu, ss, o);
    float inv = rsqrtf(ss / (float)N + 1e-6f);
    for (int c = lane; c < N; c += 32) row[c] = row[c] * inv * w[c];
}

// ---------------- assemble q: RoPE + concat + head RMSNorm -> packed fp16 hi/lo ----
__global__ void assemble_q_kernel(const float* __restrict__ nope, int ns,
                                  const float* __restrict__ rope, int rs,
                                  const float* __restrict__ w,
                                  uint32_t* __restrict__ qh,
                                  uint32_t* __restrict__ ql) {
    int gw   = (blockIdx.x * blockDim.x + threadIdx.x) >> 5;
    int lane = threadIdx.x & 31;
    if (gw >= B_ * H_ * T_) return;
    int t  = gw % T_;
    int bh = gw / T_;
    int h  = bh % H_;
    int b  = bh / H_;
    int tok = b * T_ + t;
    const float* np = nope + (size_t)tok * ns + h * 32;
    const float* rp = rope + (size_t)tok * rs + h * 32;

    float v0 = np[lane];
    float cs = g_cos[t * 16 + (lane & 15)];
    float sn = g_sin[t * 16 + (lane & 15)];
    float xj = rp[lane];
    float xp = (lane < 16) ? -rp[lane + 16] : rp[lane - 16];
    float v1 = xj * cs + xp * sn;

    float ss = v0 * v0 + v1 * v1;
    #pragma unroll
    for (int o = 16; o; o >>= 1) ss += __shfl_xor_sync(0xffffffffu, ss, o);
    float inv = rsqrtf(ss / 64.f + 1e-6f);
    float v0n = v0 * inv * w[lane];
    float v1n = v1 * inv * w[lane + 32];

    float a0 = __shfl_sync(0xffffffffu, v0n, (2 * lane) & 31);
    float b0 = __shfl_sync(0xffffffffu, v0n, (2 * lane + 1) & 31);
    float a1 = __shfl_sync(0xffffffffu, v1n, (2 * lane) & 31);
    float b1 = __shfl_sync(0xffffffffu, v1n, (2 * lane + 1) & 31);
    float A  = (lane < 16) ? a0 : a1;
    float Bv = (lane < 16) ? b0 : b1;
    uint32_t hh, ll;
    f16split2(A, Bv, hh, ll);
    qh[(size_t)gw * 32 + lane] = hh;
    ql[(size_t)gw * 32 + lane] = ll;
}

// ---------------- assemble k (+ pack v): RoPE + concat + head RMSNorm --------------
__global__ void assemble_kv_kernel(const float* __restrict__ nope, int ns,
                                   const float* __restrict__ rope, int rs,
                                   const float* __restrict__ vsrc, int vs,
                                   const float* __restrict__ w,
                                   uint32_t* __restrict__ kh,
                                   uint32_t* __restrict__ vh) {
    int gw   = (blockIdx.x * blockDim.x + threadIdx.x) >> 5;
    int lane = threadIdx.x & 31;
    if (gw >= B_ * KVH_ * T_) return;
    int t  = gw % T_;
    int bh = gw / T_;
    int h  = bh % KVH_;
    int b  = bh / KVH_;
    int tok = b * T_ + t;
    const float* np = nope + (size_t)tok * ns + h * 32;
    const float* rp = rope + (size_t)tok * rs + h * 32;

    float v0 = np[lane];
    float cs = g_cos[t * 16 + (lane & 15)];
    float sn = g_sin[t * 16 + (lane & 15)];
    float xj = rp[lane];
    float xp = (lane < 16) ? -rp[lane + 16] : rp[lane - 16];
    float v1 = xj * cs + xp * sn;

    float ss = v0 * v0 + v1 * v1;
    #pragma unroll
    for (int o = 16; o; o >>= 1) ss += __shfl_xor_sync(0xffffffffu, ss, o);
    float inv = rsqrtf(ss / 64.f + 1e-6f);
    float v0n = v0 * inv * w[lane];
    float v1n = v1 * inv * w[lane + 32];

    float a0 = __shfl_sync(0xffffffffu, v0n, (2 * lane) & 31);
    float b0 = __shfl_sync(0xffffffffu, v0n, (2 * lane + 1) & 31);
    float a1 = __shfl_sync(0xffffffffu, v1n, (2 * lane) & 31);
    float b1 = __shfl_sync(0xffffffffu, v1n, (2 * lane + 1) & 31);
    float A  = (lane < 16) ? a0 : a1;
    float Bv = (lane < 16) ? b0 : b1;
    kh[(size_t)gw * 32 + lane] = pack2f(A, Bv);

    const float* vp = vsrc + (size_t)tok * vs + h * 64;
    float2 vv = *(const float2*)(vp + 2 * lane);
    vh[(size_t)gw * 32 + lane] = pack2f(vv.x, vv.y);
}

// ---------------- flash attention: fp16 mma, FIXED-MAX softmax ---------------------
// q,k are RMS-normalized (||q||=||k||=8) so s = q.k/8 in [-8,8]; exp(s) <= e^8 fits
// fp16, row sums fit fp32. Softmax uses m=0: no running max, no corr, no O rescale;
// per-thread partial l accumulated across all kt, reduced ONCE in epilogue.
__global__ void __launch_bounds__(256)
flash_kernel(const uint32_t* __restrict__ qh, const uint32_t* __restrict__ ql,
             const uint32_t* __restrict__ kh, const uint32_t* __restrict__ vh,
             const float* __restrict__ vres, int ldvr,
             float* __restrict__ ao) {
    extern __shared__ uint32_t us[];
    constexpr int SP = 36;
    constexpr int KVu   = 64 * SP;
    constexpr int KV0u  = 2 * 128 * SP;
    constexpr int STGu  = 2 * KVu;
    uint32_t* QH = us;
    uint32_t* QL = QH + 128 * SP;

    const int tid = threadIdx.x, wid = tid >> 5, lane = tid & 31;
    const int g = lane >> 2, t4 = lane & 3;
    const int wr = wid * 16;

    const int qt = gridDim.x - 1 - blockIdx.x;   // big tiles first
    const int bh = blockIdx.y;
    const int b = bh / H_, h = bh % H_;
    const int kvh = h / GQA_;

    const uint32_t sBase = sptr(us);
    const uint32_t sQH = sBase;
    const uint32_t QLO = 128 * SP * 4;
    const int      lrA = lane & 15;
    const uint32_t lcA = (uint32_t)(lane >> 4) * 16;
    const int      lrB = (lane & 7) | ((lane >> 4) << 3);
    const uint32_t lcB = (uint32_t)((lane >> 3) & 1) * 16;
    const int      lrV = (lane & 7) | (((lane >> 3) & 1) << 3);
    const uint32_t lcV = (uint32_t)(lane >> 4) * 16;

    const uint32_t* kb = kh + ((size_t)(b * KVH_ + kvh) * T_) * 32;
    const uint32_t* vb = vh + ((size_t)(b * KVH_ + kvh) * T_) * 32;

    // stage tile 0 via cp.async
    {
        uint32_t s0 = sBase + KV0u * 4;
        int idx = tid, row = idx >> 3, qu = idx & 7;
        cpa16(s0 + (row * SP + qu * 4) * 4,       kb + (size_t)row * 32 + qu * 4);
        cpa16(s0 + (KVu + row * SP + qu * 4) * 4, vb + (size_t)row * 32 + qu * 4);
        idx = tid + 256; row = idx >> 3; qu = idx & 7;
        cpa16(s0 + (row * SP + qu * 4) * 4,       kb + (size_t)row * 32 + qu * 4);
        cpa16(s0 + (KVu + row * SP + qu * 4) * 4, vb + (size_t)row * 32 + qu * 4);
        CP_COMMIT();
    }

    // Q tile (128 rows) load: raw packed copies
    const uint32_t* qb  = qh + ((size_t)(b * H_ + h) * T_ + qt * 128) * 32;
    const uint32_t* qlb = ql + ((size_t)(b * H_ + h) * T_ + qt * 128) * 32;
    #pragma unroll
    for (int j = 0; j < 4; j++) {
        int idx = tid + 256 * j, row = idx >> 3, qu = idx & 7;
        *(uint4*)&QH[row * SP + qu * 4] = *(const uint4*)(qb + (size_t)row * 32 + qu * 4);
        *(uint4*)&QL[row * SP + qu * 4] = *(const uint4*)(qlb + (size_t)row * 32 + qu * 4);
    }

    float l0a = 0.f, l1a = 0.f;
    float o[8][4];
    #pragma unroll
    for (int ni = 0; ni < 8; ni++)
        #pragma unroll
        for (int j = 0; j < 4; j++) o[ni][j] = 0.f;

    const int ktmax = 2 * qt + 1;
    const int rowlim = qt * 128 + wr + 15;

    for (int kt = 0; kt <= ktmax; kt++) {
        const int sg = kt & 1;
        const uint32_t stg = sBase + (uint32_t)(KV0u + sg * STGu) * 4;
        const uint32_t sKS = stg;
        const uint32_t sVS = stg + KVu * 4;

        CP_WAIT0();
        __syncthreads();

        // prefetch tile kt+1 into the other stage (overlaps compute below)
        if (kt + 1 <= ktmax) {
            uint32_t ob = sBase + (uint32_t)(KV0u + (1 - sg) * STGu) * 4;
            const uint32_t* kn = kb + (size_t)(kt + 1) * 64 * 32;
            const uint32_t* vn = vb + (size_t)(kt + 1) * 64 * 32;
            #pragma unroll
            for (int j = 0; j < 2; j++) {
                int idx = tid + 256 * j, row = idx >> 3, qu = idx & 7;
                cpa16(ob + (row * SP + qu * 4) * 4,       kn + (size_t)row * 32 + qu * 4);
                cpa16(ob + (KVu + row * SP + qu * 4) * 4, vn + (size_t)row * 32 + qu * 4);
            }
            CP_COMMIT();
        }

        if (kt * 64 > rowlim) continue;   // fully masked for this warp

        // ---- S = Q @ K^T (2-term fp16: Q hi/lo, K single) ----
        float s[8][4];
        #pragma unroll
        for (int ni = 0; ni < 8; ni++)
            #pragma unroll
            for (int j = 0; j < 4; j++) s[ni][j] = 0.f;

        #pragma unroll
        for (int ks = 0; ks < 4; ks++) {
            uint32_t ad = sQH + (uint32_t)((wr + lrA) * SP) * 4 + ks * 32 + lcA;
            uint32_t ah[4], al[4];
            ldm4(ah, ad);
            ldm4(al, ad + QLO);
            #pragma unroll
            for (int p = 0; p < 4; p++) {
                uint32_t bd = sKS + (uint32_t)((p * 16 + lrB) * SP) * 4
                              + ks * 32 + lcB;
                uint32_t bh2[4];
                ldm4(bh2, bd);
                mma_f16(s[2 * p],     ah, bh2[0], bh2[1]);
                mma_f16(s[2 * p],     al, bh2[0], bh2[1]);
                mma_f16(s[2 * p + 1], ah, bh2[2], bh2[3]);
                mma_f16(s[2 * p + 1], al, bh2[2], bh2[3]);
            }
        }

        // scale + causal mask + exp (fixed max 0) + private l accumulation
        const int rg0 = qt * 128 + wr + g;
        const int rg1 = rg0 + 8;
        if (kt * 64 + 63 > qt * 128 + wr) {
            #pragma unroll
            for (int ni = 0; ni < 8; ni++) {
                int cg = kt * 64 + ni * 8 + t4 * 2;
                #pragma unroll
                for (int j = 0; j < 4; j++) {
                    s[ni][j] *= 0.125f;
                    int cc = cg + (j & 1);
                    int rr = (j < 2) ? rg0 : rg1;
                    if (cc > rr) s[ni][j] = -1e30f;
                }
            }
        } else {
            #pragma unroll
            for (int ni = 0; ni < 8; ni++)
                #pragma unroll
                for (int j = 0; j < 4; j++) s[ni][j] *= 0.125f;
        }

        #pragma unroll
        for (int ni = 0; ni < 8; ni++) {
            s[ni][0] = __expf(s[ni][0]);
            s[ni][1] = __expf(s[ni][1]);
            s[ni][2] = __expf(s[ni][2]);
            s[ni][3] = __expf(s[ni][3]);
            l0a += s[ni][0] + s[ni][1];
            l1a += s[ni][2] + s[ni][3];
        }

        // ---- O += P @ V (fp16, register-resident P, no rescale) ----
        #pragma unroll
        for (int ks = 0; ks < 4; ks++) {
            uint32_t pa[4];
            pa[0] = pack2f(s[2 * ks][0],     s[2 * ks][1]);
            pa[1] = pack2f(s[2 * ks][2],     s[2 * ks][3]);
            pa[2] = pack2f(s[2 * ks + 1][0], s[2 * ks + 1][1]);
            pa[3] = pack2f(s[2 * ks + 1][2], s[2 * ks + 1][3]);
            #pragma unroll
            for (int db = 0; db < 4; db++) {
                uint32_t vd = sVS + (uint32_t)((ks * 16 + lrV) * SP) * 4
                              + db * 32 + lcV;
                uint32_t bv[4];
                ldm4t(bv, vd);
                mma_f16(o[2 * db],     pa, bv[0], bv[1]);
                mma_f16(o[2 * db + 1], pa, bv[2], bv[3]);
            }
        }
    }

    // epilogue: single cross-lane l reduction, then write 16 rows x 64 d
    #pragma unroll
    for (int off = 1; off <= 2; off <<= 1) {
        l0a += __shfl_xor_sync(0xffffffffu, l0a, off);
        l1a += __shfl_xor_sync(0xffffffffu, l1a, off);
    }
    float invl0 = 1.f / l0a, invl1 = 1.f / l1a;
    int r0 = qt * 128 + wr + g;
    #pragma unroll
    for (int ni = 0; ni < 8; ni++) {
        int col = ni * 8 + t4 * 2;
        size_t vb0 = ((size_t)(b * T_ + r0)) * ldvr + h * 64 + col;
        size_t vb1 = ((size_t)(b * T_ + r0 + 8)) * ldvr + h * 64 + col;
        float2 vr0 = *(const float2*)(vres + vb0);
        float2 vr1 = *(const float2*)(vres + vb1);
        size_t ab0 = ((size_t)(b * T_ + r0)) * 512 + h * 64 + col;
        size_t ab1 = ((size_t)(b * T_ + r0 + 8)) * 512 + h * 64 + col;
        *(float2*)(ao + ab0) = make_float2(o[ni][0] * invl0 + vr0.x,
                                           o[ni][1] * invl0 + vr0.y);
        *(float2*)(ao + ab1) = make_float2(o[ni][2] * invl1 + vr1.x,
                                           o[ni][3] * invl1 + vr1.y);
    }
}

// ---------------- launch ----------------------------------------------------------
extern "C" void kernel_launch(void* const* d_in, const int* in_sizes, int n_in,
                              void* d_out, int out_size) {
    const float* x        = (const float*)d_in[0];
    const float* W_DQ     = (const float*)d_in[1];
    const float* W_UQ     = (const float*)d_in[2];
    const float* W_QR     = (const float*)d_in[3];
    const float* W_DKV    = (const float*)d_in[4];
    const float* W_UK     = (const float*)d_in[5];
    const float* W_UV     = (const float*)d_in[6];
    const float* W_KR     = (const float*)d_in[7];
    const float* W_VR     = (const float*)d_in[8];
    const float* W_O      = (const float*)d_in[9];
    const float* q_ln_w   = (const float*)d_in[10];
    const float* kv_ln_w  = (const float*)d_in[11];
    const float* q_head_w = (const float*)d_in[12];
    const float* k_head_w = (const float*)d_in[13];
    float* out = (float*)d_out;

    float *xall, *uqr, *ukv, *gao;
    uint32_t *qhp, *qlp, *khp, *vhp, *wt_x, *wt_uqr, *wt_ukv, *wt_o;
    cudaGetSymbolAddress((void**)&xall,   g_xall);
    cudaGetSymbolAddress((void**)&uqr,    g_uqr);
    cudaGetSymbolAddress((void**)&ukv,    g_ukv);
    cudaGetSymbolAddress((void**)&gao,    g_ao);
    cudaGetSymbolAddress((void**)&qhp,    g_qh);
    cudaGetSymbolAddress((void**)&qlp,    g_ql);
    cudaGetSymbolAddress((void**)&khp,    g_kh);
    cudaGetSymbolAddress((void**)&vhp,    g_vh);
    cudaGetSymbolAddress((void**)&wt_x,   g_wt_x);
    cudaGetSymbolAddress((void**)&wt_uqr, g_wt_uqr);
    cudaGetSymbolAddress((void**)&wt_ukv, g_wt_ukv);
    cudaGetSymbolAddress((void**)&wt_o,   g_wt_o);

    const int SMEM_G128 = 2 * (256 + 128) * 20 * 4;     // 61440
    const int SMEM_G64  = 2 * (256 + 64) * 20 * 4;      // 51200
    const int SMEM_FL   = (2 * 128 * 36 + 2 * 2 * 64 * 36) * 4;  // 73728
    cudaFuncSetAttribute(mma_gemm<128>, cudaFuncAttributeMaxDynamicSharedMemorySize, SMEM_G128);
    cudaFuncSetAttribute(mma_gemm<64>,  cudaFuncAttributeMaxDynamicSharedMemorySize, SMEM_G64);
    cudaFuncSetAttribute(flash_kernel,  cudaFuncAttributeMaxDynamicSharedMemorySize, SMEM_FL);

    // fused prep: 9 transpose+pack + rope tables
    PrepArgs pa;
    const float* srcs[9] = {W_DQ, W_DKV, W_KR, W_VR, W_UQ, W_QR, W_UK, W_UV, W_O};
    uint32_t* dsts[9] = {wt_x, wt_x + 256 * 256, wt_x + 384 * 256, wt_x + 448 * 256,
                         wt_uqr, wt_uqr + 256 * 128, wt_ukv, wt_ukv + 64 * 64, wt_o};
    int Ks[9] = {512, 512, 512, 512, 256, 256, 128, 128, 512};
    int Ns[9] = {256, 128,  64, 512, 256, 256,  64, 128, 512};
    int off = 0;
    for (int i = 0; i < 9; i++) {
        pa.src[i] = srcs[i]; pa.dst[i] = dsts[i];
        pa.K[i] = Ks[i]; pa.N[i] = Ns[i];
        pa.off[i] = off;
        off += (Ks[i] / 32) * (Ns[i] / 32);
    }
    pa.off[9] = off;   // 888
    prep_kernel<<<off + 128, dim3(32, 8)>>>(pa);

    // all x-projections in one GEMM: [8192,512] @ [512,960]
    mma_gemm<64><<<dim3(15, 64), 256, SMEM_G64>>>(x, wt_x, xall, 960, 512, 512, 960);

    // latent RMSNorms (strided views into xall)
    rmsnorm_kernel<<<BT_ / 8, 256>>>(xall,       960, q_ln_w,  256, BT_);
    rmsnorm_kernel<<<BT_ / 8, 256>>>(xall + 256, 960, kv_ln_w, 128, BT_);

    // up-projections
    mma_gemm<128><<<dim3(4, 64), 256, SMEM_G128>>>(xall,       wt_uqr, uqr, 512, 256, 960, 512);
    mma_gemm<64> <<<dim3(3, 64), 256, SMEM_G64 >>>(xall + 256, wt_ukv, ukv, 192, 128, 960, 192);

    // RoPE + concat + head RMSNorm -> packed fp16
    assemble_q_kernel <<<B_ * H_   * T_ / 8, 256>>>(uqr, 512, uqr + 256, 512, q_head_w, qhp, qlp);
    assemble_kv_kernel<<<B_ * KVH_ * T_ / 8, 256>>>(ukv, 192, xall + 384, 960,
                                                    ukv + 64, 192, k_head_w, khp, vhp);

    // causal flash attention + value residual (128-row Q tiles)
    flash_kernel<<<dim3(T_ / 128, B_ * H_), 256, SMEM_FL>>>(
        qhp, qlp, khp, vhp, xall + 448, 960, gao);

    // output projection
    mma_gemm<128><<<dim3(4, 64), 256, SMEM_G128>>>(gao, wt_o, out, 512, 512, 512, 512);
}

// round 12
// speedup vs baseline: 5.9227x; 1.1417x over previous
#include <cuda_runtime.h>
#include <cuda_fp16.h>
#include <cstdint>
#include <math.h>

#define B_   4
#define T_   2048
#define H_   8
#define KVH_ 2
#define BT_  (B_ * T_)   // 8192
#define GQA_ (H_ / KVH_) // 4

// ---------------- scratch (device globals) ----------------------------------------
__device__ float g_xall [BT_ * 960];   // [DQ 0:256 | DKV 256:384 | KR 384:448 | VR 448:960]
__device__ float g_uqr  [BT_ * 512];   // [qnope 0:256 | qrope 256:512]
__device__ float g_ukv  [BT_ * 192];   // [knope 0:64 | vproj 64:192]
__device__ float g_ao   [BT_ * 512];
__device__ float g_cos  [T_ * 16];
__device__ float g_sin  [T_ * 16];

// packed fp16x2 tensors for flash (single-precision-fp16 operands)
__device__ uint32_t g_qh [B_ * H_   * T_ * 32];
__device__ uint32_t g_kh [B_ * KVH_ * T_ * 32];
__device__ uint32_t g_vh [B_ * KVH_ * T_ * 32];

// transposed + fp16x2-packed weights [N][K/2]
__device__ uint32_t g_wt_x  [960 * 256];
__device__ uint32_t g_wt_uqr[512 * 128];
__device__ uint32_t g_wt_ukv[192 * 64];
__device__ uint32_t g_wt_o  [512 * 256];

// ---------------- helpers ---------------------------------------------------------
__device__ __forceinline__ uint32_t sptr(const void* p) {
    return (uint32_t)__cvta_generic_to_shared(p);
}
__device__ __forceinline__ uint32_t pack2f(float x, float y) {   // x -> low half
    uint32_t r;
    asm("cvt.rn.f16x2.f32 %0, %1, %2;" : "=r"(r) : "f"(y), "f"(x));
    return r;
}
__device__ __forceinline__ void f16split2(float x, float y, uint32_t& h, uint32_t& l) {
    asm("cvt.rn.f16x2.f32 %0, %1, %2;" : "=r"(h) : "f"(y), "f"(x));
    __half2 hb = *reinterpret_cast<__half2*>(&h);
    float rx = x - __low2float(hb);
    float ry = y - __high2float(hb);
    asm("cvt.rn.f16x2.f32 %0, %1, %2;" : "=r"(l) : "f"(ry), "f"(rx));
}
__device__ __forceinline__ void mma_f16(float* c, const uint32_t* a,
                                        uint32_t b0, uint32_t b1) {
    asm volatile(
        "mma.sync.aligned.m16n8k16.row.col.f32.f16.f16.f32 "
        "{%0,%1,%2,%3}, {%4,%5,%6,%7}, {%8,%9}, {%0,%1,%2,%3};\n"
        : "+f"(c[0]), "+f"(c[1]), "+f"(c[2]), "+f"(c[3])
        : "r"(a[0]), "r"(a[1]), "r"(a[2]), "r"(a[3]), "r"(b0), "r"(b1));
}
__device__ __forceinline__ void ldm4(uint32_t* r, uint32_t addr) {
    asm volatile("ldmatrix.sync.aligned.m8n8.x4.shared.b16 {%0,%1,%2,%3}, [%4];"
                 : "=r"(r[0]), "=r"(r[1]), "=r"(r[2]), "=r"(r[3]) : "r"(addr));
}
__device__ __forceinline__ void ldm4t(uint32_t* r, uint32_t addr) {
    asm volatile("ldmatrix.sync.aligned.m8n8.x4.trans.shared.b16 {%0,%1,%2,%3}, [%4];"
                 : "=r"(r[0]), "=r"(r[1]), "=r"(r[2]), "=r"(r[3]) : "r"(addr));
}
__device__ __forceinline__ void cpa16(uint32_t saddr, const void* g) {
    asm volatile("cp.async.cg.shared.global [%0], [%1], 16;" :: "r"(saddr), "l"(g) : "memory");
}
#define CP_COMMIT() asm volatile("cp.async.commit_group;" ::: "memory")
#define CP_WAIT0()  asm volatile("cp.async.wait_group 0;"  ::: "memory")

// ---------------- fused prep: 9 weight transpose+pack + rope tables ----------------
struct PrepArgs {
    const float* src[9];
    uint32_t*    dst[9];
    int K[9], N[9];
    int off[10];
};

__global__ void prep_kernel(PrepArgs a) {
    __shared__ float tb[32][33];
    int bx = blockIdx.x;
    int x = threadIdx.x, y = threadIdx.y;
    if (bx >= a.off[9]) {
        int idx = (bx - a.off[9]) * 256 + y * 32 + x;
        if (idx < T_ * 16) {
            int t = idx >> 4, i = idx & 15;
            double invf = pow(500000.0, -((double)(2 * i)) / 32.0);
            double ang  = (double)t * invf;
            g_cos[idx] = (float)cos(ang);
            g_sin[idx] = (float)sin(ang);
        }
        return;
    }
    int m = 0;
    #pragma unroll
    for (int i = 1; i < 9; i++) if (bx >= a.off[i]) m = i;
    int lt = bx - a.off[m];
    int N = a.N[m], K = a.K[m];
    int ntx = N >> 5;
    int n0 = (lt % ntx) * 32, k0 = (lt / ntx) * 32;
    const float* in = a.src[m];
    uint32_t* out = a.dst[m];
    #pragma unroll
    for (int d = 0; d < 32; d += 8)
        tb[y + d][x] = in[(size_t)(k0 + y + d) * N + n0 + x];
    __syncthreads();
    if (x < 16) {
        int kd2 = K >> 1;
        #pragma unroll
        for (int d = 0; d < 32; d += 8)
            out[(size_t)(n0 + y + d) * kd2 + (k0 >> 1) + x] =
                pack2f(tb[2 * x][y + d], tb[2 * x + 1][y + d]);
    }
}

// ---------------- fp16 GEMM, double-buffered, 1 barrier/chunk ----------------------
// C[?,N] = A[128-rows,K] @ BT[N,K]^T. block 128 x TN, 256 threads, K chunks of 32.
// SPLIT: A = hi+lo 2-term fp16; else single fp16 A.
// Stage layout (u32): [Ah 128*20 | (Al 128*20 if SPLIT) | Bh TN*20] x 2 stages.
template <int TN, bool SPLIT>
__global__ void __launch_bounds__(256)
mma_gemm(const float* __restrict__ A, const uint32_t* __restrict__ BT,
         float* __restrict__ C, int N, int K, int lda, int ldc) {
    extern __shared__ uint32_t us[];
    constexpr int SPU    = 20;
    constexpr int ALOu   = 128 * SPU;
    constexpr int BOFFu  = (SPLIT ? 256 : 128) * SPU;
    constexpr int STGu   = ((SPLIT ? 256 : 128) + TN) * SPU;

    constexpr int WMW    = (TN == 128) ? 2 : 4;
    constexpr int WARP_M = 128 / WMW;
    constexpr int MI     = WARP_M / 16;
    constexpr int BR2    = TN / 64;

    const int tid = threadIdx.x, wid = tid >> 5, lane = tid & 31;
    const int wm = wid % WMW, wn = wid / WMW;
    const int g = lane >> 2, t4 = lane & 3;
    const int m0 = blockIdx.y * 128, n0 = blockIdx.x * TN;

    const uint32_t sBase = sptr(us);
    const int      lrA = lane & 15;
    const uint32_t lcA = (uint32_t)(lane >> 4) * 16;
    const int      lrB = (lane & 7) | ((lane >> 4) << 3);
    const uint32_t lcB = (uint32_t)((lane >> 3) & 1) * 16;

    const int ldb = K >> 1;
    const float*    Ab = A + (size_t)m0 * lda;
    const uint32_t* Bb = BT + (size_t)n0 * ldb;

    float4 areg[4];
    #pragma unroll
    for (int j = 0; j < 4; j++) {
        int idx = tid + 256 * j, row = idx >> 3, q = idx & 7;
        areg[j] = *(const float4*)(Ab + (size_t)row * lda + q * 4);
    }
    #pragma unroll
    for (int j = 0; j < BR2; j++) {
        int idx = tid + 256 * j, row = idx >> 2, qu = idx & 3;
        cpa16(sBase + (BOFFu + row * SPU + qu * 4) * 4,
              Bb + (size_t)row * ldb + qu * 4);
    }
    CP_COMMIT();

    float c[MI][4][4];
    #pragma unroll
    for (int mi = 0; mi < MI; mi++)
        #pragma unroll
        for (int ni = 0; ni < 4; ni++)
            #pragma unroll
            for (int j = 0; j < 4; j++) c[mi][ni][j] = 0.f;

    const int NC = K >> 5;
    for (int ch = 0; ch < NC; ch++) {
        const int sg = ch & 1;
        uint32_t* stg = us + sg * STGu;
        const uint32_t stb = sBase + (uint32_t)(sg * STGu) * 4;

        #pragma unroll
        for (int j = 0; j < 4; j++) {
            int idx = tid + 256 * j, row = idx >> 3, q = idx & 7;
            if (SPLIT) {
                uint32_t h0, l0, h1, l1;
                f16split2(areg[j].x, areg[j].y, h0, l0);
                f16split2(areg[j].z, areg[j].w, h1, l1);
                *(uint2*)&stg[row * SPU + 2 * q]        = make_uint2(h0, h1);
                *(uint2*)&stg[ALOu + row * SPU + 2 * q] = make_uint2(l0, l1);
            } else {
                *(uint2*)&stg[row * SPU + 2 * q] =
                    make_uint2(pack2f(areg[j].x, areg[j].y),
                               pack2f(areg[j].z, areg[j].w));
            }
        }
        CP_WAIT0();
        __syncthreads();

        if (ch + 1 < NC) {
            int k0 = (ch + 1) * 32;
            #pragma unroll
            for (int j = 0; j < 4; j++) {
                int idx = tid + 256 * j, row = idx >> 3, q = idx & 7;
                areg[j] = *(const float4*)(Ab + (size_t)row * lda + k0 + q * 4);
            }
            uint32_t ob = sBase + (uint32_t)((1 - sg) * STGu) * 4;
            #pragma unroll
            for (int j = 0; j < BR2; j++) {
                int idx = tid + 256 * j, row = idx >> 2, qu = idx & 3;
                cpa16(ob + (BOFFu + row * SPU + qu * 4) * 4,
                      Bb + (size_t)row * ldb + (k0 >> 1) + qu * 4);
            }
            CP_COMMIT();
        }

        #pragma unroll
        for (int ks = 0; ks < 2; ks++) {
            uint32_t ah[MI][4], al[MI][4];
            #pragma unroll
            for (int mi = 0; mi < MI; mi++) {
                uint32_t ad = stb + (uint32_t)((wm * WARP_M + mi * 16 + lrA) * SPU) * 4
                              + ks * 32 + lcA;
                ldm4(ah[mi], ad);
                if (SPLIT) ldm4(al[mi], ad + ALOu * 4);
            }
            #pragma unroll
            for (int p = 0; p < 2; p++) {
                uint32_t bd = stb + (uint32_t)(BOFFu + (wn * 32 + p * 16 + lrB) * SPU) * 4
                              + ks * 32 + lcB;
                uint32_t bh2[4];
                ldm4(bh2, bd);
                #pragma unroll
                for (int mi = 0; mi < MI; mi++) {
                    mma_f16(c[mi][2 * p],     ah[mi], bh2[0], bh2[1]);
                    if (SPLIT) mma_f16(c[mi][2 * p], al[mi], bh2[0], bh2[1]);
                    mma_f16(c[mi][2 * p + 1], ah[mi], bh2[2], bh2[3]);
                    if (SPLIT) mma_f16(c[mi][2 * p + 1], al[mi], bh2[2], bh2[3]);
                }
            }
        }
        // no trailing barrier: stage sg next written at ch+2, after ch+1's barrier.
    }

    #pragma unroll
    for (int mi = 0; mi < MI; mi++) {
        int row = m0 + wm * WARP_M + mi * 16 + g;
        #pragma unroll
        for (int ni = 0; ni < 4; ni++) {
            int col = n0 + wn * 32 + ni * 8 + t4 * 2;
            *(float2*)(C + (size_t)row * ldc + col) =
                make_float2(c[mi][ni][0], c[mi][ni][1]);
            *(float2*)(C + (size_t)(row + 8) * ldc + col) =
                make_float2(c[mi][ni][2], c[mi][ni][3]);
        }
    }
}

// ---------------- strided in-place row RMSNorm ------------------------------------
__global__ void rmsnorm_kernel(float* __restrict__ X, int ld,
                               const float* __restrict__ w, int N, int rows) {
    int warp = (blockIdx.x * blockDim.x + threadIdx.x) >> 5;
    int lane = threadIdx.x & 31;
    if (warp >= rows) return;
    float* row = X + (size_t)warp * ld;
    float ss = 0.f;
    for (int c = lane; c < N; c += 32) { float v = row[c]; ss += v * v; }
    #pragma unroll
    for (int o = 16; o; o >>= 1) ss += __shfl_xor_sync(0xffffffffu, ss, o);
    float inv = rsqrtf(ss / (float)N + 1e-6f);
    for (int c = lane; c < N; c += 32) row[c] = row[c] * inv * w[c];
}

// ---------------- assemble q: RoPE + concat + head RMSNorm -> packed fp16 ----------
__global__ void assemble_q_kernel(const float* __restrict__ nope, int ns,
                                  const float* __restrict__ rope, int rs,
                                  const float* __restrict__ w,
                                  uint32_t* __restrict__ qh) {
    int gw   = (blockIdx.x * blockDim.x + threadIdx.x) >> 5;
    int lane = threadIdx.x & 31;
    if (gw >= B_ * H_ * T_) return;
    int t  = gw % T_;
    int bh = gw / T_;
    int h  = bh % H_;
    int b  = bh / H_;
    int tok = b * T_ + t;
    const float* np = nope + (size_t)tok * ns + h * 32;
    const float* rp = rope + (size_t)tok * rs + h * 32;

    float v0 = np[lane];
    float cs = g_cos[t * 16 + (lane & 15)];
    float sn = g_sin[t * 16 + (lane & 15)];
    float xj = rp[lane];
    float xp = (lane < 16) ? -rp[lane + 16] : rp[lane - 16];
    float v1 = xj * cs + xp * sn;

    float ss = v0 * v0 + v1 * v1;
    #pragma unroll
    for (int o = 16; o; o >>= 1) ss += __shfl_xor_sync(0xffffffffu, ss, o);
    float inv = rsqrtf(ss / 64.f + 1e-6f);
    float v0n = v0 * inv * w[lane];
    float v1n = v1 * inv * w[lane + 32];

    float a0 = __shfl_sync(0xffffffffu, v0n, (2 * lane) & 31);
    float b0 = __shfl_sync(0xffffffffu, v0n, (2 * lane + 1) & 31);
    float a1 = __shfl_sync(0xffffffffu, v1n, (2 * lane) & 31);
    float b1 = __shfl_sync(0xffffffffu, v1n, (2 * lane + 1) & 31);
    float A  = (lane < 16) ? a0 : a1;
    float Bv = (lane < 16) ? b0 : b1;
    qh[(size_t)gw * 32 + lane] = pack2f(A, Bv);
}

// ---------------- assemble k (+ pack v): RoPE + concat + head RMSNorm --------------
__global__ void assemble_kv_kernel(const float* __restrict__ nope, int ns,
                                   const float* __restrict__ rope, int rs,
                                   const float* __restrict__ vsrc, int vs,
                                   const float* __restrict__ w,
                                   uint32_t* __restrict__ kh,
                                   uint32_t* __restrict__ vh) {
    int gw   = (blockIdx.x * blockDim.x + threadIdx.x) >> 5;
    int lane = threadIdx.x & 31;
    if (gw >= B_ * KVH_ * T_) return;
    int t  = gw % T_;
    int bh = gw / T_;
    int h  = bh % KVH_;
    int b  = bh / KVH_;
    int tok = b * T_ + t;
    const float* np = nope + (size_t)tok * ns + h * 32;
    const float* rp = rope + (size_t)tok * rs + h * 32;

    float v0 = np[lane];
    float cs = g_cos[t * 16 + (lane & 15)];
    float sn = g_sin[t * 16 + (lane & 15)];
    float xj = rp[lane];
    float xp = (lane < 16) ? -rp[lane + 16] : rp[lane - 16];
    float v1 = xj * cs + xp * sn;

    float ss = v0 * v0 + v1 * v1;
    #pragma unroll
    for (int o = 16; o; o >>= 1) ss += __shfl_xor_sync(0xffffffffu, ss, o);
    float inv = rsqrtf(ss / 64.f + 1e-6f);
    float v0n = v0 * inv * w[lane];
    float v1n = v1 * inv * w[lane + 32];

    float a0 = __shfl_sync(0xffffffffu, v0n, (2 * lane) & 31);
    float b0 = __shfl_sync(0xffffffffu, v0n, (2 * lane + 1) & 31);
    float a1 = __shfl_sync(0xffffffffu, v1n, (2 * lane) & 31);
    float b1 = __shfl_sync(0xffffffffu, v1n, (2 * lane + 1) & 31);
    float A  = (lane < 16) ? a0 : a1;
    float Bv = (lane < 16) ? b0 : b1;
    kh[(size_t)gw * 32 + lane] = pack2f(A, Bv);

    const float* vp = vsrc + (size_t)tok * vs + h * 64;
    float2 vv = *(const float2*)(vp + 2 * lane);
    vh[(size_t)gw * 32 + lane] = pack2f(vv.x, vv.y);
}

// ---------------- flash attention: single-fp16 Q/K/V, fixed-max softmax ------------
// 128 q-rows x 64 k-cols per kt step, 256 threads (8 warps).
// Each warp owns 16 q-rows x all 64 k-cols; softmax warp-internal, m == 0
// (valid because ||q||=||k||=8 -> s in [-8,8]); l reduced once in epilogue.
__global__ void __launch_bounds__(256)
flash_kernel(const uint32_t* __restrict__ qh,
             const uint32_t* __restrict__ kh, const uint32_t* __restrict__ vh,
             const float* __restrict__ vres, int ldvr,
             float* __restrict__ ao) {
    extern __shared__ uint32_t us[];
    constexpr int SP = 36;
    constexpr int KVu   = 64 * SP;
    constexpr int KV0u  = 128 * SP;     // stages start after QH
    constexpr int STGu  = 2 * KVu;
    uint32_t* QH = us;

    const int tid = threadIdx.x, wid = tid >> 5, lane = tid & 31;
    const int g = lane >> 2, t4 = lane & 3;
    const int wr = wid * 16;

    const int qt = gridDim.x - 1 - blockIdx.x;   // big tiles first
    const int bh = blockIdx.y;
    const int b = bh / H_, h = bh % H_;
    const int kvh = h / GQA_;

    const uint32_t sBase = sptr(us);
    const uint32_t sQH = sBase;
    const int      lrA = lane & 15;
    const uint32_t lcA = (uint32_t)(lane >> 4) * 16;
    const int      lrB = (lane & 7) | ((lane >> 4) << 3);
    const uint32_t lcB = (uint32_t)((lane >> 3) & 1) * 16;
    const int      lrV = (lane & 7) | (((lane >> 3) & 1) << 3);
    const uint32_t lcV = (uint32_t)(lane >> 4) * 16;

    const uint32_t* kb = kh + ((size_t)(b * KVH_ + kvh) * T_) * 32;
    const uint32_t* vb = vh + ((size_t)(b * KVH_ + kvh) * T_) * 32;

    // stage tile 0 via cp.async
    {
        uint32_t s0 = sBase + KV0u * 4;
        int idx = tid, row = idx >> 3, qu = idx & 7;
        cpa16(s0 + (row * SP + qu * 4) * 4,       kb + (size_t)row * 32 + qu * 4);
        cpa16(s0 + (KVu + row * SP + qu * 4) * 4, vb + (size_t)row * 32 + qu * 4);
        idx = tid + 256; row = idx >> 3; qu = idx & 7;
        cpa16(s0 + (row * SP + qu * 4) * 4,       kb + (size_t)row * 32 + qu * 4);
        cpa16(s0 + (KVu + row * SP + qu * 4) * 4, vb + (size_t)row * 32 + qu * 4);
        CP_COMMIT();
    }

    // Q tile (128 rows): raw packed copy
    const uint32_t* qb = qh + ((size_t)(b * H_ + h) * T_ + qt * 128) * 32;
    #pragma unroll
    for (int j = 0; j < 2; j++) {
        int idx = tid + 256 * j, row = idx >> 2, qu = idx & 3;
        *(uint4*)&QH[row * SP + qu * 8]     = *(const uint4*)(qb + (size_t)row * 32 + qu * 8);
        *(uint4*)&QH[row * SP + qu * 8 + 4] = *(const uint4*)(qb + (size_t)row * 32 + qu * 8 + 4);
    }

    float l0a = 0.f, l1a = 0.f;
    float o[8][4];
    #pragma unroll
    for (int ni = 0; ni < 8; ni++)
        #pragma unroll
        for (int j = 0; j < 4; j++) o[ni][j] = 0.f;

    const int ktmax = 2 * qt + 1;
    const int rowlim = qt * 128 + wr + 15;

    for (int kt = 0; kt <= ktmax; kt++) {
        const int sg = kt & 1;
        const uint32_t stg = sBase + (uint32_t)(KV0u + sg * STGu) * 4;
        const uint32_t sKS = stg;
        const uint32_t sVS = stg + KVu * 4;

        CP_WAIT0();
        __syncthreads();

        // prefetch tile kt+1 into the other stage (overlaps compute below)
        if (kt + 1 <= ktmax) {
            uint32_t ob = sBase + (uint32_t)(KV0u + (1 - sg) * STGu) * 4;
            const uint32_t* kn = kb + (size_t)(kt + 1) * 64 * 32;
            const uint32_t* vn = vb + (size_t)(kt + 1) * 64 * 32;
            #pragma unroll
            for (int j = 0; j < 2; j++) {
                int idx = tid + 256 * j, row = idx >> 3, qu = idx & 7;
                cpa16(ob + (row * SP + qu * 4) * 4,       kn + (size_t)row * 32 + qu * 4);
                cpa16(ob + (KVu + row * SP + qu * 4) * 4, vn + (size_t)row * 32 + qu * 4);
            }
            CP_COMMIT();
        }

        if (kt * 64 > rowlim) continue;   // fully masked for this warp

        // ---- S = Q @ K^T (single fp16) ----
        float s[8][4];
        #pragma unroll
        for (int ni = 0; ni < 8; ni++)
            #pragma unroll
            for (int j = 0; j < 4; j++) s[ni][j] = 0.f;

        #pragma unroll
        for (int ks = 0; ks < 4; ks++) {
            uint32_t ad = sQH + (uint32_t)((wr + lrA) * SP) * 4 + ks * 32 + lcA;
            uint32_t ah[4];
            ldm4(ah, ad);
            #pragma unroll
            for (int p = 0; p < 4; p++) {
                uint32_t bd = sKS + (uint32_t)((p * 16 + lrB) * SP) * 4
                              + ks * 32 + lcB;
                uint32_t bh2[4];
                ldm4(bh2, bd);
                mma_f16(s[2 * p],     ah, bh2[0], bh2[1]);
                mma_f16(s[2 * p + 1], ah, bh2[2], bh2[3]);
            }
        }

        // scale + causal mask + exp (fixed max 0) + private l accumulation
        const int rg0 = qt * 128 + wr + g;
        const int rg1 = rg0 + 8;
        if (kt * 64 + 63 > qt * 128 + wr) {
            #pragma unroll
            for (int ni = 0; ni < 8; ni++) {
                int cg = kt * 64 + ni * 8 + t4 * 2;
                #pragma unroll
                for (int j = 0; j < 4; j++) {
                    s[ni][j] *= 0.125f;
                    int cc = cg + (j & 1);
                    int rr = (j < 2) ? rg0 : rg1;
                    if (cc > rr) s[ni][j] = -1e30f;
                }
            }
        } else {
            #pragma unroll
            for (int ni = 0; ni < 8; ni++)
                #pragma unroll
                for (int j = 0; j < 4; j++) s[ni][j] *= 0.125f;
        }

        #pragma unroll
        for (int ni = 0; ni < 8; ni++) {
            s[ni][0] = __expf(s[ni][0]);
            s[ni][1] = __expf(s[ni][1]);
            s[ni][2] = __expf(s[ni][2]);
            s[ni][3] = __expf(s[ni][3]);
            l0a += s[ni][0] + s[ni][1];
            l1a += s[ni][2] + s[ni][3];
        }

        // ---- O += P @ V (fp16, register-resident P, no rescale) ----
        #pragma unroll
        for (int ks = 0; ks < 4; ks++) {
            uint32_t pa[4];
            pa[0] = pack2f(s[2 * ks][0],     s[2 * ks][1]);
            pa[1] = pack2f(s[2 * ks][2],     s[2 * ks][3]);
            pa[2] = pack2f(s[2 * ks + 1][0], s[2 * ks + 1][1]);
            pa[3] = pack2f(s[2 * ks + 1][2], s[2 * ks + 1][3]);
            #pragma unroll
            for (int db = 0; db < 4; db++) {
                uint32_t vd = sVS + (uint32_t)((ks * 16 + lrV) * SP) * 4
                              + db * 32 + lcV;
                uint32_t bv[4];
                ldm4t(bv, vd);
                mma_f16(o[2 * db],     pa, bv[0], bv[1]);
                mma_f16(o[2 * db + 1], pa, bv[2], bv[3]);
            }
        }
    }

    // epilogue: single cross-lane l reduction, then write 16 rows x 64 d
    #pragma unroll
    for (int off = 1; off <= 2; off <<= 1) {
        l0a += __shfl_xor_sync(0xffffffffu, l0a, off);
        l1a += __shfl_xor_sync(0xffffffffu, l1a, off);
    }
    float invl0 = 1.f / l0a, invl1 = 1.f / l1a;
    int r0 = qt * 128 + wr + g;
    #pragma unroll
    for (int ni = 0; ni < 8; ni++) {
        int col = ni * 8 + t4 * 2;
        size_t vb0 = ((size_t)(b * T_ + r0)) * ldvr + h * 64 + col;
        size_t vb1 = ((size_t)(b * T_ + r0 + 8)) * ldvr + h * 64 + col;
        float2 vr0 = *(const float2*)(vres + vb0);
        float2 vr1 = *(const float2*)(vres + vb1);
        size_t ab0 = ((size_t)(b * T_ + r0)) * 512 + h * 64 + col;
        size_t ab1 = ((size_t)(b * T_ + r0 + 8)) * 512 + h * 64 + col;
        *(float2*)(ao + ab0) = make_float2(o[ni][0] * invl0 + vr0.x,
                                           o[ni][1] * invl0 + vr0.y);
        *(float2*)(ao + ab1) = make_float2(o[ni][2] * invl1 + vr1.x,
                                           o[ni][3] * invl1 + vr1.y);
    }
}

// ---------------- launch ----------------------------------------------------------
extern "C" void kernel_launch(void* const* d_in, const int* in_sizes, int n_in,
                              void* d_out, int out_size) {
    const float* x        = (const float*)d_in[0];
    const float* W_DQ     = (const float*)d_in[1];
    const float* W_UQ     = (const float*)d_in[2];
    const float* W_QR     = (const float*)d_in[3];
    const float* W_DKV    = (const float*)d_in[4];
    const float* W_UK     = (const float*)d_in[5];
    const float* W_UV     = (const float*)d_in[6];
    const float* W_KR     = (const float*)d_in[7];
    const float* W_VR     = (const float*)d_in[8];
    const float* W_O      = (const float*)d_in[9];
    const float* q_ln_w   = (const float*)d_in[10];
    const float* kv_ln_w  = (const float*)d_in[11];
    const float* q_head_w = (const float*)d_in[12];
    const float* k_head_w = (const float*)d_in[13];
    float* out = (float*)d_out;

    float *xall, *uqr, *ukv, *gao;
    uint32_t *qhp, *khp, *vhp, *wt_x, *wt_uqr, *wt_ukv, *wt_o;
    cudaGetSymbolAddress((void**)&xall,   g_xall);
    cudaGetSymbolAddress((void**)&uqr,    g_uqr);
    cudaGetSymbolAddress((void**)&ukv,    g_ukv);
    cudaGetSymbolAddress((void**)&gao,    g_ao);
    cudaGetSymbolAddress((void**)&qhp,    g_qh);
    cudaGetSymbolAddress((void**)&khp,    g_kh);
    cudaGetSymbolAddress((void**)&vhp,    g_vh);
    cudaGetSymbolAddress((void**)&wt_x,   g_wt_x);
    cudaGetSymbolAddress((void**)&wt_uqr, g_wt_uqr);
    cudaGetSymbolAddress((void**)&wt_ukv, g_wt_ukv);
    cudaGetSymbolAddress((void**)&wt_o,   g_wt_o);

    const int SMEM_GX   = 2 * (128 + 64) * 20 * 4;      // 30720 (x-proj, no split)
    const int SMEM_G128 = 2 * (256 + 128) * 20 * 4;     // 61440
    const int SMEM_G64  = 2 * (256 + 64) * 20 * 4;      // 51200
    const int SMEM_FL   = (128 * 36 + 2 * 2 * 64 * 36) * 4;  // 55296
    cudaFuncSetAttribute((const void*)mma_gemm<128, true>,
                         cudaFuncAttributeMaxDynamicSharedMemorySize, SMEM_G128);
    cudaFuncSetAttribute((const void*)mma_gemm<64, true>,
                         cudaFuncAttributeMaxDynamicSharedMemorySize, SMEM_G64);
    cudaFuncSetAttribute((const void*)flash_kernel,
                         cudaFuncAttributeMaxDynamicSharedMemorySize, SMEM_FL);

    // fused prep: 9 transpose+pack + rope tables
    PrepArgs pa;
    const float* srcs[9] = {W_DQ, W_DKV, W_KR, W_VR, W_UQ, W_QR, W_UK, W_UV, W_O};
    uint32_t* dsts[9] = {wt_x, wt_x + 256 * 256, wt_x + 384 * 256, wt_x + 448 * 256,
                         wt_uqr, wt_uqr + 256 * 128, wt_ukv, wt_ukv + 64 * 64, wt_o};
    int Ks[9] = {512, 512, 512, 512, 256, 256, 128, 128, 512};
    int Ns[9] = {256, 128,  64, 512, 256, 256,  64, 128, 512};
    int off = 0;
    for (int i = 0; i < 9; i++) {
        pa.src[i] = srcs[i]; pa.dst[i] = dsts[i];
        pa.K[i] = Ks[i]; pa.N[i] = Ns[i];
        pa.off[i] = off;
        off += (Ks[i] / 32) * (Ns[i] / 32);
    }
    pa.off[9] = off;   // 888
    prep_kernel<<<off + 128, dim3(32, 8)>>>(pa);

    // all x-projections in one GEMM (single-fp16 A): [8192,512] @ [512,960]
    mma_gemm<64, false><<<dim3(15, 64), 256, SMEM_GX>>>(x, wt_x, xall, 960, 512, 512, 960);

    // latent RMSNorms (strided views into xall)
    rmsnorm_kernel<<<BT_ / 8, 256>>>(xall,       960, q_ln_w,  256, BT_);
    rmsnorm_kernel<<<BT_ / 8, 256>>>(xall + 256, 960, kv_ln_w, 128, BT_);

    // up-projections (2-term A)
    mma_gemm<128, true><<<dim3(4, 64), 256, SMEM_G128>>>(xall,       wt_uqr, uqr, 512, 256, 960, 512);
    mma_gemm<64,  true><<<dim3(3, 64), 256, SMEM_G64 >>>(xall + 256, wt_ukv, ukv, 192, 128, 960, 192);

    // RoPE + concat + head RMSNorm -> packed fp16
    assemble_q_kernel <<<B_ * H_   * T_ / 8, 256>>>(uqr, 512, uqr + 256, 512, q_head_w, qhp);
    assemble_kv_kernel<<<B_ * KVH_ * T_ / 8, 256>>>(ukv, 192, xall + 384, 960,
                                                    ukv + 64, 192, k_head_w, khp, vhp);

    // causal flash attention + value residual (128-row Q tiles)
    flash_kernel<<<dim3(T_ / 128, B_ * H_), 256, SMEM_FL>>>(
        qhp, khp, vhp, xall + 448, 960, gao);

    // output projection (2-term A)
    mma_gemm<128, true><<<dim3(4, 64), 256, SMEM_G128>>>(gao, wt_o, out, 512, 512, 512, 512);
}

// round 13
// speedup vs baseline: 6.2611x; 1.0571x over previous
#include <cuda_runtime.h>
#include <cuda_fp16.h>
#include <cstdint>
#include <math.h>

#define B_   4
#define T_   2048
#define H_   8
#define KVH_ 2
#define BT_  (B_ * T_)   // 8192
#define GQA_ (H_ / KVH_) // 4

// ---------------- scratch (device globals) ----------------------------------------
__device__ float g_xall [BT_ * 960];   // [DQ 0:256 | DKV 256:384 | KR 384:448 | VR 448:960]
__device__ float g_uqr  [BT_ * 512];   // [qnope 0:256 | qrope 256:512]
__device__ float g_ukv  [BT_ * 192];   // [knope 0:64 | vproj 64:192]
__device__ float g_ao   [BT_ * 512];
__device__ float g_cos  [T_ * 16];
__device__ float g_sin  [T_ * 16];

// packed fp16x2 tensors for flash
__device__ uint32_t g_qh [B_ * H_   * T_ * 32];
__device__ uint32_t g_kh [B_ * KVH_ * T_ * 32];
__device__ uint32_t g_vh [B_ * KVH_ * T_ * 32];

// transposed + fp16x2-packed weights [N][K/2]
__device__ uint32_t g_wt_x  [960 * 256];
__device__ uint32_t g_wt_uqr[512 * 128];
__device__ uint32_t g_wt_ukv[192 * 64];
__device__ uint32_t g_wt_o  [512 * 256];

// ---------------- helpers ---------------------------------------------------------
__device__ __forceinline__ uint32_t sptr(const void* p) {
    return (uint32_t)__cvta_generic_to_shared(p);
}
__device__ __forceinline__ uint32_t pack2f(float x, float y) {   // x -> low half
    uint32_t r;
    asm("cvt.rn.f16x2.f32 %0, %1, %2;" : "=r"(r) : "f"(y), "f"(x));
    return r;
}
__device__ __forceinline__ void f16split2(float x, float y, uint32_t& h, uint32_t& l) {
    asm("cvt.rn.f16x2.f32 %0, %1, %2;" : "=r"(h) : "f"(y), "f"(x));
    __half2 hb = *reinterpret_cast<__half2*>(&h);
    float rx = x - __low2float(hb);
    float ry = y - __high2float(hb);
    asm("cvt.rn.f16x2.f32 %0, %1, %2;" : "=r"(l) : "f"(ry), "f"(rx));
}
__device__ __forceinline__ void mma_f16(float* c, const uint32_t* a,
                                        uint32_t b0, uint32_t b1) {
    asm volatile(
        "mma.sync.aligned.m16n8k16.row.col.f32.f16.f16.f32 "
        "{%0,%1,%2,%3}, {%4,%5,%6,%7}, {%8,%9}, {%0,%1,%2,%3};\n"
        : "+f"(c[0]), "+f"(c[1]), "+f"(c[2]), "+f"(c[3])
        : "r"(a[0]), "r"(a[1]), "r"(a[2]), "r"(a[3]), "r"(b0), "r"(b1));
}
__device__ __forceinline__ void ldm4(uint32_t* r, uint32_t addr) {
    asm volatile("ldmatrix.sync.aligned.m8n8.x4.shared.b16 {%0,%1,%2,%3}, [%4];"
                 : "=r"(r[0]), "=r"(r[1]), "=r"(r[2]), "=r"(r[3]) : "r"(addr));
}
__device__ __forceinline__ void ldm4t(uint32_t* r, uint32_t addr) {
    asm volatile("ldmatrix.sync.aligned.m8n8.x4.trans.shared.b16 {%0,%1,%2,%3}, [%4];"
                 : "=r"(r[0]), "=r"(r[1]), "=r"(r[2]), "=r"(r[3]) : "r"(addr));
}
__device__ __forceinline__ void cpa16(uint32_t saddr, const void* g) {
    asm volatile("cp.async.cg.shared.global [%0], [%1], 16;" :: "r"(saddr), "l"(g) : "memory");
}
#define CP_COMMIT() asm volatile("cp.async.commit_group;" ::: "memory")
#define CP_WAIT0()  asm volatile("cp.async.wait_group 0;"  ::: "memory")

// ---------------- fused prep: 9 weight transpose+pack + rope tables ----------------
struct PrepArgs {
    const float* src[9];
    uint32_t*    dst[9];
    int K[9], N[9];
    int off[10];
};

__global__ void prep_kernel(PrepArgs a) {
    __shared__ float tb[32][33];
    int bx = blockIdx.x;
    int x = threadIdx.x, y = threadIdx.y;
    if (bx >= a.off[9]) {
        int idx = (bx - a.off[9]) * 256 + y * 32 + x;
        if (idx < T_ * 16) {
            int t = idx >> 4, i = idx & 15;
            double invf = pow(500000.0, -((double)(2 * i)) / 32.0);
            double ang  = (double)t * invf;
            g_cos[idx] = (float)cos(ang);
            g_sin[idx] = (float)sin(ang);
        }
        return;
    }
    int m = 0;
    #pragma unroll
    for (int i = 1; i < 9; i++) if (bx >= a.off[i]) m = i;
    int lt = bx - a.off[m];
    int N = a.N[m], K = a.K[m];
    int ntx = N >> 5;
    int n0 = (lt % ntx) * 32, k0 = (lt / ntx) * 32;
    const float* in = a.src[m];
    uint32_t* out = a.dst[m];
    #pragma unroll
    for (int d = 0; d < 32; d += 8)
        tb[y + d][x] = in[(size_t)(k0 + y + d) * N + n0 + x];
    __syncthreads();
    if (x < 16) {
        int kd2 = K >> 1;
        #pragma unroll
        for (int d = 0; d < 32; d += 8)
            out[(size_t)(n0 + y + d) * kd2 + (k0 >> 1) + x] =
                pack2f(tb[2 * x][y + d], tb[2 * x + 1][y + d]);
    }
}

// ---------------- fp16 GEMM, double-buffered, 1 barrier/chunk ----------------------
// C[?,N] = A[128-rows,K] @ BT[N,K]^T. block 128 x TN, 256 threads, K chunks of 32.
// SPLIT kept for revert; all call sites currently use SPLIT=false (single fp16 A).
template <int TN, bool SPLIT>
__global__ void __launch_bounds__(256)
mma_gemm(const float* __restrict__ A, const uint32_t* __restrict__ BT,
         float* __restrict__ C, int N, int K, int lda, int ldc) {
    extern __shared__ uint32_t us[];
    constexpr int SPU    = 20;
    constexpr int ALOu   = 128 * SPU;
    constexpr int BOFFu  = (SPLIT ? 256 : 128) * SPU;
    constexpr int STGu   = ((SPLIT ? 256 : 128) + TN) * SPU;

    constexpr int WMW    = (TN == 128) ? 2 : 4;
    constexpr int WARP_M = 128 / WMW;
    constexpr int MI     = WARP_M / 16;
    constexpr int BR2    = TN / 64;

    const int tid = threadIdx.x, wid = tid >> 5, lane = tid & 31;
    const int wm = wid % WMW, wn = wid / WMW;
    const int g = lane >> 2, t4 = lane & 3;
    const int m0 = blockIdx.y * 128, n0 = blockIdx.x * TN;

    const uint32_t sBase = sptr(us);
    const int      lrA = lane & 15;
    const uint32_t lcA = (uint32_t)(lane >> 4) * 16;
    const int      lrB = (lane & 7) | ((lane >> 4) << 3);
    const uint32_t lcB = (uint32_t)((lane >> 3) & 1) * 16;

    const int ldb = K >> 1;
    const float*    Ab = A + (size_t)m0 * lda;
    const uint32_t* Bb = BT + (size_t)n0 * ldb;

    float4 areg[4];
    #pragma unroll
    for (int j = 0; j < 4; j++) {
        int idx = tid + 256 * j, row = idx >> 3, q = idx & 7;
        areg[j] = *(const float4*)(Ab + (size_t)row * lda + q * 4);
    }
    #pragma unroll
    for (int j = 0; j < BR2; j++) {
        int idx = tid + 256 * j, row = idx >> 2, qu = idx & 3;
        cpa16(sBase + (BOFFu + row * SPU + qu * 4) * 4,
              Bb + (size_t)row * ldb + qu * 4);
    }
    CP_COMMIT();

    float c[MI][4][4];
    #pragma unroll
    for (int mi = 0; mi < MI; mi++)
        #pragma unroll
        for (int ni = 0; ni < 4; ni++)
            #pragma unroll
            for (int j = 0; j < 4; j++) c[mi][ni][j] = 0.f;

    const int NC = K >> 5;
    for (int ch = 0; ch < NC; ch++) {
        const int sg = ch & 1;
        uint32_t* stg = us + sg * STGu;
        const uint32_t stb = sBase + (uint32_t)(sg * STGu) * 4;

        #pragma unroll
        for (int j = 0; j < 4; j++) {
            int idx = tid + 256 * j, row = idx >> 3, q = idx & 7;
            if (SPLIT) {
                uint32_t h0, l0, h1, l1;
                f16split2(areg[j].x, areg[j].y, h0, l0);
                f16split2(areg[j].z, areg[j].w, h1, l1);
                *(uint2*)&stg[row * SPU + 2 * q]        = make_uint2(h0, h1);
                *(uint2*)&stg[ALOu + row * SPU + 2 * q] = make_uint2(l0, l1);
            } else {
                *(uint2*)&stg[row * SPU + 2 * q] =
                    make_uint2(pack2f(areg[j].x, areg[j].y),
                               pack2f(areg[j].z, areg[j].w));
            }
        }
        CP_WAIT0();
        __syncthreads();

        if (ch + 1 < NC) {
            int k0 = (ch + 1) * 32;
            #pragma unroll
            for (int j = 0; j < 4; j++) {
                int idx = tid + 256 * j, row = idx >> 3, q = idx & 7;
                areg[j] = *(const float4*)(Ab + (size_t)row * lda + k0 + q * 4);
            }
            uint32_t ob = sBase + (uint32_t)((1 - sg) * STGu) * 4;
            #pragma unroll
            for (int j = 0; j < BR2; j++) {
                int idx = tid + 256 * j, row = idx >> 2, qu = idx & 3;
                cpa16(ob + (BOFFu + row * SPU + qu * 4) * 4,
                      Bb + (size_t)row * ldb + (k0 >> 1) + qu * 4);
            }
            CP_COMMIT();
        }

        #pragma unroll
        for (int ks = 0; ks < 2; ks++) {
            uint32_t ah[MI][4], al[MI][4];
            #pragma unroll
            for (int mi = 0; mi < MI; mi++) {
                uint32_t ad = stb + (uint32_t)((wm * WARP_M + mi * 16 + lrA) * SPU) * 4
                              + ks * 32 + lcA;
                ldm4(ah[mi], ad);
                if (SPLIT) ldm4(al[mi], ad + ALOu * 4);
            }
            #pragma unroll
            for (int p = 0; p < 2; p++) {
                uint32_t bd = stb + (uint32_t)(BOFFu + (wn * 32 + p * 16 + lrB) * SPU) * 4
                              + ks * 32 + lcB;
                uint32_t bh2[4];
                ldm4(bh2, bd);
                #pragma unroll
                for (int mi = 0; mi < MI; mi++) {
                    mma_f16(c[mi][2 * p],     ah[mi], bh2[0], bh2[1]);
                    if (SPLIT) mma_f16(c[mi][2 * p], al[mi], bh2[0], bh2[1]);
                    mma_f16(c[mi][2 * p + 1], ah[mi], bh2[2], bh2[3]);
                    if (SPLIT) mma_f16(c[mi][2 * p + 1], al[mi], bh2[2], bh2[3]);
                }
            }
        }
        // no trailing barrier: stage sg next written at ch+2, after ch+1's barrier.
    }

    #pragma unroll
    for (int mi = 0; mi < MI; mi++) {
        int row = m0 + wm * WARP_M + mi * 16 + g;
        #pragma unroll
        for (int ni = 0; ni < 4; ni++) {
            int col = n0 + wn * 32 + ni * 8 + t4 * 2;
            *(float2*)(C + (size_t)row * ldc + col) =
                make_float2(c[mi][ni][0], c[mi][ni][1]);
            *(float2*)(C + (size_t)(row + 8) * ldc + col) =
                make_float2(c[mi][ni][2], c[mi][ni][3]);
        }
    }
}

// ---------------- strided in-place row RMSNorm ------------------------------------
__global__ void rmsnorm_kernel(float* __restrict__ X, int ld,
                               const float* __restrict__ w, int N, int rows) {
    int warp = (blockIdx.x * blockDim.x + threadIdx.x) >> 5;
    int lane = threadIdx.x & 31;
    if (warp >= rows) return;
    float* row = X + (size_t)warp * ld;
    float ss = 0.f;
    for (int c = lane; c < N; c += 32) { float v = row[c]; ss += v * v; }
    #pragma unroll
    for (int o = 16; o; o >>= 1) ss += __shfl_xor_sync(0xffffffffu, ss, o);
    float inv = rsqrtf(ss / (float)N + 1e-6f);
    for (int c = lane; c < N; c += 32) row[c] = row[c] * inv * w[c];
}

// ---------------- assemble q: RoPE + concat + head RMSNorm -> packed fp16 ----------
__global__ void assemble_q_kernel(const float* __restrict__ nope, int ns,
                                  const float* __restrict__ rope, int rs,
                                  const float* __restrict__ w,
                                  uint32_t* __restrict__ qh) {
    int gw   = (blockIdx.x * blockDim.x + threadIdx.x) >> 5;
    int lane = threadIdx.x & 31;
    if (gw >= B_ * H_ * T_) return;
    int t  = gw % T_;
    int bh = gw / T_;
    int h  = bh % H_;
    int b  = bh / H_;
    int tok = b * T_ + t;
    const float* np = nope + (size_t)tok * ns + h * 32;
    const float* rp = rope + (size_t)tok * rs + h * 32;

    float v0 = np[lane];
    float cs = g_cos[t * 16 + (lane & 15)];
    float sn = g_sin[t * 16 + (lane & 15)];
    float xj = rp[lane];
    float xp = (lane < 16) ? -rp[lane + 16] : rp[lane - 16];
    float v1 = xj * cs + xp * sn;

    float ss = v0 * v0 + v1 * v1;
    #pragma unroll
    for (int o = 16; o; o >>= 1) ss += __shfl_xor_sync(0xffffffffu, ss, o);
    float inv = rsqrtf(ss / 64.f + 1e-6f);
    float v0n = v0 * inv * w[lane];
    float v1n = v1 * inv * w[lane + 32];

    float a0 = __shfl_sync(0xffffffffu, v0n, (2 * lane) & 31);
    float b0 = __shfl_sync(0xffffffffu, v0n, (2 * lane + 1) & 31);
    float a1 = __shfl_sync(0xffffffffu, v1n, (2 * lane) & 31);
    float b1 = __shfl_sync(0xffffffffu, v1n, (2 * lane + 1) & 31);
    float A  = (lane < 16) ? a0 : a1;
    float Bv = (lane < 16) ? b0 : b1;
    qh[(size_t)gw * 32 + lane] = pack2f(A, Bv);
}

// ---------------- assemble k (+ pack v): RoPE + concat + head RMSNorm --------------
__global__ void assemble_kv_kernel(const float* __restrict__ nope, int ns,
                                   const float* __restrict__ rope, int rs,
                                   const float* __restrict__ vsrc, int vs,
                                   const float* __restrict__ w,
                                   uint32_t* __restrict__ kh,
                                   uint32_t* __restrict__ vh) {
    int gw   = (blockIdx.x * blockDim.x + threadIdx.x) >> 5;
    int lane = threadIdx.x & 31;
    if (gw >= B_ * KVH_ * T_) return;
    int t  = gw % T_;
    int bh = gw / T_;
    int h  = bh % KVH_;
    int b  = bh / KVH_;
    int tok = b * T_ + t;
    const float* np = nope + (size_t)tok * ns + h * 32;
    const float* rp = rope + (size_t)tok * rs + h * 32;

    float v0 = np[lane];
    float cs = g_cos[t * 16 + (lane & 15)];
    float sn = g_sin[t * 16 + (lane & 15)];
    float xj = rp[lane];
    float xp = (lane < 16) ? -rp[lane + 16] : rp[lane - 16];
    float v1 = xj * cs + xp * sn;

    float ss = v0 * v0 + v1 * v1;
    #pragma unroll
    for (int o = 16; o; o >>= 1) ss += __shfl_xor_sync(0xffffffffu, ss, o);
    float inv = rsqrtf(ss / 64.f + 1e-6f);
    float v0n = v0 * inv * w[lane];
    float v1n = v1 * inv * w[lane + 32];

    float a0 = __shfl_sync(0xffffffffu, v0n, (2 * lane) & 31);
    float b0 = __shfl_sync(0xffffffffu, v0n, (2 * lane + 1) & 31);
    float a1 = __shfl_sync(0xffffffffu, v1n, (2 * lane) & 31);
    float b1 = __shfl_sync(0xffffffffu, v1n, (2 * lane + 1) & 31);
    float A  = (lane < 16) ? a0 : a1;
    float Bv = (lane < 16) ? b0 : b1;
    kh[(size_t)gw * 32 + lane] = pack2f(A, Bv);

    const float* vp = vsrc + (size_t)tok * vs + h * 64;
    float2 vv = *(const float2*)(vp + 2 * lane);
    vh[(size_t)gw * 32 + lane] = pack2f(vv.x, vv.y);
}

// ---------------- flash attention: single-fp16, fixed-max softmax, hoisted Q -------
// 128 q-rows x 64 k-cols per kt step, 256 threads (8 warps).
// Each warp owns 16 q-rows x all 64 k-cols; softmax warp-internal, m == 0;
// Q fragments hoisted into registers for the whole kt loop.
__global__ void __launch_bounds__(256)
flash_kernel(const uint32_t* __restrict__ qh,
             const uint32_t* __restrict__ kh, const uint32_t* __restrict__ vh,
             const float* __restrict__ vres, int ldvr,
             float* __restrict__ ao) {
    extern __shared__ uint32_t us[];
    constexpr int SP = 36;
    constexpr int KVu   = 64 * SP;
    constexpr int KV0u  = 128 * SP;
    constexpr int STGu  = 2 * KVu;
    uint32_t* QH = us;

    const int tid = threadIdx.x, wid = tid >> 5, lane = tid & 31;
    const int g = lane >> 2, t4 = lane & 3;
    const int wr = wid * 16;

    const int qt = gridDim.x - 1 - blockIdx.x;   // big tiles first
    const int bh = blockIdx.y;
    const int b = bh / H_, h = bh % H_;
    const int kvh = h / GQA_;

    const uint32_t sBase = sptr(us);
    const int      lrA = lane & 15;
    const uint32_t lcA = (uint32_t)(lane >> 4) * 16;
    const int      lrB = (lane & 7) | ((lane >> 4) << 3);
    const uint32_t lcB = (uint32_t)((lane >> 3) & 1) * 16;
    const int      lrV = (lane & 7) | (((lane >> 3) & 1) << 3);
    const uint32_t lcV = (uint32_t)(lane >> 4) * 16;

    const uint32_t* kb = kh + ((size_t)(b * KVH_ + kvh) * T_) * 32;
    const uint32_t* vb = vh + ((size_t)(b * KVH_ + kvh) * T_) * 32;

    // stage tile 0 via cp.async
    {
        uint32_t s0 = sBase + KV0u * 4;
        int idx = tid, row = idx >> 3, qu = idx & 7;
        cpa16(s0 + (row * SP + qu * 4) * 4,       kb + (size_t)row * 32 + qu * 4);
        cpa16(s0 + (KVu + row * SP + qu * 4) * 4, vb + (size_t)row * 32 + qu * 4);
        idx = tid + 256; row = idx >> 3; qu = idx & 7;
        cpa16(s0 + (row * SP + qu * 4) * 4,       kb + (size_t)row * 32 + qu * 4);
        cpa16(s0 + (KVu + row * SP + qu * 4) * 4, vb + (size_t)row * 32 + qu * 4);
        CP_COMMIT();
    }

    // Q tile (128 rows): raw packed copy, then hoist this warp's fragments to regs
    const uint32_t* qb = qh + ((size_t)(b * H_ + h) * T_ + qt * 128) * 32;
    #pragma unroll
    for (int j = 0; j < 2; j++) {
        int idx = tid + 256 * j, row = idx >> 2, qu = idx & 3;
        *(uint4*)&QH[row * SP + qu * 8]     = *(const uint4*)(qb + (size_t)row * 32 + qu * 8);
        *(uint4*)&QH[row * SP + qu * 8 + 4] = *(const uint4*)(qb + (size_t)row * 32 + qu * 8 + 4);
    }
    __syncthreads();
    uint32_t qf[4][4];
    #pragma unroll
    for (int ks = 0; ks < 4; ks++) {
        uint32_t ad = sBase + (uint32_t)((wr + lrA) * SP) * 4 + ks * 32 + lcA;
        ldm4(qf[ks], ad);
    }

    float l0a = 0.f, l1a = 0.f;
    float o[8][4];
    #pragma unroll
    for (int ni = 0; ni < 8; ni++)
        #pragma unroll
        for (int j = 0; j < 4; j++) o[ni][j] = 0.f;

    const int ktmax = 2 * qt + 1;
    const int rowlim = qt * 128 + wr + 15;

    for (int kt = 0; kt <= ktmax; kt++) {
        const int sg = kt & 1;
        const uint32_t stg = sBase + (uint32_t)(KV0u + sg * STGu) * 4;
        const uint32_t sKS = stg;
        const uint32_t sVS = stg + KVu * 4;

        CP_WAIT0();
        __syncthreads();

        // prefetch tile kt+1 into the other stage (overlaps compute below)
        if (kt + 1 <= ktmax) {
            uint32_t ob = sBase + (uint32_t)(KV0u + (1 - sg) * STGu) * 4;
            const uint32_t* kn = kb + (size_t)(kt + 1) * 64 * 32;
            const uint32_t* vn = vb + (size_t)(kt + 1) * 64 * 32;
            #pragma unroll
            for (int j = 0; j < 2; j++) {
                int idx = tid + 256 * j, row = idx >> 3, qu = idx & 7;
                cpa16(ob + (row * SP + qu * 4) * 4,       kn + (size_t)row * 32 + qu * 4);
                cpa16(ob + (KVu + row * SP + qu * 4) * 4, vn + (size_t)row * 32 + qu * 4);
            }
            CP_COMMIT();
        }

        if (kt * 64 > rowlim) continue;   // fully masked for this warp

        // ---- S = Q @ K^T (single fp16, Q fragments in registers) ----
        float s[8][4];
        #pragma unroll
        for (int ni = 0; ni < 8; ni++)
            #pragma unroll
            for (int j = 0; j < 4; j++) s[ni][j] = 0.f;

        #pragma unroll
        for (int ks = 0; ks < 4; ks++) {
            #pragma unroll
            for (int p = 0; p < 4; p++) {
                uint32_t bd = sKS + (uint32_t)((p * 16 + lrB) * SP) * 4
                              + ks * 32 + lcB;
                uint32_t bh2[4];
                ldm4(bh2, bd);
                mma_f16(s[2 * p],     qf[ks], bh2[0], bh2[1]);
                mma_f16(s[2 * p + 1], qf[ks], bh2[2], bh2[3]);
            }
        }

        // scale + causal mask + exp (fixed max 0) + private l accumulation
        const int rg0 = qt * 128 + wr + g;
        const int rg1 = rg0 + 8;
        if (kt * 64 + 63 > qt * 128 + wr) {
            #pragma unroll
            for (int ni = 0; ni < 8; ni++) {
                int cg = kt * 64 + ni * 8 + t4 * 2;
                #pragma unroll
                for (int j = 0; j < 4; j++) {
                    s[ni][j] *= 0.125f;
                    int cc = cg + (j & 1);
                    int rr = (j < 2) ? rg0 : rg1;
                    if (cc > rr) s[ni][j] = -1e30f;
                }
            }
        } else {
            #pragma unroll
            for (int ni = 0; ni < 8; ni++)
                #pragma unroll
                for (int j = 0; j < 4; j++) s[ni][j] *= 0.125f;
        }

        #pragma unroll
        for (int ni = 0; ni < 8; ni++) {
            s[ni][0] = __expf(s[ni][0]);
            s[ni][1] = __expf(s[ni][1]);
            s[ni][2] = __expf(s[ni][2]);
            s[ni][3] = __expf(s[ni][3]);
            l0a += s[ni][0] + s[ni][1];
            l1a += s[ni][2] + s[ni][3];
        }

        // ---- O += P @ V (fp16, register-resident P, no rescale) ----
        #pragma unroll
        for (int ks = 0; ks < 4; ks++) {
            uint32_t pa[4];
            pa[0] = pack2f(s[2 * ks][0],     s[2 * ks][1]);
            pa[1] = pack2f(s[2 * ks][2],     s[2 * ks][3]);
            pa[2] = pack2f(s[2 * ks + 1][0], s[2 * ks + 1][1]);
            pa[3] = pack2f(s[2 * ks + 1][2], s[2 * ks + 1][3]);
            #pragma unroll
            for (int db = 0; db < 4; db++) {
                uint32_t vd = sVS + (uint32_t)((ks * 16 + lrV) * SP) * 4
                              + db * 32 + lcV;
                uint32_t bv[4];
                ldm4t(bv, vd);
                mma_f16(o[2 * db],     pa, bv[0], bv[1]);
                mma_f16(o[2 * db + 1], pa, bv[2], bv[3]);
            }
        }
    }

    // epilogue: single cross-lane l reduction, then write 16 rows x 64 d
    #pragma unroll
    for (int off = 1; off <= 2; off <<= 1) {
        l0a += __shfl_xor_sync(0xffffffffu, l0a, off);
        l1a += __shfl_xor_sync(0xffffffffu, l1a, off);
    }
    float invl0 = 1.f / l0a, invl1 = 1.f / l1a;
    int r0 = qt * 128 + wr + g;
    #pragma unroll
    for (int ni = 0; ni < 8; ni++) {
        int col = ni * 8 + t4 * 2;
        size_t vb0 = ((size_t)(b * T_ + r0)) * ldvr + h * 64 + col;
        size_t vb1 = ((size_t)(b * T_ + r0 + 8)) * ldvr + h * 64 + col;
        float2 vr0 = *(const float2*)(vres + vb0);
        float2 vr1 = *(const float2*)(vres + vb1);
        size_t ab0 = ((size_t)(b * T_ + r0)) * 512 + h * 64 + col;
        size_t ab1 = ((size_t)(b * T_ + r0 + 8)) * 512 + h * 64 + col;
        *(float2*)(ao + ab0) = make_float2(o[ni][0] * invl0 + vr0.x,
                                           o[ni][1] * invl0 + vr0.y);
        *(float2*)(ao + ab1) = make_float2(o[ni][2] * invl1 + vr1.x,
                                           o[ni][3] * invl1 + vr1.y);
    }
}

// ---------------- launch ----------------------------------------------------------
extern "C" void kernel_launch(void* const* d_in, const int* in_sizes, int n_in,
                              void* d_out, int out_size) {
    const float* x        = (const float*)d_in[0];
    const float* W_DQ     = (const float*)d_in[1];
    const float* W_UQ     = (const float*)d_in[2];
    const float* W_QR     = (const float*)d_in[3];
    const float* W_DKV    = (const float*)d_in[4];
    const float* W_UK     = (const float*)d_in[5];
    const float* W_UV     = (const float*)d_in[6];
    const float* W_KR     = (const float*)d_in[7];
    const float* W_VR     = (const float*)d_in[8];
    const float* W_O      = (const float*)d_in[9];
    const float* q_ln_w   = (const float*)d_in[10];
    const float* kv_ln_w  = (const float*)d_in[11];
    const float* q_head_w = (const float*)d_in[12];
    const float* k_head_w = (const float*)d_in[13];
    float* out = (float*)d_out;

    float *xall, *uqr, *ukv, *gao;
    uint32_t *qhp, *khp, *vhp, *wt_x, *wt_uqr, *wt_ukv, *wt_o;
    cudaGetSymbolAddress((void**)&xall,   g_xall);
    cudaGetSymbolAddress((void**)&uqr,    g_uqr);
    cudaGetSymbolAddress((void**)&ukv,    g_ukv);
    cudaGetSymbolAddress((void**)&gao,    g_ao);
    cudaGetSymbolAddress((void**)&qhp,    g_qh);
    cudaGetSymbolAddress((void**)&khp,    g_kh);
    cudaGetSymbolAddress((void**)&vhp,    g_vh);
    cudaGetSymbolAddress((void**)&wt_x,   g_wt_x);
    cudaGetSymbolAddress((void**)&wt_uqr, g_wt_uqr);
    cudaGetSymbolAddress((void**)&wt_ukv, g_wt_ukv);
    cudaGetSymbolAddress((void**)&wt_o,   g_wt_o);

    const int SMEM_G64  = 2 * (128 + 64) * 20 * 4;      // 30720
    const int SMEM_G128 = 2 * (128 + 128) * 20 * 4;     // 40960
    const int SMEM_FL   = (128 * 36 + 2 * 2 * 64 * 36) * 4;  // 55296
    cudaFuncSetAttribute((const void*)flash_kernel,
                         cudaFuncAttributeMaxDynamicSharedMemorySize, SMEM_FL);

    // fused prep: 9 transpose+pack + rope tables
    PrepArgs pa;
    const float* srcs[9] = {W_DQ, W_DKV, W_KR, W_VR, W_UQ, W_QR, W_UK, W_UV, W_O};
    uint32_t* dsts[9] = {wt_x, wt_x + 256 * 256, wt_x + 384 * 256, wt_x + 448 * 256,
                         wt_uqr, wt_uqr + 256 * 128, wt_ukv, wt_ukv + 64 * 64, wt_o};
    int Ks[9] = {512, 512, 512, 512, 256, 256, 128, 128, 512};
    int Ns[9] = {256, 128,  64, 512, 256, 256,  64, 128, 512};
    int off = 0;
    for (int i = 0; i < 9; i++) {
        pa.src[i] = srcs[i]; pa.dst[i] = dsts[i];
        pa.K[i] = Ks[i]; pa.N[i] = Ns[i];
        pa.off[i] = off;
        off += (Ks[i] / 32) * (Ns[i] / 32);
    }
    pa.off[9] = off;   // 888
    prep_kernel<<<off + 128, dim3(32, 8)>>>(pa);

    // all x-projections in one GEMM: [8192,512] @ [512,960]
    mma_gemm<64, false><<<dim3(15, 64), 256, SMEM_G64>>>(x, wt_x, xall, 960, 512, 512, 960);

    // latent RMSNorms (strided views into xall)
    rmsnorm_kernel<<<BT_ / 8, 256>>>(xall,       960, q_ln_w,  256, BT_);
    rmsnorm_kernel<<<BT_ / 8, 256>>>(xall + 256, 960, kv_ln_w, 128, BT_);

    // up-projections (single fp16 A)
    mma_gemm<128, false><<<dim3(4, 64), 256, SMEM_G128>>>(xall,       wt_uqr, uqr, 512, 256, 960, 512);
    mma_gemm<64,  false><<<dim3(3, 64), 256, SMEM_G64 >>>(xall + 256, wt_ukv, ukv, 192, 128, 960, 192);

    // RoPE + concat + head RMSNorm -> packed fp16
    assemble_q_kernel <<<B_ * H_   * T_ / 8, 256>>>(uqr, 512, uqr + 256, 512, q_head_w, qhp);
    assemble_kv_kernel<<<B_ * KVH_ * T_ / 8, 256>>>(ukv, 192, xall + 384, 960,
                                                    ukv + 64, 192, k_head_w, khp, vhp);

    // causal flash attention + value residual (128-row Q tiles)
    flash_kernel<<<dim3(T_ / 128, B_ * H_), 256, SMEM_FL>>>(
        qhp, khp, vhp, xall + 448, 960, gao);

    // output projection (single fp16 A)
    mma_gemm<128, false><<<dim3(4, 64), 256, SMEM_G128>>>(gao, wt_o, out, 512, 512, 512, 512);
}

// round 14
// speedup vs baseline: 6.4465x; 1.0296x over previous
#include <cuda_runtime.h>
#include <cuda_fp16.h>
#include <cstdint>
#include <math.h>

#define B_   4
#define T_   2048
#define H_   8
#define KVH_ 2
#define BT_  (B_ * T_)   // 8192
#define GQA_ (H_ / KVH_) // 4

// ---------------- scratch (device globals) ----------------------------------------
__device__ float g_xall [BT_ * 960];   // [DQ 0:256 | DKV 256:384 | KR 384:448 | VR 448:960]
__device__ float g_uqr  [BT_ * 512];   // [qnope 0:256 | qrope 256:512]
__device__ float g_ukv  [BT_ * 192];   // [knope 0:64 | vproj 64:192]
__device__ float g_ao   [BT_ * 512];
__device__ float g_cos  [T_ * 16];
__device__ float g_sin  [T_ * 16];

// packed fp16x2 tensors for flash
__device__ uint32_t g_qh [B_ * H_   * T_ * 32];
__device__ uint32_t g_kh [B_ * KVH_ * T_ * 32];
__device__ uint32_t g_vh [B_ * KVH_ * T_ * 32];

// transposed + fp16x2-packed weights [N][K/2]
__device__ uint32_t g_wt_x  [960 * 256];
__device__ uint32_t g_wt_uqr[512 * 128];
__device__ uint32_t g_wt_ukv[192 * 64];
__device__ uint32_t g_wt_o  [512 * 256];

// ---------------- helpers ---------------------------------------------------------
__device__ __forceinline__ uint32_t sptr(const void* p) {
    return (uint32_t)__cvta_generic_to_shared(p);
}
__device__ __forceinline__ uint32_t pack2f(float x, float y) {   // x -> low half
    uint32_t r;
    asm("cvt.rn.f16x2.f32 %0, %1, %2;" : "=r"(r) : "f"(y), "f"(x));
    return r;
}
__device__ __forceinline__ void f16split2(float x, float y, uint32_t& h, uint32_t& l) {
    asm("cvt.rn.f16x2.f32 %0, %1, %2;" : "=r"(h) : "f"(y), "f"(x));
    __half2 hb = *reinterpret_cast<__half2*>(&h);
    float rx = x - __low2float(hb);
    float ry = y - __high2float(hb);
    asm("cvt.rn.f16x2.f32 %0, %1, %2;" : "=r"(l) : "f"(ry), "f"(rx));
}
__device__ __forceinline__ void mma_f16(float* c, const uint32_t* a,
                                        uint32_t b0, uint32_t b1) {
    asm volatile(
        "mma.sync.aligned.m16n8k16.row.col.f32.f16.f16.f32 "
        "{%0,%1,%2,%3}, {%4,%5,%6,%7}, {%8,%9}, {%0,%1,%2,%3};\n"
        : "+f"(c[0]), "+f"(c[1]), "+f"(c[2]), "+f"(c[3])
        : "r"(a[0]), "r"(a[1]), "r"(a[2]), "r"(a[3]), "r"(b0), "r"(b1));
}
__device__ __forceinline__ void ldm4(uint32_t* r, uint32_t addr) {
    asm volatile("ldmatrix.sync.aligned.m8n8.x4.shared.b16 {%0,%1,%2,%3}, [%4];"
                 : "=r"(r[0]), "=r"(r[1]), "=r"(r[2]), "=r"(r[3]) : "r"(addr));
}
__device__ __forceinline__ void ldm4t(uint32_t* r, uint32_t addr) {
    asm volatile("ldmatrix.sync.aligned.m8n8.x4.trans.shared.b16 {%0,%1,%2,%3}, [%4];"
                 : "=r"(r[0]), "=r"(r[1]), "=r"(r[2]), "=r"(r[3]) : "r"(addr));
}
__device__ __forceinline__ void cpa16(uint32_t saddr, const void* g) {
    asm volatile("cp.async.cg.shared.global [%0], [%1], 16;" :: "r"(saddr), "l"(g) : "memory");
}
#define CP_COMMIT() asm volatile("cp.async.commit_group;" ::: "memory")
#define CP_WAIT0()  asm volatile("cp.async.wait_group 0;"  ::: "memory")

// ---------------- fused prep: 9 weight transpose+pack + rope tables ----------------
struct PrepArgs {
    const float* src[9];
    uint32_t*    dst[9];
    int K[9], N[9];
    int off[10];
};

__global__ void prep_kernel(PrepArgs a) {
    __shared__ float tb[32][33];
    int bx = blockIdx.x;
    int x = threadIdx.x, y = threadIdx.y;
    if (bx >= a.off[9]) {
        int idx = (bx - a.off[9]) * 256 + y * 32 + x;
        if (idx < T_ * 16) {
            int t = idx >> 4, i = idx & 15;
            double invf = pow(500000.0, -((double)(2 * i)) / 32.0);
            double ang  = (double)t * invf;
            g_cos[idx] = (float)cos(ang);
            g_sin[idx] = (float)sin(ang);
        }
        return;
    }
    int m = 0;
    #pragma unroll
    for (int i = 1; i < 9; i++) if (bx >= a.off[i]) m = i;
    int lt = bx - a.off[m];
    int N = a.N[m], K = a.K[m];
    int ntx = N >> 5;
    int n0 = (lt % ntx) * 32, k0 = (lt / ntx) * 32;
    const float* in = a.src[m];
    uint32_t* out = a.dst[m];
    #pragma unroll
    for (int d = 0; d < 32; d += 8)
        tb[y + d][x] = in[(size_t)(k0 + y + d) * N + n0 + x];
    __syncthreads();
    if (x < 16) {
        int kd2 = K >> 1;
        #pragma unroll
        for (int d = 0; d < 32; d += 8)
            out[(size_t)(n0 + y + d) * kd2 + (k0 >> 1) + x] =
                pack2f(tb[2 * x][y + d], tb[2 * x + 1][y + d]);
    }
}

// ---------------- fp16 GEMM body (device fn), double-buffered ----------------------
// C[?,N] = A[128-rows,K] @ BT[N,K]^T. block 128 x TN, 256 threads, K chunks of 32.
template <int TN, bool SPLIT>
__device__ __forceinline__ void gemm_body(
        const float* __restrict__ A, const uint32_t* __restrict__ BT,
        float* __restrict__ C, int N, int K, int lda, int ldc,
        int bxn, int bym) {
    extern __shared__ uint32_t us[];
    constexpr int SPU    = 20;
    constexpr int ALOu   = 128 * SPU;
    constexpr int BOFFu  = (SPLIT ? 256 : 128) * SPU;
    constexpr int STGu   = ((SPLIT ? 256 : 128) + TN) * SPU;

    constexpr int WMW    = (TN == 128) ? 2 : 4;
    constexpr int WARP_M = 128 / WMW;
    constexpr int MI     = WARP_M / 16;
    constexpr int BR2    = TN / 64;

    const int tid = threadIdx.x, wid = tid >> 5, lane = tid & 31;
    const int wm = wid % WMW, wn = wid / WMW;
    const int g = lane >> 2, t4 = lane & 3;
    const int m0 = bym * 128, n0 = bxn * TN;

    const uint32_t sBase = sptr(us);
    const int      lrA = lane & 15;
    const uint32_t lcA = (uint32_t)(lane >> 4) * 16;
    const int      lrB = (lane & 7) | ((lane >> 4) << 3);
    const uint32_t lcB = (uint32_t)((lane >> 3) & 1) * 16;

    const int ldb = K >> 1;
    const float*    Ab = A + (size_t)m0 * lda;
    const uint32_t* Bb = BT + (size_t)n0 * ldb;

    float4 areg[4];
    #pragma unroll
    for (int j = 0; j < 4; j++) {
        int idx = tid + 256 * j, row = idx >> 3, q = idx & 7;
        areg[j] = *(const float4*)(Ab + (size_t)row * lda + q * 4);
    }
    #pragma unroll
    for (int j = 0; j < BR2; j++) {
        int idx = tid + 256 * j, row = idx >> 2, qu = idx & 3;
        cpa16(sBase + (BOFFu + row * SPU + qu * 4) * 4,
              Bb + (size_t)row * ldb + qu * 4);
    }
    CP_COMMIT();

    float c[MI][4][4];
    #pragma unroll
    for (int mi = 0; mi < MI; mi++)
        #pragma unroll
        for (int ni = 0; ni < 4; ni++)
            #pragma unroll
            for (int j = 0; j < 4; j++) c[mi][ni][j] = 0.f;

    const int NC = K >> 5;
    for (int ch = 0; ch < NC; ch++) {
        const int sg = ch & 1;
        uint32_t* stg = us + sg * STGu;
        const uint32_t stb = sBase + (uint32_t)(sg * STGu) * 4;

        #pragma unroll
        for (int j = 0; j < 4; j++) {
            int idx = tid + 256 * j, row = idx >> 3, q = idx & 7;
            if (SPLIT) {
                uint32_t h0, l0, h1, l1;
                f16split2(areg[j].x, areg[j].y, h0, l0);
                f16split2(areg[j].z, areg[j].w, h1, l1);
                *(uint2*)&stg[row * SPU + 2 * q]        = make_uint2(h0, h1);
                *(uint2*)&stg[ALOu + row * SPU + 2 * q] = make_uint2(l0, l1);
            } else {
                *(uint2*)&stg[row * SPU + 2 * q] =
                    make_uint2(pack2f(areg[j].x, areg[j].y),
                               pack2f(areg[j].z, areg[j].w));
            }
        }
        CP_WAIT0();
        __syncthreads();

        if (ch + 1 < NC) {
            int k0 = (ch + 1) * 32;
            #pragma unroll
            for (int j = 0; j < 4; j++) {
                int idx = tid + 256 * j, row = idx >> 3, q = idx & 7;
                areg[j] = *(const float4*)(Ab + (size_t)row * lda + k0 + q * 4);
            }
            uint32_t ob = sBase + (uint32_t)((1 - sg) * STGu) * 4;
            #pragma unroll
            for (int j = 0; j < BR2; j++) {
                int idx = tid + 256 * j, row = idx >> 2, qu = idx & 3;
                cpa16(ob + (BOFFu + row * SPU + qu * 4) * 4,
                      Bb + (size_t)row * ldb + (k0 >> 1) + qu * 4);
            }
            CP_COMMIT();
        }

        #pragma unroll
        for (int ks = 0; ks < 2; ks++) {
            uint32_t ah[MI][4], al[MI][4];
            #pragma unroll
            for (int mi = 0; mi < MI; mi++) {
                uint32_t ad = stb + (uint32_t)((wm * WARP_M + mi * 16 + lrA) * SPU) * 4
                              + ks * 32 + lcA;
                ldm4(ah[mi], ad);
                if (SPLIT) ldm4(al[mi], ad + ALOu * 4);
            }
            #pragma unroll
            for (int p = 0; p < 2; p++) {
                uint32_t bd = stb + (uint32_t)(BOFFu + (wn * 32 + p * 16 + lrB) * SPU) * 4
                              + ks * 32 + lcB;
                uint32_t bh2[4];
                ldm4(bh2, bd);
                #pragma unroll
                for (int mi = 0; mi < MI; mi++) {
                    mma_f16(c[mi][2 * p],     ah[mi], bh2[0], bh2[1]);
                    if (SPLIT) mma_f16(c[mi][2 * p], al[mi], bh2[0], bh2[1]);
                    mma_f16(c[mi][2 * p + 1], ah[mi], bh2[2], bh2[3]);
                    if (SPLIT) mma_f16(c[mi][2 * p + 1], al[mi], bh2[2], bh2[3]);
                }
            }
        }
    }

    #pragma unroll
    for (int mi = 0; mi < MI; mi++) {
        int row = m0 + wm * WARP_M + mi * 16 + g;
        #pragma unroll
        for (int ni = 0; ni < 4; ni++) {
            int col = n0 + wn * 32 + ni * 8 + t4 * 2;
            *(float2*)(C + (size_t)row * ldc + col) =
                make_float2(c[mi][ni][0], c[mi][ni][1]);
            *(float2*)(C + (size_t)(row + 8) * ldc + col) =
                make_float2(c[mi][ni][2], c[mi][ni][3]);
        }
    }
}

template <int TN, bool SPLIT>
__global__ void __launch_bounds__(256)
mma_gemm(const float* __restrict__ A, const uint32_t* __restrict__ BT,
         float* __restrict__ C, int N, int K, int lda, int ldc) {
    gemm_body<TN, SPLIT>(A, BT, C, N, K, lda, ldc, blockIdx.x, blockIdx.y);
}

// dual dispatcher: two TN=64 GEMMs in one launch
struct GemmP {
    const float* A; const uint32_t* BT; float* C;
    int N, K, lda, ldc, nx;
};
__global__ void __launch_bounds__(256)
mma_gemm_dual(GemmP p0, GemmP p1) {
    int bx = blockIdx.x;
    if (bx < p0.nx)
        gemm_body<64, false>(p0.A, p0.BT, p0.C, p0.N, p0.K, p0.lda, p0.ldc, bx, blockIdx.y);
    else
        gemm_body<64, false>(p1.A, p1.BT, p1.C, p1.N, p1.K, p1.lda, p1.ldc, bx - p0.nx, blockIdx.y);
}

// ---------------- fused dual RMSNorm (both latents, one launch) --------------------
__global__ void rmsnorm_fused(float* __restrict__ X1, const float* __restrict__ w1,
                              float* __restrict__ X2, const float* __restrict__ w2) {
    int bx = blockIdx.x;
    int warp = threadIdx.x >> 5, lane = threadIdx.x & 31;
    float* X; const float* w; int N, row;
    if (bx < 1024) { X = X1; w = w1; N = 256; row = bx * 8 + warp; }
    else           { X = X2; w = w2; N = 128; row = (bx - 1024) * 8 + warp; }
    float* rp = X + (size_t)row * 960;
    float ss = 0.f;
    for (int c = lane; c < N; c += 32) { float v = rp[c]; ss += v * v; }
    #pragma unroll
    for (int o = 16; o; o >>= 1) ss += __shfl_xor_sync(0xffffffffu, ss, o);
    float inv = rsqrtf(ss / (float)N + 1e-6f);
    for (int c = lane; c < N; c += 32) rp[c] = rp[c] * inv * w[c];
}

// ---------------- fused assemble (q + kv), one launch ------------------------------
__global__ void assemble_fused(const float* __restrict__ uqr,
                               const float* __restrict__ ukv,
                               const float* __restrict__ xall,
                               const float* __restrict__ qw,
                               const float* __restrict__ kw,
                               uint32_t* __restrict__ qh,
                               uint32_t* __restrict__ kh,
                               uint32_t* __restrict__ vh) {
    int bx = blockIdx.x;
    int warp = threadIdx.x >> 5, lane = threadIdx.x & 31;
    if (bx < 8192) {
        // q path: gw over B*H*T
        int gw = bx * 8 + warp;
        int t  = gw % T_;
        int bh = gw / T_;
        int h  = bh % H_;
        int b  = bh / H_;
        int tok = b * T_ + t;
        const float* np = uqr + (size_t)tok * 512 + h * 32;
        const float* rp = uqr + (size_t)tok * 512 + 256 + h * 32;

        float v0 = np[lane];
        float cs = g_cos[t * 16 + (lane & 15)];
        float sn = g_sin[t * 16 + (lane & 15)];
        float xj = rp[lane];
        float xp = (lane < 16) ? -rp[lane + 16] : rp[lane - 16];
        float v1 = xj * cs + xp * sn;

        float ss = v0 * v0 + v1 * v1;
        #pragma unroll
        for (int o = 16; o; o >>= 1) ss += __shfl_xor_sync(0xffffffffu, ss, o);
        float inv = rsqrtf(ss / 64.f + 1e-6f);
        float v0n = v0 * inv * qw[lane];
        float v1n = v1 * inv * qw[lane + 32];

        float a0 = __shfl_sync(0xffffffffu, v0n, (2 * lane) & 31);
        float b0 = __shfl_sync(0xffffffffu, v0n, (2 * lane + 1) & 31);
        float a1 = __shfl_sync(0xffffffffu, v1n, (2 * lane) & 31);
        float b1 = __shfl_sync(0xffffffffu, v1n, (2 * lane + 1) & 31);
        float A  = (lane < 16) ? a0 : a1;
        float Bv = (lane < 16) ? b0 : b1;
        qh[(size_t)gw * 32 + lane] = pack2f(A, Bv);
    } else {
        // kv path: gw over B*KVH*T
        int gw = (bx - 8192) * 8 + warp;
        int t  = gw % T_;
        int bh = gw / T_;
        int h  = bh % KVH_;
        int b  = bh / KVH_;
        int tok = b * T_ + t;
        const float* np = ukv + (size_t)tok * 192 + h * 32;
        const float* rp = xall + (size_t)tok * 960 + 384 + h * 32;

        float v0 = np[lane];
        float cs = g_cos[t * 16 + (lane & 15)];
        float sn = g_sin[t * 16 + (lane & 15)];
        float xj = rp[lane];
        float xp = (lane < 16) ? -rp[lane + 16] : rp[lane - 16];
        float v1 = xj * cs + xp * sn;

        float ss = v0 * v0 + v1 * v1;
        #pragma unroll
        for (int o = 16; o; o >>= 1) ss += __shfl_xor_sync(0xffffffffu, ss, o);
        float inv = rsqrtf(ss / 64.f + 1e-6f);
        float v0n = v0 * inv * kw[lane];
        float v1n = v1 * inv * kw[lane + 32];

        float a0 = __shfl_sync(0xffffffffu, v0n, (2 * lane) & 31);
        float b0 = __shfl_sync(0xffffffffu, v0n, (2 * lane + 1) & 31);
        float a1 = __shfl_sync(0xffffffffu, v1n, (2 * lane) & 31);
        float b1 = __shfl_sync(0xffffffffu, v1n, (2 * lane + 1) & 31);
        float A  = (lane < 16) ? a0 : a1;
        float Bv = (lane < 16) ? b0 : b1;
        kh[(size_t)gw * 32 + lane] = pack2f(A, Bv);

        const float* vp = ukv + (size_t)tok * 192 + 64 + h * 64;
        float2 vv = *(const float2*)(vp + 2 * lane);
        vh[(size_t)gw * 32 + lane] = pack2f(vv.x, vv.y);
    }
}

// ---------------- flash attention: 128-col staged K/V, 2 subtiles per barrier ------
// 128 q-rows; kt pairs (2qt+2 tiles is always even). Single-fp16, fixed-max softmax,
// hoisted Q fragments, private-l deferred reduction.
__global__ void __launch_bounds__(256, 2)
flash_kernel(const uint32_t* __restrict__ qh,
             const uint32_t* __restrict__ kh, const uint32_t* __restrict__ vh,
             const float* __restrict__ vres, int ldvr,
             float* __restrict__ ao) {
    extern __shared__ uint32_t us[];
    constexpr int SP   = 36;
    constexpr int KSTu = 128 * SP;      // K part of one stage (128 rows)
    constexpr int KV0u = 128 * SP;      // stages start after QH
    constexpr int STGu = 2 * KSTu;      // K + V
    uint32_t* QH = us;

    const int tid = threadIdx.x, wid = tid >> 5, lane = tid & 31;
    const int g = lane >> 2, t4 = lane & 3;
    const int wr = wid * 16;

    const int qt = gridDim.x - 1 - blockIdx.x;   // big tiles first
    const int bh = blockIdx.y;
    const int b = bh / H_, h = bh % H_;
    const int kvh = h / GQA_;

    const uint32_t sBase = sptr(us);
    const int      lrA = lane & 15;
    const uint32_t lcA = (uint32_t)(lane >> 4) * 16;
    const int      lrB = (lane & 7) | ((lane >> 4) << 3);
    const uint32_t lcB = (uint32_t)((lane >> 3) & 1) * 16;
    const int      lrV = (lane & 7) | (((lane >> 3) & 1) << 3);
    const uint32_t lcV = (uint32_t)(lane >> 4) * 16;

    const uint32_t* kb = kh + ((size_t)(b * KVH_ + kvh) * T_) * 32;
    const uint32_t* vb = vh + ((size_t)(b * KVH_ + kvh) * T_) * 32;

    // stage pair 0 (128 K rows + 128 V rows) via cp.async
    {
        uint32_t s0 = sBase + KV0u * 4;
        #pragma unroll
        for (int j = 0; j < 4; j++) {
            int idx = tid + 256 * j, row = idx >> 3, qu = idx & 7;
            cpa16(s0 + (row * SP + qu * 4) * 4,        kb + (size_t)row * 32 + qu * 4);
            cpa16(s0 + (KSTu + row * SP + qu * 4) * 4, vb + (size_t)row * 32 + qu * 4);
        }
        CP_COMMIT();
    }

    // Q tile (128 rows): raw packed copy, then hoist this warp's fragments to regs
    const uint32_t* qb = qh + ((size_t)(b * H_ + h) * T_ + qt * 128) * 32;
    #pragma unroll
    for (int j = 0; j < 2; j++) {
        int idx = tid + 256 * j, row = idx >> 2, qu = idx & 3;
        *(uint4*)&QH[row * SP + qu * 8]     = *(const uint4*)(qb + (size_t)row * 32 + qu * 8);
        *(uint4*)&QH[row * SP + qu * 8 + 4] = *(const uint4*)(qb + (size_t)row * 32 + qu * 8 + 4);
    }
    __syncthreads();
    uint32_t qf[4][4];
    #pragma unroll
    for (int ks = 0; ks < 4; ks++) {
        uint32_t ad = sBase + (uint32_t)((wr + lrA) * SP) * 4 + ks * 32 + lcA;
        ldm4(qf[ks], ad);
    }

    float l0a = 0.f, l1a = 0.f;
    float o[8][4];
    #pragma unroll
    for (int ni = 0; ni < 8; ni++)
        #pragma unroll
        for (int j = 0; j < 4; j++) o[ni][j] = 0.f;

    const int npair = qt + 1;             // 2qt+2 tiles = qt+1 pairs
    const int rowlim = qt * 128 + wr + 15;

    for (int p = 0; p < npair; p++) {
        const int sg = p & 1;
        const uint32_t stgK = sBase + (uint32_t)(KV0u + sg * STGu) * 4;
        const uint32_t stgV = stgK + KSTu * 4;

        CP_WAIT0();
        __syncthreads();

        // prefetch pair p+1 into the other stage (overlaps both subtiles below)
        if (p + 1 < npair) {
            uint32_t ob = sBase + (uint32_t)(KV0u + (1 - sg) * STGu) * 4;
            const uint32_t* kn = kb + (size_t)(p + 1) * 128 * 32;
            const uint32_t* vn = vb + (size_t)(p + 1) * 128 * 32;
            #pragma unroll
            for (int j = 0; j < 4; j++) {
                int idx = tid + 256 * j, row = idx >> 3, qu = idx & 7;
                cpa16(ob + (row * SP + qu * 4) * 4,        kn + (size_t)row * 32 + qu * 4);
                cpa16(ob + (KSTu + row * SP + qu * 4) * 4, vn + (size_t)row * 32 + qu * 4);
            }
            CP_COMMIT();
        }

        #pragma unroll
        for (int sub = 0; sub < 2; sub++) {
            const int ktile = 2 * p + sub;
            if (ktile * 64 > rowlim) continue;   // fully masked for this warp
            const uint32_t sKS = stgK + (uint32_t)(sub * 64 * SP) * 4;
            const uint32_t sVS = stgV + (uint32_t)(sub * 64 * SP) * 4;

            // ---- S = Q @ K^T (single fp16, Q fragments in registers) ----
            float s[8][4];
            #pragma unroll
            for (int ni = 0; ni < 8; ni++)
                #pragma unroll
                for (int j = 0; j < 4; j++) s[ni][j] = 0.f;

            #pragma unroll
            for (int ks = 0; ks < 4; ks++) {
                #pragma unroll
                for (int pp = 0; pp < 4; pp++) {
                    uint32_t bd = sKS + (uint32_t)((pp * 16 + lrB) * SP) * 4
                                  + ks * 32 + lcB;
                    uint32_t bh2[4];
                    ldm4(bh2, bd);
                    mma_f16(s[2 * pp],     qf[ks], bh2[0], bh2[1]);
                    mma_f16(s[2 * pp + 1], qf[ks], bh2[2], bh2[3]);
                }
            }

            // scale + causal mask + exp (fixed max 0) + private l accumulation
            const int rg0 = qt * 128 + wr + g;
            const int rg1 = rg0 + 8;
            if (ktile * 64 + 63 > qt * 128 + wr) {
                #pragma unroll
                for (int ni = 0; ni < 8; ni++) {
                    int cg = ktile * 64 + ni * 8 + t4 * 2;
                    #pragma unroll
                    for (int j = 0; j < 4; j++) {
                        s[ni][j] *= 0.125f;
                        int cc = cg + (j & 1);
                        int rr = (j < 2) ? rg0 : rg1;
                        if (cc > rr) s[ni][j] = -1e30f;
                    }
                }
            } else {
                #pragma unroll
                for (int ni = 0; ni < 8; ni++)
                    #pragma unroll
                    for (int j = 0; j < 4; j++) s[ni][j] *= 0.125f;
            }

            #pragma unroll
            for (int ni = 0; ni < 8; ni++) {
                s[ni][0] = __expf(s[ni][0]);
                s[ni][1] = __expf(s[ni][1]);
                s[ni][2] = __expf(s[ni][2]);
                s[ni][3] = __expf(s[ni][3]);
                l0a += s[ni][0] + s[ni][1];
                l1a += s[ni][2] + s[ni][3];
            }

            // ---- O += P @ V (fp16, register-resident P, no rescale) ----
            #pragma unroll
            for (int ks = 0; ks < 4; ks++) {
                uint32_t pa[4];
                pa[0] = pack2f(s[2 * ks][0],     s[2 * ks][1]);
                pa[1] = pack2f(s[2 * ks][2],     s[2 * ks][3]);
                pa[2] = pack2f(s[2 * ks + 1][0], s[2 * ks + 1][1]);
                pa[3] = pack2f(s[2 * ks + 1][2], s[2 * ks + 1][3]);
                #pragma unroll
                for (int db = 0; db < 4; db++) {
                    uint32_t vd = sVS + (uint32_t)((ks * 16 + lrV) * SP) * 4
                                  + db * 32 + lcV;
                    uint32_t bv[4];
                    ldm4t(bv, vd);
                    mma_f16(o[2 * db],     pa, bv[0], bv[1]);
                    mma_f16(o[2 * db + 1], pa, bv[2], bv[3]);
                }
            }
        }
    }

    // epilogue: single cross-lane l reduction, then write 16 rows x 64 d
    #pragma unroll
    for (int off = 1; off <= 2; off <<= 1) {
        l0a += __shfl_xor_sync(0xffffffffu, l0a, off);
        l1a += __shfl_xor_sync(0xffffffffu, l1a, off);
    }
    float invl0 = 1.f / l0a, invl1 = 1.f / l1a;
    int r0 = qt * 128 + wr + g;
    #pragma unroll
    for (int ni = 0; ni < 8; ni++) {
        int col = ni * 8 + t4 * 2;
        size_t vb0 = ((size_t)(b * T_ + r0)) * ldvr + h * 64 + col;
        size_t vb1 = ((size_t)(b * T_ + r0 + 8)) * ldvr + h * 64 + col;
        float2 vr0 = *(const float2*)(vres + vb0);
        float2 vr1 = *(const float2*)(vres + vb1);
        size_t ab0 = ((size_t)(b * T_ + r0)) * 512 + h * 64 + col;
        size_t ab1 = ((size_t)(b * T_ + r0 + 8)) * 512 + h * 64 + col;
        *(float2*)(ao + ab0) = make_float2(o[ni][0] * invl0 + vr0.x,
                                           o[ni][1] * invl0 + vr0.y);
        *(float2*)(ao + ab1) = make_float2(o[ni][2] * invl1 + vr1.x,
                                           o[ni][3] * invl1 + vr1.y);
    }
}

// ---------------- launch ----------------------------------------------------------
extern "C" void kernel_launch(void* const* d_in, const int* in_sizes, int n_in,
                              void* d_out, int out_size) {
    const float* x        = (const float*)d_in[0];
    const float* W_DQ     = (const float*)d_in[1];
    const float* W_UQ     = (const float*)d_in[2];
    const float* W_QR     = (const float*)d_in[3];
    const float* W_DKV    = (const float*)d_in[4];
    const float* W_UK     = (const float*)d_in[5];
    const float* W_UV     = (const float*)d_in[6];
    const float* W_KR     = (const float*)d_in[7];
    const float* W_VR     = (const float*)d_in[8];
    const float* W_O      = (const float*)d_in[9];
    const float* q_ln_w   = (const float*)d_in[10];
    const float* kv_ln_w  = (const float*)d_in[11];
    const float* q_head_w = (const float*)d_in[12];
    const float* k_head_w = (const float*)d_in[13];
    float* out = (float*)d_out;

    float *xall, *uqr, *ukv, *gao;
    uint32_t *qhp, *khp, *vhp, *wt_x, *wt_uqr, *wt_ukv, *wt_o;
    cudaGetSymbolAddress((void**)&xall,   g_xall);
    cudaGetSymbolAddress((void**)&uqr,    g_uqr);
    cudaGetSymbolAddress((void**)&ukv,    g_ukv);
    cudaGetSymbolAddress((void**)&gao,    g_ao);
    cudaGetSymbolAddress((void**)&qhp,    g_qh);
    cudaGetSymbolAddress((void**)&khp,    g_kh);
    cudaGetSymbolAddress((void**)&vhp,    g_vh);
    cudaGetSymbolAddress((void**)&wt_x,   g_wt_x);
    cudaGetSymbolAddress((void**)&wt_uqr, g_wt_uqr);
    cudaGetSymbolAddress((void**)&wt_ukv, g_wt_ukv);
    cudaGetSymbolAddress((void**)&wt_o,   g_wt_o);

    const int SMEM_G64  = 2 * (128 + 64) * 20 * 4;      // 30720
    const int SMEM_G128 = 2 * (128 + 128) * 20 * 4;     // 40960
    const int SMEM_FL   = (128 * 36 + 2 * 256 * 36) * 4;  // 92160
    cudaFuncSetAttribute((const void*)flash_kernel,
                         cudaFuncAttributeMaxDynamicSharedMemorySize, SMEM_FL);

    // fused prep: 9 transpose+pack + rope tables
    PrepArgs pa;
    const float* srcs[9] = {W_DQ, W_DKV, W_KR, W_VR, W_UQ, W_QR, W_UK, W_UV, W_O};
    uint32_t* dsts[9] = {wt_x, wt_x + 256 * 256, wt_x + 384 * 256, wt_x + 448 * 256,
                         wt_uqr, wt_uqr + 256 * 128, wt_ukv, wt_ukv + 64 * 64, wt_o};
    int Ks[9] = {512, 512, 512, 512, 256, 256, 128, 128, 512};
    int Ns[9] = {256, 128,  64, 512, 256, 256,  64, 128, 512};
    int off = 0;
    for (int i = 0; i < 9; i++) {
        pa.src[i] = srcs[i]; pa.dst[i] = dsts[i];
        pa.K[i] = Ks[i]; pa.N[i] = Ns[i];
        pa.off[i] = off;
        off += (Ks[i] / 32) * (Ns[i] / 32);
    }
    pa.off[9] = off;   // 888
    prep_kernel<<<off + 128, dim3(32, 8)>>>(pa);

    // all x-projections in one GEMM: [8192,512] @ [512,960]
    mma_gemm<64, false><<<dim3(15, 64), 256, SMEM_G64>>>(x, wt_x, xall, 960, 512, 512, 960);

    // both latent RMSNorms, one launch
    rmsnorm_fused<<<2048, 256>>>(xall, q_ln_w, xall + 256, kv_ln_w);

    // both up-projections, one dispatcher launch (TN=64)
    GemmP p0 = {xall,       wt_uqr, uqr, 512, 256, 960, 512, 8};
    GemmP p1 = {xall + 256, wt_ukv, ukv, 192, 128, 960, 192, 3};
    mma_gemm_dual<<<dim3(11, 64), 256, SMEM_G64>>>(p0, p1);

    // fused assemble (q + kv) -> packed fp16
    assemble_fused<<<8192 + 2048, 256>>>(uqr, ukv, xall, q_head_w, k_head_w,
                                         qhp, khp, vhp);

    // causal flash attention + value residual (128-row Q tiles, paired K staging)
    flash_kernel<<<dim3(T_ / 128, B_ * H_), 256, SMEM_FL>>>(
        qhp, khp, vhp, xall + 448, 960, gao);

    // output projection
    mma_gemm<128, false><<<dim3(4, 64), 256, SMEM_G128>>>(gao, wt_o, out, 512, 512, 512, 512);
}